// round 5
// baseline (speedup 1.0000x reference)
#include <cuda_runtime.h>

// Attention_9328668967755 — fused fp32 implementation.
// b=8, c=256, n=48*48=2304, heads=4, d_head=32, hidden=128.
//
// Pipeline:
//   1) gemm64: qkv[b,384,n] = w_qkv[384,256] @ x[b,256,n]
//   2) attn_kernel: flash-style online-softmax attention per (b, head, 64-query block)
//      -> att[b,128,n]   (layout b, h*32+d, n  == reference's 'b (h d) n')
//   3) gemm64: out[b,256,n] = w_out[256,128] @ att[b,128,n] + b_out
//
// All math fp32 (FFMA). Scratch via __device__ globals (no allocations).

#define NTOK 2304
#define SCALE 0.17677669529663689f   // 32^-0.5

__device__ float g_qkv[8 * 384 * NTOK];   // ~28.3 MB
__device__ float g_att[8 * 128 * NTOK];   // ~9.4 MB

// ---------------------------------------------------------------------------
// Generic tiled SGEMM: C[b] = A @ B[b] (+bias), A row-major [M,K], B row-major
// [K,N], C row-major [M,N]. Block tile 64x64, K-tile 16, 128 threads,
// thread tile 8x4. Requires M%64==0, N%64==0, K%16==0 (true for both uses).
// ---------------------------------------------------------------------------
__global__ __launch_bounds__(128, 4)
void gemm64(const float* __restrict__ A, const float* __restrict__ B,
            float* __restrict__ C, const float* __restrict__ bias,
            int M, int N, int K, size_t strideB, size_t strideC)
{
    __shared__ float As[16][68];   // [k][m], padded (store-transpose conflicts)
    __shared__ float Bs[16][68];   // [k][n]

    const int tid = threadIdx.x;
    const int mb = blockIdx.y * 64;
    const int nb = blockIdx.x * 64;
    const float* Bb = B + (size_t)blockIdx.z * strideB;
    float*       Cb = C + (size_t)blockIdx.z * strideC;

    const int tm8 = (tid >> 4) * 8;    // 8 row-groups
    const int tn4 = (tid & 15) * 4;    // 16 col-groups

    float acc[8][4];
#pragma unroll
    for (int r = 0; r < 8; r++)
#pragma unroll
        for (int c = 0; c < 4; c++) acc[r][c] = 0.f;

    const int lam = tid >> 2;          // 0..31 (A tile row)
    const int lak = (tid & 3) * 4;     // 0,4,8,12 (A tile k)
    const int lbk = tid >> 4;          // 0..7 (B tile k)
    const int lbn = (tid & 15) * 4;    // B tile col

    for (int k0 = 0; k0 < K; k0 += 16) {
        __syncthreads();
#pragma unroll
        for (int i = 0; i < 2; i++) {
            float4 a = *(const float4*)(A + (size_t)(mb + lam + 32 * i) * K + k0 + lak);
            As[lak + 0][lam + 32 * i] = a.x;
            As[lak + 1][lam + 32 * i] = a.y;
            As[lak + 2][lam + 32 * i] = a.z;
            As[lak + 3][lam + 32 * i] = a.w;
        }
#pragma unroll
        for (int i = 0; i < 2; i++) {
            *(float4*)&Bs[lbk + 8 * i][lbn] =
                *(const float4*)(Bb + (size_t)(k0 + lbk + 8 * i) * N + nb + lbn);
        }
        __syncthreads();
#pragma unroll
        for (int kk = 0; kk < 16; kk++) {
            float4 b4 = *(float4*)&Bs[kk][tn4];
            float4 a0 = *(float4*)&As[kk][tm8];
            float4 a1 = *(float4*)&As[kk][tm8 + 4];
            float av[8] = {a0.x, a0.y, a0.z, a0.w, a1.x, a1.y, a1.z, a1.w};
            float bv[4] = {b4.x, b4.y, b4.z, b4.w};
#pragma unroll
            for (int r = 0; r < 8; r++)
#pragma unroll
                for (int c = 0; c < 4; c++)
                    acc[r][c] += av[r] * bv[c];
        }
    }

#pragma unroll
    for (int r = 0; r < 8; r++) {
        int row = mb + tm8 + r;
        float bsv = bias ? bias[row] : 0.f;
        float4 res = make_float4(acc[r][0] + bsv, acc[r][1] + bsv,
                                 acc[r][2] + bsv, acc[r][3] + bsv);
        *(float4*)(Cb + (size_t)row * N + nb + tn4) = res;
    }
}

// ---------------------------------------------------------------------------
// Flash attention. Grid (n/64, heads, batch), 128 threads.
// qkv layout: [b][384][n] with q rows 0..127, k 128..255, v 256..383;
// head h occupies rows h*32..h*32+31 of each segment, d-major.
// Output att[b][h*32+d][token] = softmax-weighted V.
// ---------------------------------------------------------------------------
#define DOT4(P, V) ((P).x * (V).x + (P).y * (V).y + (P).z * (V).z + (P).w * (V).w)

__global__ __launch_bounds__(128, 4)
void attn_kernel(const float* __restrict__ qkv, float* __restrict__ outp)
{
    __shared__ float Qs[32][64];      // [d][query]
    __shared__ float Ks[32][64];      // [d][key]
    __shared__ float Vs[32][64];      // [d][key]
    __shared__ float Ps[64][68];      // [query][key] exp(S - m)
    __shared__ float Als[64];         // per-row rescale alpha
    __shared__ float Lls[64];         // per-row final l

    const int tid = threadIdx.x;
    const int q0 = blockIdx.x * 64;
    const int hh = blockIdx.y;
    const int bb = blockIdx.z;

    const float* Qg = qkv + ((size_t)bb * 384 + 0   + hh * 32) * NTOK;
    const float* Kg = qkv + ((size_t)bb * 384 + 128 + hh * 32) * NTOK;
    const float* Vg = qkv + ((size_t)bb * 384 + 256 + hh * 32) * NTOK;

    const int lc4 = (tid & 15) * 4;   // tile-load col
    const int ldr = tid >> 4;         // tile-load d row (0..7)

    // Load Q tile (scaled). Protected by the sync after the first K/V load.
#pragma unroll
    for (int i = 0; i < 4; i++) {
        int d = ldr + 8 * i;
        float4 v = *(const float4*)(Qg + (size_t)d * NTOK + q0 + lc4);
        v.x *= SCALE; v.y *= SCALE; v.z *= SCALE; v.w *= SCALE;
        *(float4*)&Qs[d][lc4] = v;
    }

    // S-phase mapping: rows tq8..tq8+7 (query), cols tk4..tk4+3 (key)
    const int tq8 = (tid >> 4) * 8;
    const int tk4 = (tid & 15) * 4;
    // O-phase mapping: rows {ti, ti+16, ti+32, ti+48}, dims tj4..tj4+3
    const int ti  = tid & 15;
    const int tj4 = (tid >> 4) * 4;

    float m[8], l[8];
#pragma unroll
    for (int r = 0; r < 8; r++) { m[r] = -1e30f; l[r] = 0.f; }
    float o[4][4];
#pragma unroll
    for (int r = 0; r < 4; r++)
#pragma unroll
        for (int c = 0; c < 4; c++) o[r][c] = 0.f;

    for (int kb = 0; kb < NTOK; kb += 64) {
        __syncthreads();   // prior iter's Ps/Vs reads done before overwrite
#pragma unroll
        for (int i = 0; i < 4; i++) {
            int d = ldr + 8 * i;
            *(float4*)&Ks[d][lc4] = *(const float4*)(Kg + (size_t)d * NTOK + kb + lc4);
            *(float4*)&Vs[d][lc4] = *(const float4*)(Vg + (size_t)d * NTOK + kb + lc4);
        }
        __syncthreads();

        // ---- S = (scale*Q)^T K : 8x4 per thread --------------------------
        float s[8][4];
#pragma unroll
        for (int r = 0; r < 8; r++)
#pragma unroll
            for (int c = 0; c < 4; c++) s[r][c] = 0.f;

#pragma unroll
        for (int d = 0; d < 32; d++) {
            float4 k4 = *(float4*)&Ks[d][tk4];
            float4 qa = *(float4*)&Qs[d][tq8];
            float4 qb = *(float4*)&Qs[d][tq8 + 4];
            float qv[8] = {qa.x, qa.y, qa.z, qa.w, qb.x, qb.y, qb.z, qb.w};
            float kv[4] = {k4.x, k4.y, k4.z, k4.w};
#pragma unroll
            for (int r = 0; r < 8; r++)
#pragma unroll
                for (int c = 0; c < 4; c++)
                    s[r][c] += qv[r] * kv[c];
        }

        // ---- online softmax (reduce over the 16 tk lanes; xor<=8 stays
        //      inside the 16-lane half-warp group) --------------------------
        float alpha[8];
#pragma unroll
        for (int r = 0; r < 8; r++) {
            float mt = fmaxf(fmaxf(s[r][0], s[r][1]), fmaxf(s[r][2], s[r][3]));
#pragma unroll
            for (int off = 8; off; off >>= 1)
                mt = fmaxf(mt, __shfl_xor_sync(0xffffffffu, mt, off));
            float mn = fmaxf(m[r], mt);
            alpha[r] = __expf(m[r] - mn);
            m[r] = mn;
            float rs = 0.f;
#pragma unroll
            for (int c = 0; c < 4; c++) {
                float p = __expf(s[r][c] - mn);
                s[r][c] = p;
                rs += p;
            }
#pragma unroll
            for (int off = 8; off; off >>= 1)
                rs += __shfl_xor_sync(0xffffffffu, rs, off);
            l[r] = l[r] * alpha[r] + rs;
        }

#pragma unroll
        for (int r = 0; r < 8; r++)
            *(float4*)&Ps[tq8 + r][tk4] = make_float4(s[r][0], s[r][1], s[r][2], s[r][3]);
        if ((tid & 15) == 0) {
#pragma unroll
            for (int r = 0; r < 8; r++) Als[tq8 + r] = alpha[r];
        }
        __syncthreads();

        // ---- O = alpha*O + P @ V^T : 4 rows x 4 dims per thread ----------
        float a0 = Als[ti], a1 = Als[ti + 16], a2 = Als[ti + 32], a3 = Als[ti + 48];
#pragma unroll
        for (int c = 0; c < 4; c++) {
            o[0][c] *= a0; o[1][c] *= a1; o[2][c] *= a2; o[3][c] *= a3;
        }
#pragma unroll
        for (int j = 0; j < 64; j += 4) {
            float4 p0 = *(float4*)&Ps[ti][j];
            float4 p1 = *(float4*)&Ps[ti + 16][j];
            float4 p2 = *(float4*)&Ps[ti + 32][j];
            float4 p3 = *(float4*)&Ps[ti + 48][j];
            float4 v0 = *(float4*)&Vs[tj4 + 0][j];
            float4 v1 = *(float4*)&Vs[tj4 + 1][j];
            float4 v2 = *(float4*)&Vs[tj4 + 2][j];
            float4 v3 = *(float4*)&Vs[tj4 + 3][j];
            o[0][0] += DOT4(p0, v0); o[0][1] += DOT4(p0, v1);
            o[0][2] += DOT4(p0, v2); o[0][3] += DOT4(p0, v3);
            o[1][0] += DOT4(p1, v0); o[1][1] += DOT4(p1, v1);
            o[1][2] += DOT4(p1, v2); o[1][3] += DOT4(p1, v3);
            o[2][0] += DOT4(p2, v0); o[2][1] += DOT4(p2, v1);
            o[2][2] += DOT4(p2, v2); o[2][3] += DOT4(p2, v3);
            o[3][0] += DOT4(p3, v0); o[3][1] += DOT4(p3, v1);
            o[3][2] += DOT4(p3, v2); o[3][3] += DOT4(p3, v3);
        }
    }

    __syncthreads();
    if ((tid & 15) == 0) {
#pragma unroll
        for (int r = 0; r < 8; r++) Lls[tq8 + r] = l[r];
    }
    __syncthreads();

    float i0 = 1.f / Lls[ti];
    float i1 = 1.f / Lls[ti + 16];
    float i2 = 1.f / Lls[ti + 32];
    float i3 = 1.f / Lls[ti + 48];

#pragma unroll
    for (int c = 0; c < 4; c++) {
        float* dst = outp + ((size_t)bb * 128 + hh * 32 + tj4 + c) * NTOK + q0;
        dst[ti]      = o[0][c] * i0;
        dst[ti + 16] = o[1][c] * i1;
        dst[ti + 32] = o[2][c] * i2;
        dst[ti + 48] = o[3][c] * i3;
    }
}

// ---------------------------------------------------------------------------
extern "C" void kernel_launch(void* const* d_in, const int* in_sizes, int n_in,
                              void* d_out, int out_size)
{
    const float* x     = (const float*)d_in[0];   // [8,256,48,48]
    const float* w_qkv = (const float*)d_in[1];   // [384,256]
    const float* w_out = (const float*)d_in[2];   // [256,128]
    const float* b_out = (const float*)d_in[3];   // [256]
    float* out = (float*)d_out;                   // [8,256,48,48]

    float* qkv = nullptr;
    float* att = nullptr;
    cudaGetSymbolAddress((void**)&qkv, g_qkv);
    cudaGetSymbolAddress((void**)&att, g_att);

    dim3 threads(128);

    // 1) QKV projection: per batch [384,2304] = [384,256] @ [256,2304]
    gemm64<<<dim3(NTOK / 64, 384 / 64, 8), threads>>>(
        w_qkv, x, qkv, nullptr,
        384, NTOK, 256,
        (size_t)256 * NTOK, (size_t)384 * NTOK);

    // 2) Attention
    attn_kernel<<<dim3(NTOK / 64, 4, 8), threads>>>(qkv, att);

    // 3) Output projection + bias: per batch [256,2304] = [256,128] @ [128,2304]
    gemm64<<<dim3(NTOK / 64, 256 / 64, 8), threads>>>(
        w_out, att, out, b_out,
        256, NTOK, 128,
        (size_t)128 * NTOK, (size_t)256 * NTOK);
}

// round 6
// speedup vs baseline: 1.0100x; 1.0100x over previous
#include <cuda_runtime.h>

// Attention_9328668967755 — fused fp32 implementation.
// b=8, c=256, n=48*48=2304, heads=4, d_head=32, hidden=128.
//
// Pipeline:
//   1) gemm64: qkv[b,384,n] = w_qkv[384,256] @ x[b,256,n]
//   2) attn_kernel: flash-style online-softmax attention per (b, head, 64-query block)
//      -> att[b,128,n]   (layout b, h*32+d, n  == reference's 'b (h d) n')
//   3) gemm64: out[b,256,n] = w_out[256,128] @ att[b,128,n] + b_out
//
// All math fp32 (FFMA). Scratch via __device__ globals (no allocations).

#define NTOK 2304
#define SCALE 0.17677669529663689f   // 32^-0.5

__device__ float g_qkv[8 * 384 * NTOK];   // ~28.3 MB
__device__ float g_att[8 * 128 * NTOK];   // ~9.4 MB

// ---------------------------------------------------------------------------
// Generic tiled SGEMM: C[b] = A @ B[b] (+bias), A row-major [M,K], B row-major
// [K,N], C row-major [M,N]. Block tile 64x64, K-tile 16, 128 threads,
// thread tile 8x4. Requires M%64==0, N%64==0, K%16==0 (true for both uses).
// ---------------------------------------------------------------------------
__global__ __launch_bounds__(128, 4)
void gemm64(const float* __restrict__ A, const float* __restrict__ B,
            float* __restrict__ C, const float* __restrict__ bias,
            int M, int N, int K, size_t strideB, size_t strideC)
{
    __shared__ float As[16][68];   // [k][m], padded (store-transpose conflicts)
    __shared__ float Bs[16][68];   // [k][n]

    const int tid = threadIdx.x;
    const int mb = blockIdx.y * 64;
    const int nb = blockIdx.x * 64;
    const float* Bb = B + (size_t)blockIdx.z * strideB;
    float*       Cb = C + (size_t)blockIdx.z * strideC;

    const int tm8 = (tid >> 4) * 8;    // 8 row-groups
    const int tn4 = (tid & 15) * 4;    // 16 col-groups

    float acc[8][4];
#pragma unroll
    for (int r = 0; r < 8; r++)
#pragma unroll
        for (int c = 0; c < 4; c++) acc[r][c] = 0.f;

    const int lam = tid >> 2;          // 0..31 (A tile row)
    const int lak = (tid & 3) * 4;     // 0,4,8,12 (A tile k)
    const int lbk = tid >> 4;          // 0..7 (B tile k)
    const int lbn = (tid & 15) * 4;    // B tile col

    for (int k0 = 0; k0 < K; k0 += 16) {
        __syncthreads();
#pragma unroll
        for (int i = 0; i < 2; i++) {
            float4 a = *(const float4*)(A + (size_t)(mb + lam + 32 * i) * K + k0 + lak);
            As[lak + 0][lam + 32 * i] = a.x;
            As[lak + 1][lam + 32 * i] = a.y;
            As[lak + 2][lam + 32 * i] = a.z;
            As[lak + 3][lam + 32 * i] = a.w;
        }
#pragma unroll
        for (int i = 0; i < 2; i++) {
            *(float4*)&Bs[lbk + 8 * i][lbn] =
                *(const float4*)(Bb + (size_t)(k0 + lbk + 8 * i) * N + nb + lbn);
        }
        __syncthreads();
#pragma unroll
        for (int kk = 0; kk < 16; kk++) {
            float4 b4 = *(float4*)&Bs[kk][tn4];
            float4 a0 = *(float4*)&As[kk][tm8];
            float4 a1 = *(float4*)&As[kk][tm8 + 4];
            float av[8] = {a0.x, a0.y, a0.z, a0.w, a1.x, a1.y, a1.z, a1.w};
            float bv[4] = {b4.x, b4.y, b4.z, b4.w};
#pragma unroll
            for (int r = 0; r < 8; r++)
#pragma unroll
                for (int c = 0; c < 4; c++)
                    acc[r][c] += av[r] * bv[c];
        }
    }

#pragma unroll
    for (int r = 0; r < 8; r++) {
        int row = mb + tm8 + r;
        float bsv = bias ? bias[row] : 0.f;
        float4 res = make_float4(acc[r][0] + bsv, acc[r][1] + bsv,
                                 acc[r][2] + bsv, acc[r][3] + bsv);
        *(float4*)(Cb + (size_t)row * N + nb + tn4) = res;
    }
}

// ---------------------------------------------------------------------------
// Flash attention. Grid (n/64, heads, batch), 128 threads.
// qkv layout: [b][384][n] with q rows 0..127, k 128..255, v 256..383;
// head h occupies rows h*32..h*32+31 of each segment, d-major.
// Output att[b][h*32+d][token] = softmax-weighted V.
// ---------------------------------------------------------------------------
#define DOT4(P, V) ((P).x * (V).x + (P).y * (V).y + (P).z * (V).z + (P).w * (V).w)

__global__ __launch_bounds__(128, 4)
void attn_kernel(const float* __restrict__ qkv, float* __restrict__ outp)
{
    __shared__ float Qs[32][64];      // [d][query]
    __shared__ float Ks[32][64];      // [d][key]
    __shared__ float Vs[32][64];      // [d][key]
    __shared__ float Ps[64][68];      // [query][key] exp(S - m)
    __shared__ float Als[64];         // per-row rescale alpha
    __shared__ float Lls[64];         // per-row final l

    const int tid = threadIdx.x;
    const int q0 = blockIdx.x * 64;
    const int hh = blockIdx.y;
    const int bb = blockIdx.z;

    const float* Qg = qkv + ((size_t)bb * 384 + 0   + hh * 32) * NTOK;
    const float* Kg = qkv + ((size_t)bb * 384 + 128 + hh * 32) * NTOK;
    const float* Vg = qkv + ((size_t)bb * 384 + 256 + hh * 32) * NTOK;

    const int lc4 = (tid & 15) * 4;   // tile-load col
    const int ldr = tid >> 4;         // tile-load d row (0..7)

    // Load Q tile (scaled). Protected by the sync after the first K/V load.
#pragma unroll
    for (int i = 0; i < 4; i++) {
        int d = ldr + 8 * i;
        float4 v = *(const float4*)(Qg + (size_t)d * NTOK + q0 + lc4);
        v.x *= SCALE; v.y *= SCALE; v.z *= SCALE; v.w *= SCALE;
        *(float4*)&Qs[d][lc4] = v;
    }

    // S-phase mapping: rows tq8..tq8+7 (query), cols tk4..tk4+3 (key)
    const int tq8 = (tid >> 4) * 8;
    const int tk4 = (tid & 15) * 4;
    // O-phase mapping: rows {ti, ti+16, ti+32, ti+48}, dims tj4..tj4+3
    const int ti  = tid & 15;
    const int tj4 = (tid >> 4) * 4;

    float m[8], l[8];
#pragma unroll
    for (int r = 0; r < 8; r++) { m[r] = -1e30f; l[r] = 0.f; }
    float o[4][4];
#pragma unroll
    for (int r = 0; r < 4; r++)
#pragma unroll
        for (int c = 0; c < 4; c++) o[r][c] = 0.f;

    for (int kb = 0; kb < NTOK; kb += 64) {
        __syncthreads();   // prior iter's Ps/Vs reads done before overwrite
#pragma unroll
        for (int i = 0; i < 4; i++) {
            int d = ldr + 8 * i;
            *(float4*)&Ks[d][lc4] = *(const float4*)(Kg + (size_t)d * NTOK + kb + lc4);
            *(float4*)&Vs[d][lc4] = *(const float4*)(Vg + (size_t)d * NTOK + kb + lc4);
        }
        __syncthreads();

        // ---- S = (scale*Q)^T K : 8x4 per thread --------------------------
        float s[8][4];
#pragma unroll
        for (int r = 0; r < 8; r++)
#pragma unroll
            for (int c = 0; c < 4; c++) s[r][c] = 0.f;

#pragma unroll
        for (int d = 0; d < 32; d++) {
            float4 k4 = *(float4*)&Ks[d][tk4];
            float4 qa = *(float4*)&Qs[d][tq8];
            float4 qb = *(float4*)&Qs[d][tq8 + 4];
            float qv[8] = {qa.x, qa.y, qa.z, qa.w, qb.x, qb.y, qb.z, qb.w};
            float kv[4] = {k4.x, k4.y, k4.z, k4.w};
#pragma unroll
            for (int r = 0; r < 8; r++)
#pragma unroll
                for (int c = 0; c < 4; c++)
                    s[r][c] += qv[r] * kv[c];
        }

        // ---- online softmax (reduce over the 16 tk lanes; xor<=8 stays
        //      inside the 16-lane half-warp group) --------------------------
        float alpha[8];
#pragma unroll
        for (int r = 0; r < 8; r++) {
            float mt = fmaxf(fmaxf(s[r][0], s[r][1]), fmaxf(s[r][2], s[r][3]));
#pragma unroll
            for (int off = 8; off; off >>= 1)
                mt = fmaxf(mt, __shfl_xor_sync(0xffffffffu, mt, off));
            float mn = fmaxf(m[r], mt);
            alpha[r] = __expf(m[r] - mn);
            m[r] = mn;
            float rs = 0.f;
#pragma unroll
            for (int c = 0; c < 4; c++) {
                float p = __expf(s[r][c] - mn);
                s[r][c] = p;
                rs += p;
            }
#pragma unroll
            for (int off = 8; off; off >>= 1)
                rs += __shfl_xor_sync(0xffffffffu, rs, off);
            l[r] = l[r] * alpha[r] + rs;
        }

#pragma unroll
        for (int r = 0; r < 8; r++)
            *(float4*)&Ps[tq8 + r][tk4] = make_float4(s[r][0], s[r][1], s[r][2], s[r][3]);
        if ((tid & 15) == 0) {
#pragma unroll
            for (int r = 0; r < 8; r++) Als[tq8 + r] = alpha[r];
        }
        __syncthreads();

        // ---- O = alpha*O + P @ V^T : 4 rows x 4 dims per thread ----------
        float a0 = Als[ti], a1 = Als[ti + 16], a2 = Als[ti + 32], a3 = Als[ti + 48];
#pragma unroll
        for (int c = 0; c < 4; c++) {
            o[0][c] *= a0; o[1][c] *= a1; o[2][c] *= a2; o[3][c] *= a3;
        }
#pragma unroll
        for (int j = 0; j < 64; j += 4) {
            float4 p0 = *(float4*)&Ps[ti][j];
            float4 p1 = *(float4*)&Ps[ti + 16][j];
            float4 p2 = *(float4*)&Ps[ti + 32][j];
            float4 p3 = *(float4*)&Ps[ti + 48][j];
            float4 v0 = *(float4*)&Vs[tj4 + 0][j];
            float4 v1 = *(float4*)&Vs[tj4 + 1][j];
            float4 v2 = *(float4*)&Vs[tj4 + 2][j];
            float4 v3 = *(float4*)&Vs[tj4 + 3][j];
            o[0][0] += DOT4(p0, v0); o[0][1] += DOT4(p0, v1);
            o[0][2] += DOT4(p0, v2); o[0][3] += DOT4(p0, v3);
            o[1][0] += DOT4(p1, v0); o[1][1] += DOT4(p1, v1);
            o[1][2] += DOT4(p1, v2); o[1][3] += DOT4(p1, v3);
            o[2][0] += DOT4(p2, v0); o[2][1] += DOT4(p2, v1);
            o[2][2] += DOT4(p2, v2); o[2][3] += DOT4(p2, v3);
            o[3][0] += DOT4(p3, v0); o[3][1] += DOT4(p3, v1);
            o[3][2] += DOT4(p3, v2); o[3][3] += DOT4(p3, v3);
        }
    }

    __syncthreads();
    if ((tid & 15) == 0) {
#pragma unroll
        for (int r = 0; r < 8; r++) Lls[tq8 + r] = l[r];
    }
    __syncthreads();

    float i0 = 1.f / Lls[ti];
    float i1 = 1.f / Lls[ti + 16];
    float i2 = 1.f / Lls[ti + 32];
    float i3 = 1.f / Lls[ti + 48];

#pragma unroll
    for (int c = 0; c < 4; c++) {
        float* dst = outp + ((size_t)bb * 128 + hh * 32 + tj4 + c) * NTOK + q0;
        dst[ti]      = o[0][c] * i0;
        dst[ti + 16] = o[1][c] * i1;
        dst[ti + 32] = o[2][c] * i2;
        dst[ti + 48] = o[3][c] * i3;
    }
}

// ---------------------------------------------------------------------------
extern "C" void kernel_launch(void* const* d_in, const int* in_sizes, int n_in,
                              void* d_out, int out_size)
{
    const float* x     = (const float*)d_in[0];   // [8,256,48,48]
    const float* w_qkv = (const float*)d_in[1];   // [384,256]
    const float* w_out = (const float*)d_in[2];   // [256,128]
    const float* b_out = (const float*)d_in[3];   // [256]
    float* out = (float*)d_out;                   // [8,256,48,48]

    float* qkv = nullptr;
    float* att = nullptr;
    cudaGetSymbolAddress((void**)&qkv, g_qkv);
    cudaGetSymbolAddress((void**)&att, g_att);

    dim3 threads(128);

    // 1) QKV projection: per batch [384,2304] = [384,256] @ [256,2304]
    gemm64<<<dim3(NTOK / 64, 384 / 64, 8), threads>>>(
        w_qkv, x, qkv, nullptr,
        384, NTOK, 256,
        (size_t)256 * NTOK, (size_t)384 * NTOK);

    // 2) Attention
    attn_kernel<<<dim3(NTOK / 64, 4, 8), threads>>>(qkv, att);

    // 3) Output projection + bias: per batch [256,2304] = [256,128] @ [128,2304]
    gemm64<<<dim3(NTOK / 64, 256 / 64, 8), threads>>>(
        w_out, att, out, b_out,
        256, NTOK, 128,
        (size_t)128 * NTOK, (size_t)256 * NTOK);
}

// round 8
// speedup vs baseline: 2.4801x; 2.4555x over previous
#include <cuda_runtime.h>
#include <cuda_bf16.h>
#include <cstdint>

// Attention_9328668967755 — HMMA (mma.sync bf16 split) attention + fp32 projections.
// b=8, c=256, n=2304, heads=4, d_head=32.
//  1) gemm64 (fp32): qkv = w_qkv @ x
//  2) prep_qk / prep_v: transpose+bf16-split Q(pre-scaled),K ; split V
//  3) attn_hmma: S = QK^T (3 split terms, mma.m16n8k16), exp (no max-sub),
//     P split in registers, O += P V^T (3 terms), O in fp32 registers.
//  4) gemm64 (fp32): out = w_out @ att + b_out

#define NTOK 2304
#define NT2  1152
#define SCALE 0.17677669529663689f

__device__ float g_qkv[8 * 384 * NTOK];
__device__ float g_att[8 * 128 * NTOK];
__device__ unsigned g_qh[8 * 4 * NTOK * 16];  // [bh][tok][16 u32] bf16x2 hi (32 d)
__device__ unsigned g_ql[8 * 4 * NTOK * 16];
__device__ unsigned g_kh[8 * 4 * NTOK * 16];
__device__ unsigned g_kl[8 * 4 * NTOK * 16];
__device__ unsigned g_vh[8 * 128 * NT2];      // [b*128+hd][NT2 u32] bf16x2 (token pairs)
__device__ unsigned g_vl[8 * 128 * NT2];

// ---------------- helpers ----------------
__device__ __forceinline__ uint32_t cvt_bf16x2(float lo, float hi) {
    uint32_t r;
    asm("cvt.rn.satfinite.bf16x2.f32 %0, %1, %2;" : "=r"(r) : "f"(hi), "f"(lo));
    return r;
}
__device__ __forceinline__ float bflo(uint32_t u) { return __uint_as_float(u << 16); }
__device__ __forceinline__ float bfhi(uint32_t u) { return __uint_as_float(u & 0xffff0000u); }

__device__ __forceinline__ void mma16816(float* c, const uint32_t* a,
                                         uint32_t b0, uint32_t b1) {
    asm volatile(
        "mma.sync.aligned.m16n8k16.row.col.f32.bf16.bf16.f32 "
        "{%0,%1,%2,%3}, {%4,%5,%6,%7}, {%8,%9}, {%0,%1,%2,%3};"
        : "+f"(c[0]), "+f"(c[1]), "+f"(c[2]), "+f"(c[3])
        : "r"(a[0]), "r"(a[1]), "r"(a[2]), "r"(a[3]), "r"(b0), "r"(b1));
}

// ---------------- fp32 GEMM ----------------
__global__ __launch_bounds__(128, 4)
void gemm64(const float* __restrict__ A, const float* __restrict__ B,
            float* __restrict__ C, const float* __restrict__ bias,
            int M, int N, int K, size_t strideB, size_t strideC)
{
    __shared__ float As[16][68];
    __shared__ float Bs[16][68];
    const int tid = threadIdx.x;
    const int mb = blockIdx.y * 64, nb = blockIdx.x * 64;
    const float* Bb = B + (size_t)blockIdx.z * strideB;
    float*       Cb = C + (size_t)blockIdx.z * strideC;
    const int tm8 = (tid >> 4) * 8, tn4 = (tid & 15) * 4;

    float acc[8][4];
#pragma unroll
    for (int r = 0; r < 8; r++)
#pragma unroll
        for (int c = 0; c < 4; c++) acc[r][c] = 0.f;

    const int lam = tid >> 2, lak = (tid & 3) * 4;
    const int lbk = tid >> 4, lbn = (tid & 15) * 4;

    for (int k0 = 0; k0 < K; k0 += 16) {
        __syncthreads();
#pragma unroll
        for (int i = 0; i < 2; i++) {
            float4 a = *(const float4*)(A + (size_t)(mb + lam + 32 * i) * K + k0 + lak);
            As[lak + 0][lam + 32 * i] = a.x; As[lak + 1][lam + 32 * i] = a.y;
            As[lak + 2][lam + 32 * i] = a.z; As[lak + 3][lam + 32 * i] = a.w;
        }
#pragma unroll
        for (int i = 0; i < 2; i++)
            *(float4*)&Bs[lbk + 8 * i][lbn] =
                *(const float4*)(Bb + (size_t)(k0 + lbk + 8 * i) * N + nb + lbn);
        __syncthreads();
#pragma unroll
        for (int kk = 0; kk < 16; kk++) {
            float4 b4 = *(float4*)&Bs[kk][tn4];
            float4 a0 = *(float4*)&As[kk][tm8];
            float4 a1 = *(float4*)&As[kk][tm8 + 4];
            float av[8] = {a0.x, a0.y, a0.z, a0.w, a1.x, a1.y, a1.z, a1.w};
            float bv[4] = {b4.x, b4.y, b4.z, b4.w};
#pragma unroll
            for (int r = 0; r < 8; r++)
#pragma unroll
                for (int c = 0; c < 4; c++) acc[r][c] += av[r] * bv[c];
        }
    }
#pragma unroll
    for (int r = 0; r < 8; r++) {
        int row = mb + tm8 + r;
        float bsv = bias ? bias[row] : 0.f;
        *(float4*)(Cb + (size_t)row * N + nb + tn4) =
            make_float4(acc[r][0] + bsv, acc[r][1] + bsv, acc[r][2] + bsv, acc[r][3] + bsv);
    }
}

// ---------------- prep kernels ----------------
__global__ __launch_bounds__(256)
void prep_qk()
{
    __shared__ float ts[32][33];
    const int t = threadIdx.x;
    const int tile = blockIdx.x;          // token tile of 32
    const int hy = blockIdx.y;            // h + 4*isK
    const int b = blockIdx.z;
    const int isK = hy >> 2, h = hy & 3;

    const float* src = g_qkv + ((size_t)b * 384 + (size_t)isK * 128 + h * 32) * NTOK
                       + (size_t)tile * 32;
    {
        int r = t >> 3, c = (t & 7) * 4;
        float4 v = *(const float4*)(src + (size_t)r * NTOK + c);
        ts[r][c + 0] = v.x; ts[r][c + 1] = v.y; ts[r][c + 2] = v.z; ts[r][c + 3] = v.w;
    }
    __syncthreads();

    int tok = t >> 3, d0 = (t & 7) * 4;
    float f0 = ts[d0 + 0][tok], f1 = ts[d0 + 1][tok];
    float f2 = ts[d0 + 2][tok], f3 = ts[d0 + 3][tok];
    if (!isK) { f0 *= SCALE; f1 *= SCALE; f2 *= SCALE; f3 *= SCALE; }

    uint32_t h01 = cvt_bf16x2(f0, f1);
    uint32_t l01 = cvt_bf16x2(f0 - bflo(h01), f1 - bfhi(h01));
    uint32_t h23 = cvt_bf16x2(f2, f3);
    uint32_t l23 = cvt_bf16x2(f2 - bflo(h23), f3 - bfhi(h23));

    unsigned* oh = isK ? g_kh : g_qh;
    unsigned* ol = isK ? g_kl : g_ql;
    size_t idx = ((size_t)(b * 4 + h) * NTOK + (size_t)tile * 32 + tok) * 16 + (t & 7) * 2;
    oh[idx] = h01; oh[idx + 1] = h23;
    ol[idx] = l01; ol[idx + 1] = l23;
}

__global__ __launch_bounds__(256)
void prep_v()
{
    size_t idx = (size_t)blockIdx.x * 256 + threadIdx.x;
    const size_t per_b = (size_t)128 * NT2;
    size_t b = idx / per_b, rem = idx % per_b;
    const float2 s = *(const float2*)(g_qkv + ((size_t)b * 384 + 256) * NTOK + rem * 2);
    uint32_t hw = cvt_bf16x2(s.x, s.y);
    uint32_t lw = cvt_bf16x2(s.x - bflo(hw), s.y - bfhi(hw));
    g_vh[idx] = hw;
    g_vl[idx] = lw;
}

// ---------------- attention (HMMA) ----------------
// Grid (18, 4, 8); 128 threads = 4 warps x 32 queries.
// Per tile: 64 keys. K smem: 64 rows x 16 u32, row stride 80B (conflict-free frags).
// V smem: 32 d-rows x 32 u32 (64 tok bf16), row stride 144B (conflict-free frags).
__global__ __launch_bounds__(128, 2)
void attn_hmma()
{
    __shared__ __align__(16) unsigned char sKh[5120];
    __shared__ __align__(16) unsigned char sKl[5120];
    __shared__ __align__(16) unsigned char sVh[4608];
    __shared__ __align__(16) unsigned char sVl[4608];

    const int tid = threadIdx.x;
    const int w = tid >> 5, lane = tid & 31;
    const int t4 = lane >> 2, tm4 = lane & 3;
    const int q0 = blockIdx.x * 128;
    const int h = blockIdx.y, b = blockIdx.z;
    const int bh = b * 4 + h;

    // ---- Q fragments (loaded once from global) ----
    // a-frag m16n8k16: reg r -> row = t4 + 8*(r&1), k-pair word = tm4 + 4*(r>>1)
    uint32_t qh[2][2][4], ql[2][2][4];
#pragma unroll
    for (int f = 0; f < 2; f++)
#pragma unroll
        for (int ks = 0; ks < 2; ks++)
#pragma unroll
            for (int r = 0; r < 4; r++) {
                int row = q0 + w * 32 + f * 16 + (r & 1) * 8 + t4;
                int word = ks * 8 + tm4 + (r >> 1) * 4;
                size_t gi = ((size_t)bh * NTOK + row) * 16 + word;
                qh[f][ks][r] = g_qh[gi];
                ql[f][ks][r] = g_ql[gi];
            }

    float o[2][4][4];
#pragma unroll
    for (int f = 0; f < 2; f++)
#pragma unroll
        for (int j = 0; j < 4; j++)
#pragma unroll
            for (int r = 0; r < 4; r++) o[f][j][r] = 0.f;
    float lsum[2][2] = {{0.f, 0.f}, {0.f, 0.f}};

    // cooperative-load addressing
    const int ktok = tid >> 1, khalf = tid & 1;
    const size_t kgbase = ((size_t)bh * NTOK + ktok) * 16 + khalf * 8;
    unsigned char* ksh = sKh + ktok * 80 + khalf * 32;
    unsigned char* ksl = sKl + ktok * 80 + khalf * 32;
    const int vd = tid >> 2, vq = tid & 3;
    const size_t vgbase = ((size_t)(b * 128 + h * 32 + vd)) * NT2 + vq * 8;
    unsigned char* vsh = sVh + vd * 144 + vq * 32;
    unsigned char* vsl = sVl + vd * 144 + vq * 32;

    // fragment-load bases
    const unsigned char* kfh = sKh + t4 * 80 + tm4 * 4;
    const unsigned char* kfl = sKl + t4 * 80 + tm4 * 4;
    const unsigned char* vfh = sVh + t4 * 144 + tm4 * 4;
    const unsigned char* vfl = sVl + t4 * 144 + tm4 * 4;

    for (int t = 0; t < 36; t++) {
        __syncthreads();
        {
            const uint4* s = (const uint4*)(g_kh + kgbase + (size_t)t * 64 * 16);
            uint4 a = s[0], c = s[1];
            *(uint4*)ksh = a; *(uint4*)(ksh + 16) = c;
            s = (const uint4*)(g_kl + kgbase + (size_t)t * 64 * 16);
            a = s[0]; c = s[1];
            *(uint4*)ksl = a; *(uint4*)(ksl + 16) = c;
            s = (const uint4*)(g_vh + vgbase + t * 32);
            a = s[0]; c = s[1];
            *(uint4*)vsh = a; *(uint4*)(vsh + 16) = c;
            s = (const uint4*)(g_vl + vgbase + t * 32);
            a = s[0]; c = s[1];
            *(uint4*)vsl = a; *(uint4*)(vsl + 16) = c;
        }
        __syncthreads();

        uint32_t pah[2][4][4], pal[2][4][4];
        float ep[2][4];

        // ---- S = QK^T per 8-token ntile, exp, pack P ----
#pragma unroll
        for (int i = 0; i < 8; i++) {
            const unsigned char* ka = kfh + i * 640;
            const unsigned char* kb_ = kfl + i * 640;
            uint32_t bh0 = *(const uint32_t*)(ka);
            uint32_t bh1 = *(const uint32_t*)(ka + 16);
            uint32_t bh2 = *(const uint32_t*)(ka + 32);
            uint32_t bh3 = *(const uint32_t*)(ka + 48);
            uint32_t bl0 = *(const uint32_t*)(kb_);
            uint32_t bl1 = *(const uint32_t*)(kb_ + 16);
            uint32_t bl2 = *(const uint32_t*)(kb_ + 32);
            uint32_t bl3 = *(const uint32_t*)(kb_ + 48);

            float cacc[2][4];
#pragma unroll
            for (int f = 0; f < 2; f++) {
#pragma unroll
                for (int r = 0; r < 4; r++) cacc[f][r] = 0.f;
                mma16816(cacc[f], qh[f][0], bh0, bh1);
                mma16816(cacc[f], qh[f][0], bl0, bl1);
                mma16816(cacc[f], ql[f][0], bh0, bh1);
                mma16816(cacc[f], qh[f][1], bh2, bh3);
                mma16816(cacc[f], qh[f][1], bl2, bl3);
                mma16816(cacc[f], ql[f][1], bh2, bh3);
            }

            float e[2][4];
#pragma unroll
            for (int f = 0; f < 2; f++) {
#pragma unroll
                for (int r = 0; r < 4; r++) e[f][r] = __expf(cacc[f][r]);
                lsum[f][0] += e[f][0] + e[f][1];
                lsum[f][1] += e[f][2] + e[f][3];
            }
            if ((i & 1) == 0) {
#pragma unroll
                for (int f = 0; f < 2; f++)
#pragma unroll
                    for (int r = 0; r < 4; r++) ep[f][r] = e[f][r];
            } else {
                const int m = i >> 1;
#pragma unroll
                for (int f = 0; f < 2; f++) {
                    uint32_t a0 = cvt_bf16x2(ep[f][0], ep[f][1]);
                    uint32_t a1 = cvt_bf16x2(ep[f][2], ep[f][3]);
                    uint32_t a2 = cvt_bf16x2(e[f][0], e[f][1]);
                    uint32_t a3 = cvt_bf16x2(e[f][2], e[f][3]);
                    pah[f][m][0] = a0; pah[f][m][1] = a1;
                    pah[f][m][2] = a2; pah[f][m][3] = a3;
                    pal[f][m][0] = cvt_bf16x2(ep[f][0] - bflo(a0), ep[f][1] - bfhi(a0));
                    pal[f][m][1] = cvt_bf16x2(ep[f][2] - bflo(a1), ep[f][3] - bfhi(a1));
                    pal[f][m][2] = cvt_bf16x2(e[f][0] - bflo(a2), e[f][1] - bfhi(a2));
                    pal[f][m][3] = cvt_bf16x2(e[f][2] - bflo(a3), e[f][3] - bfhi(a3));
                }
            }
        }

        // ---- O += P V^T ----
#pragma unroll
        for (int kt = 0; kt < 4; kt++)
#pragma unroll
            for (int j = 0; j < 4; j++) {
                const unsigned char* va = vfh + j * 1152 + kt * 32;
                const unsigned char* vb = vfl + j * 1152 + kt * 32;
                uint32_t v0 = *(const uint32_t*)va;
                uint32_t v1 = *(const uint32_t*)(va + 16);
                uint32_t u0 = *(const uint32_t*)vb;
                uint32_t u1 = *(const uint32_t*)(vb + 16);
#pragma unroll
                for (int f = 0; f < 2; f++) {
                    mma16816(o[f][j], pah[f][kt], v0, v1);
                    mma16816(o[f][j], pah[f][kt], u0, u1);
                    mma16816(o[f][j], pal[f][kt], v0, v1);
                }
            }
    }

    // ---- epilogue: normalize and store ----
    float inv[2][2];
#pragma unroll
    for (int f = 0; f < 2; f++)
#pragma unroll
        for (int rr = 0; rr < 2; rr++) {
            float lv = lsum[f][rr];
            lv += __shfl_xor_sync(0xffffffffu, lv, 1);
            lv += __shfl_xor_sync(0xffffffffu, lv, 2);
            inv[f][rr] = 1.f / lv;
        }

#pragma unroll
    for (int f = 0; f < 2; f++)
#pragma unroll
        for (int j = 0; j < 4; j++)
#pragma unroll
            for (int rr = 0; rr < 2; rr++) {
                int qrow = q0 + w * 32 + f * 16 + rr * 8 + t4;
#pragma unroll
                for (int cc = 0; cc < 2; cc++) {
                    int drow = h * 32 + j * 8 + tm4 * 2 + cc;
                    g_att[((size_t)b * 128 + drow) * NTOK + qrow] =
                        o[f][j][rr * 2 + cc] * inv[f][rr];
                }
            }
}

// ---------------- launch ----------------
extern "C" void kernel_launch(void* const* d_in, const int* in_sizes, int n_in,
                              void* d_out, int out_size)
{
    const float* x     = (const float*)d_in[0];
    const float* w_qkv = (const float*)d_in[1];
    const float* w_out = (const float*)d_in[2];
    const float* b_out = (const float*)d_in[3];
    float* out = (float*)d_out;

    float* qkv = nullptr;
    float* att = nullptr;
    cudaGetSymbolAddress((void**)&qkv, g_qkv);
    cudaGetSymbolAddress((void**)&att, g_att);

    gemm64<<<dim3(NTOK / 64, 384 / 64, 8), 128>>>(
        w_qkv, x, qkv, nullptr, 384, NTOK, 256,
        (size_t)256 * NTOK, (size_t)384 * NTOK);

    prep_qk<<<dim3(NTOK / 32, 8, 8), 256>>>();
    prep_v<<<dim3((8 * 128 * NT2) / 256), 256>>>();

    attn_hmma<<<dim3(NTOK / 128, 4, 8), 128>>>();

    gemm64<<<dim3(NTOK / 64, 256 / 64, 8), 128>>>(
        w_out, att, out, b_out, 256, NTOK, 128,
        (size_t)128 * NTOK, (size_t)256 * NTOK);
}

// round 9
// speedup vs baseline: 2.5336x; 1.0216x over previous
#include <cuda_runtime.h>
#include <cuda_bf16.h>
#include <cstdint>

// Attention_9328668967755 — all-HMMA (bf16 3-term split) pipeline.
// b=8, c=256, n=2304, heads=4, d_head=32.
//  prep_w : split weights to bf16 hi/lo (k-contiguous u32 pairs)
//  prep_x : transpose+split x -> xt[b][tok][k] hi/lo
//  gemm_hmma(1): qkv[b,384,n] = w_qkv @ x        (fp32 out)
//  prep_qk/prep_v: transpose+split Q(scaled),K ; split V
//  attn_hmma: S=QK^T (3 terms), exp (no max-sub), O += P V^T (3 terms);
//             epilogue writes att as bf16 hi/lo [b][tok][hidden]
//  gemm_hmma(2): out = w_out @ att + b_out       (fp32 out)

#define NTOK 2304
#define NT2  1152
#define SCALE 0.17677669529663689f

__device__ float    g_qkv[8 * 384 * NTOK];
__device__ unsigned g_qh[8 * 4 * NTOK * 16];
__device__ unsigned g_ql[8 * 4 * NTOK * 16];
__device__ unsigned g_kh[8 * 4 * NTOK * 16];
__device__ unsigned g_kl[8 * 4 * NTOK * 16];
__device__ unsigned g_vh[8 * 128 * NT2];
__device__ unsigned g_vl[8 * 128 * NT2];
__device__ unsigned g_xth[8 * NTOK * 128];   // x^T split: [b][tok][128 u32 = 256 k]
__device__ unsigned g_xtl[8 * NTOK * 128];
__device__ unsigned g_ah[8 * NTOK * 64];     // att split: [b][tok][64 u32 = 128 dims]
__device__ unsigned g_al[8 * NTOK * 64];
__device__ unsigned g_wqh[384 * 128];        // w_qkv split: [m][128 u32]
__device__ unsigned g_wql[384 * 128];
__device__ unsigned g_woh[256 * 64];         // w_out split
__device__ unsigned g_wol[256 * 64];

// ---------------- helpers ----------------
__device__ __forceinline__ uint32_t cvt_bf16x2(float lo, float hi) {
    uint32_t r;
    asm("cvt.rn.satfinite.bf16x2.f32 %0, %1, %2;" : "=r"(r) : "f"(hi), "f"(lo));
    return r;
}
__device__ __forceinline__ float bflo(uint32_t u) { return __uint_as_float(u << 16); }
__device__ __forceinline__ float bfhi(uint32_t u) { return __uint_as_float(u & 0xffff0000u); }

__device__ __forceinline__ void mma16816(float* c, const uint32_t* a,
                                         uint32_t b0, uint32_t b1) {
    asm volatile(
        "mma.sync.aligned.m16n8k16.row.col.f32.bf16.bf16.f32 "
        "{%0,%1,%2,%3}, {%4,%5,%6,%7}, {%8,%9}, {%0,%1,%2,%3};"
        : "+f"(c[0]), "+f"(c[1]), "+f"(c[2]), "+f"(c[3])
        : "r"(a[0]), "r"(a[1]), "r"(a[2]), "r"(a[3]), "r"(b0), "r"(b1));
}

// ---------------- prep: weight split ----------------
__global__ __launch_bounds__(256)
void prep_w(const float* __restrict__ src, unsigned* __restrict__ dh,
            unsigned* __restrict__ dl, int nwords)
{
    int idx = blockIdx.x * 256 + threadIdx.x;
    if (idx >= nwords) return;
    float2 s = *(const float2*)(src + (size_t)idx * 2);
    uint32_t hw = cvt_bf16x2(s.x, s.y);
    dh[idx] = hw;
    dl[idx] = cvt_bf16x2(s.x - bflo(hw), s.y - bfhi(hw));
}

// ---------------- prep: x transpose+split ----------------
__global__ __launch_bounds__(256)
void prep_x(const float* __restrict__ x)
{
    __shared__ float ts[32][33];
    const int t = threadIdx.x;
    const int tok0 = blockIdx.x * 32;
    const int k0 = blockIdx.y * 32;
    const int b = blockIdx.z;

    {
        int r = t >> 3, c = (t & 7) * 4;
        float4 v = *(const float4*)(x + ((size_t)b * 256 + k0 + r) * NTOK + tok0 + c);
        ts[r][c + 0] = v.x; ts[r][c + 1] = v.y; ts[r][c + 2] = v.z; ts[r][c + 3] = v.w;
    }
    __syncthreads();

    int tok = t >> 3, kq = (t & 7) * 4;
    float f0 = ts[kq + 0][tok], f1 = ts[kq + 1][tok];
    float f2 = ts[kq + 2][tok], f3 = ts[kq + 3][tok];

    uint32_t h01 = cvt_bf16x2(f0, f1);
    uint32_t l01 = cvt_bf16x2(f0 - bflo(h01), f1 - bfhi(h01));
    uint32_t h23 = cvt_bf16x2(f2, f3);
    uint32_t l23 = cvt_bf16x2(f2 - bflo(h23), f3 - bfhi(h23));

    size_t gi = ((size_t)b * NTOK + tok0 + tok) * 128 + (k0 + kq) / 2;
    g_xth[gi] = h01; g_xth[gi + 1] = h23;
    g_xtl[gi] = l01; g_xtl[gi + 1] = l23;
}

// ---------------- prep: qk transpose+split ----------------
__global__ __launch_bounds__(256)
void prep_qk()
{
    __shared__ float ts[32][33];
    const int t = threadIdx.x;
    const int tile = blockIdx.x;
    const int hy = blockIdx.y;
    const int b = blockIdx.z;
    const int isK = hy >> 2, h = hy & 3;

    const float* src = g_qkv + ((size_t)b * 384 + (size_t)isK * 128 + h * 32) * NTOK
                       + (size_t)tile * 32;
    {
        int r = t >> 3, c = (t & 7) * 4;
        float4 v = *(const float4*)(src + (size_t)r * NTOK + c);
        ts[r][c + 0] = v.x; ts[r][c + 1] = v.y; ts[r][c + 2] = v.z; ts[r][c + 3] = v.w;
    }
    __syncthreads();

    int tok = t >> 3, d0 = (t & 7) * 4;
    float f0 = ts[d0 + 0][tok], f1 = ts[d0 + 1][tok];
    float f2 = ts[d0 + 2][tok], f3 = ts[d0 + 3][tok];
    if (!isK) { f0 *= SCALE; f1 *= SCALE; f2 *= SCALE; f3 *= SCALE; }

    uint32_t h01 = cvt_bf16x2(f0, f1);
    uint32_t l01 = cvt_bf16x2(f0 - bflo(h01), f1 - bfhi(h01));
    uint32_t h23 = cvt_bf16x2(f2, f3);
    uint32_t l23 = cvt_bf16x2(f2 - bflo(h23), f3 - bfhi(h23));

    unsigned* oh = isK ? g_kh : g_qh;
    unsigned* ol = isK ? g_kl : g_ql;
    size_t idx = ((size_t)(b * 4 + h) * NTOK + (size_t)tile * 32 + tok) * 16 + (t & 7) * 2;
    oh[idx] = h01; oh[idx + 1] = h23;
    ol[idx] = l01; ol[idx + 1] = l23;
}

__global__ __launch_bounds__(256)
void prep_v()
{
    size_t idx = (size_t)blockIdx.x * 256 + threadIdx.x;
    const size_t per_b = (size_t)128 * NT2;
    size_t b = idx / per_b, rem = idx % per_b;
    const float2 s = *(const float2*)(g_qkv + ((size_t)b * 384 + 256) * NTOK + rem * 2);
    uint32_t hw = cvt_bf16x2(s.x, s.y);
    uint32_t lw = cvt_bf16x2(s.x - bflo(hw), s.y - bfhi(hw));
    g_vh[idx] = hw;
    g_vl[idx] = lw;
}

// ---------------- HMMA GEMM: C[b][M][N] = Wsplit @ Xsplit^T (+bias) ----------------
// W: [M][K/2 u32] hi/lo.  X: [b][N tok][K/2 u32] hi/lo.  C fp32 [b][M][N].
// Grid (N/64, M/128, 8), 128 threads = 4 warps x 32 rows.
__global__ __launch_bounds__(128, 3)
void gemm_hmma(const unsigned* __restrict__ wh, const unsigned* __restrict__ wl,
               const unsigned* __restrict__ xh, const unsigned* __restrict__ xl,
               float* __restrict__ C, const float* __restrict__ bias,
               int M, int K)
{
    __shared__ __align__(16) unsigned char sWh[10240];  // 128 rows x 80B
    __shared__ __align__(16) unsigned char sWl[10240];
    __shared__ __align__(16) unsigned char sXh[5120];   // 64 rows x 80B
    __shared__ __align__(16) unsigned char sXl[5120];

    const int tid = threadIdx.x;
    const int w = tid >> 5, lane = tid & 31;
    const int t4 = lane >> 2, tm4 = lane & 3;
    const int nb = blockIdx.x * 64;
    const int mb = blockIdx.y * 128;
    const int bz = blockIdx.z;
    const int kws = K / 2;

    float o[2][8][4];
#pragma unroll
    for (int f = 0; f < 2; f++)
#pragma unroll
        for (int nf = 0; nf < 8; nf++)
#pragma unroll
            for (int r = 0; r < 4; r++) o[f][nf][r] = 0.f;

    const unsigned* wgh = wh + (size_t)(mb + tid) * kws;
    const unsigned* wgl = wl + (size_t)(mb + tid) * kws;
    const int xtok = tid >> 1, xhalf = tid & 1;
    const unsigned* xgh = xh + ((size_t)bz * NTOK + nb + xtok) * kws + xhalf * 8;
    const unsigned* xgl = xl + ((size_t)bz * NTOK + nb + xtok) * kws + xhalf * 8;
    unsigned char* swh = sWh + tid * 80;
    unsigned char* swl = sWl + tid * 80;
    unsigned char* sxh = sXh + xtok * 80 + xhalf * 32;
    unsigned char* sxl = sXl + xtok * 80 + xhalf * 32;

    const unsigned char* wfh = sWh + (w * 32 + t4) * 80 + tm4 * 4;
    const unsigned char* wfl = sWl + (w * 32 + t4) * 80 + tm4 * 4;
    const unsigned char* xfh = sXh + t4 * 80 + tm4 * 4;
    const unsigned char* xfl = sXl + t4 * 80 + tm4 * 4;

    for (int k0 = 0; k0 < kws; k0 += 16) {
        __syncthreads();
#pragma unroll
        for (int i = 0; i < 4; i++) {
            uint4 a = *(const uint4*)(wgh + k0 + i * 4);
            *(uint4*)(swh + i * 16) = a;
            a = *(const uint4*)(wgl + k0 + i * 4);
            *(uint4*)(swl + i * 16) = a;
        }
#pragma unroll
        for (int i = 0; i < 2; i++) {
            uint4 a = *(const uint4*)(xgh + k0 + i * 4);
            *(uint4*)(sxh + i * 16) = a;
            a = *(const uint4*)(xgl + k0 + i * 4);
            *(uint4*)(sxl + i * 16) = a;
        }
        __syncthreads();

#pragma unroll
        for (int ks = 0; ks < 2; ks++) {
            uint32_t ah[2][4], al[2][4];
#pragma unroll
            for (int f = 0; f < 2; f++)
#pragma unroll
                for (int r = 0; r < 4; r++) {
                    int off = (f * 16 + (r & 1) * 8) * 80 + ((r >> 1) * 4 + ks * 8) * 4;
                    ah[f][r] = *(const uint32_t*)(wfh + off);
                    al[f][r] = *(const uint32_t*)(wfl + off);
                }
#pragma unroll
            for (int nf = 0; nf < 8; nf++) {
                const unsigned char* ba = xfh + nf * 640 + ks * 32;
                const unsigned char* bb = xfl + nf * 640 + ks * 32;
                uint32_t bh0 = *(const uint32_t*)ba;
                uint32_t bh1 = *(const uint32_t*)(ba + 16);
                uint32_t bl0 = *(const uint32_t*)bb;
                uint32_t bl1 = *(const uint32_t*)(bb + 16);
#pragma unroll
                for (int f = 0; f < 2; f++) {
                    mma16816(o[f][nf], ah[f], bh0, bh1);
                    mma16816(o[f][nf], ah[f], bl0, bl1);
                    mma16816(o[f][nf], al[f], bh0, bh1);
                }
            }
        }
    }

    // epilogue
    float* Cb = C + (size_t)bz * M * NTOK;
#pragma unroll
    for (int f = 0; f < 2; f++) {
        int row0 = mb + w * 32 + f * 16 + t4;
        int row1 = row0 + 8;
        float b0 = bias ? bias[row0] : 0.f;
        float b1 = bias ? bias[row1] : 0.f;
#pragma unroll
        for (int nf = 0; nf < 8; nf++) {
            int col = nb + nf * 8 + tm4 * 2;
            *(float2*)(Cb + (size_t)row0 * NTOK + col) =
                make_float2(o[f][nf][0] + b0, o[f][nf][1] + b0);
            *(float2*)(Cb + (size_t)row1 * NTOK + col) =
                make_float2(o[f][nf][2] + b1, o[f][nf][3] + b1);
        }
    }
}

// ---------------- attention (HMMA, interleaved S->PV) ----------------
__global__ __launch_bounds__(128, 3)
void attn_hmma()
{
    __shared__ __align__(16) unsigned char sKh[5120];
    __shared__ __align__(16) unsigned char sKl[5120];
    __shared__ __align__(16) unsigned char sVh[4608];
    __shared__ __align__(16) unsigned char sVl[4608];

    const int tid = threadIdx.x;
    const int w = tid >> 5, lane = tid & 31;
    const int t4 = lane >> 2, tm4 = lane & 3;
    const int q0 = blockIdx.x * 128;
    const int h = blockIdx.y, b = blockIdx.z;
    const int bh = b * 4 + h;

    uint32_t qh[2][2][4], ql[2][2][4];
#pragma unroll
    for (int f = 0; f < 2; f++)
#pragma unroll
        for (int ks = 0; ks < 2; ks++)
#pragma unroll
            for (int r = 0; r < 4; r++) {
                int row = q0 + w * 32 + f * 16 + (r & 1) * 8 + t4;
                int word = ks * 8 + tm4 + (r >> 1) * 4;
                size_t gi = ((size_t)bh * NTOK + row) * 16 + word;
                qh[f][ks][r] = g_qh[gi];
                ql[f][ks][r] = g_ql[gi];
            }

    float o[2][4][4];
#pragma unroll
    for (int f = 0; f < 2; f++)
#pragma unroll
        for (int j = 0; j < 4; j++)
#pragma unroll
            for (int r = 0; r < 4; r++) o[f][j][r] = 0.f;
    float lsum[2][2] = {{0.f, 0.f}, {0.f, 0.f}};

    const int ktok = tid >> 1, khalf = tid & 1;
    const size_t kgbase = ((size_t)bh * NTOK + ktok) * 16 + khalf * 8;
    unsigned char* ksh = sKh + ktok * 80 + khalf * 32;
    unsigned char* ksl = sKl + ktok * 80 + khalf * 32;
    const int vd = tid >> 2, vq = tid & 3;
    const size_t vgbase = ((size_t)(b * 128 + h * 32 + vd)) * NT2 + vq * 8;
    unsigned char* vsh = sVh + vd * 144 + vq * 32;
    unsigned char* vsl = sVl + vd * 144 + vq * 32;

    const unsigned char* kfh = sKh + t4 * 80 + tm4 * 4;
    const unsigned char* kfl = sKl + t4 * 80 + tm4 * 4;
    const unsigned char* vfh = sVh + t4 * 144 + tm4 * 4;
    const unsigned char* vfl = sVl + t4 * 144 + tm4 * 4;

    for (int t = 0; t < 36; t++) {
        __syncthreads();
        {
            const uint4* s = (const uint4*)(g_kh + kgbase + (size_t)t * 64 * 16);
            uint4 a = s[0], c = s[1];
            *(uint4*)ksh = a; *(uint4*)(ksh + 16) = c;
            s = (const uint4*)(g_kl + kgbase + (size_t)t * 64 * 16);
            a = s[0]; c = s[1];
            *(uint4*)ksl = a; *(uint4*)(ksl + 16) = c;
            s = (const uint4*)(g_vh + vgbase + t * 32);
            a = s[0]; c = s[1];
            *(uint4*)vsh = a; *(uint4*)(vsh + 16) = c;
            s = (const uint4*)(g_vl + vgbase + t * 32);
            a = s[0]; c = s[1];
            *(uint4*)vsl = a; *(uint4*)(vsl + 16) = c;
        }
        __syncthreads();

        // per 16-key chunk: S (2 ntiles) -> exp -> pack -> PV
#pragma unroll
        for (int kt = 0; kt < 4; kt++) {
            float e2[2][2][4];
#pragma unroll
            for (int ii = 0; ii < 2; ii++) {
                const int i = kt * 2 + ii;
                const unsigned char* ka = kfh + i * 640;
                const unsigned char* kb_ = kfl + i * 640;
                uint32_t bh0 = *(const uint32_t*)(ka);
                uint32_t bh1 = *(const uint32_t*)(ka + 16);
                uint32_t bh2 = *(const uint32_t*)(ka + 32);
                uint32_t bh3 = *(const uint32_t*)(ka + 48);
                uint32_t bl0 = *(const uint32_t*)(kb_);
                uint32_t bl1 = *(const uint32_t*)(kb_ + 16);
                uint32_t bl2 = *(const uint32_t*)(kb_ + 32);
                uint32_t bl3 = *(const uint32_t*)(kb_ + 48);

#pragma unroll
                for (int f = 0; f < 2; f++) {
                    float cacc[4] = {0.f, 0.f, 0.f, 0.f};
                    mma16816(cacc, qh[f][0], bh0, bh1);
                    mma16816(cacc, qh[f][0], bl0, bl1);
                    mma16816(cacc, ql[f][0], bh0, bh1);
                    mma16816(cacc, qh[f][1], bh2, bh3);
                    mma16816(cacc, qh[f][1], bl2, bl3);
                    mma16816(cacc, ql[f][1], bh2, bh3);
#pragma unroll
                    for (int r = 0; r < 4; r++) e2[f][ii][r] = __expf(cacc[r]);
                    lsum[f][0] += e2[f][ii][0] + e2[f][ii][1];
                    lsum[f][1] += e2[f][ii][2] + e2[f][ii][3];
                }
            }

            uint32_t pah[2][4], pal[2][4];
#pragma unroll
            for (int f = 0; f < 2; f++) {
                uint32_t a0 = cvt_bf16x2(e2[f][0][0], e2[f][0][1]);
                uint32_t a1 = cvt_bf16x2(e2[f][0][2], e2[f][0][3]);
                uint32_t a2 = cvt_bf16x2(e2[f][1][0], e2[f][1][1]);
                uint32_t a3 = cvt_bf16x2(e2[f][1][2], e2[f][1][3]);
                pah[f][0] = a0; pah[f][1] = a1; pah[f][2] = a2; pah[f][3] = a3;
                pal[f][0] = cvt_bf16x2(e2[f][0][0] - bflo(a0), e2[f][0][1] - bfhi(a0));
                pal[f][1] = cvt_bf16x2(e2[f][0][2] - bflo(a1), e2[f][0][3] - bfhi(a1));
                pal[f][2] = cvt_bf16x2(e2[f][1][0] - bflo(a2), e2[f][1][1] - bfhi(a2));
                pal[f][3] = cvt_bf16x2(e2[f][1][2] - bflo(a3), e2[f][1][3] - bfhi(a3));
            }

#pragma unroll
            for (int j = 0; j < 4; j++) {
                const unsigned char* va = vfh + j * 1152 + kt * 32;
                const unsigned char* vb = vfl + j * 1152 + kt * 32;
                uint32_t v0 = *(const uint32_t*)va;
                uint32_t v1 = *(const uint32_t*)(va + 16);
                uint32_t u0 = *(const uint32_t*)vb;
                uint32_t u1 = *(const uint32_t*)(vb + 16);
#pragma unroll
                for (int f = 0; f < 2; f++) {
                    mma16816(o[f][j], pah[f], v0, v1);
                    mma16816(o[f][j], pah[f], u0, u1);
                    mma16816(o[f][j], pal[f], v0, v1);
                }
            }
        }
    }

    // epilogue: normalize + split-store att[b][tok][hidden]
    float inv[2][2];
#pragma unroll
    for (int f = 0; f < 2; f++)
#pragma unroll
        for (int rr = 0; rr < 2; rr++) {
            float lv = lsum[f][rr];
            lv += __shfl_xor_sync(0xffffffffu, lv, 1);
            lv += __shfl_xor_sync(0xffffffffu, lv, 2);
            inv[f][rr] = 1.f / lv;
        }

#pragma unroll
    for (int f = 0; f < 2; f++)
#pragma unroll
        for (int rr = 0; rr < 2; rr++) {
            int qrow = q0 + w * 32 + f * 16 + rr * 8 + t4;
            float iv = inv[f][rr];
#pragma unroll
            for (int j = 0; j < 4; j++) {
                float v0 = o[f][j][rr * 2 + 0] * iv;
                float v1 = o[f][j][rr * 2 + 1] * iv;
                uint32_t hw = cvt_bf16x2(v0, v1);
                uint32_t lw = cvt_bf16x2(v0 - bflo(hw), v1 - bfhi(hw));
                size_t gi = ((size_t)b * NTOK + qrow) * 64 + h * 16 + j * 4 + tm4;
                g_ah[gi] = hw;
                g_al[gi] = lw;
            }
        }
}

// ---------------- launch ----------------
extern "C" void kernel_launch(void* const* d_in, const int* in_sizes, int n_in,
                              void* d_out, int out_size)
{
    const float* x     = (const float*)d_in[0];
    const float* w_qkv = (const float*)d_in[1];
    const float* w_out = (const float*)d_in[2];
    const float* b_out = (const float*)d_in[3];
    float* out = (float*)d_out;

    float* qkv = nullptr;
    cudaGetSymbolAddress((void**)&qkv, g_qkv);
    unsigned *wqh, *wql, *woh, *wol, *xth, *xtl, *ah, *al;
    cudaGetSymbolAddress((void**)&wqh, g_wqh);
    cudaGetSymbolAddress((void**)&wql, g_wql);
    cudaGetSymbolAddress((void**)&woh, g_woh);
    cudaGetSymbolAddress((void**)&wol, g_wol);
    cudaGetSymbolAddress((void**)&xth, g_xth);
    cudaGetSymbolAddress((void**)&xtl, g_xtl);
    cudaGetSymbolAddress((void**)&ah, g_ah);
    cudaGetSymbolAddress((void**)&al, g_al);

    prep_w<<<192, 256>>>(w_qkv, wqh, wql, 384 * 128);
    prep_w<<<64, 256>>>(w_out, woh, wol, 256 * 64);
    prep_x<<<dim3(NTOK / 32, 8, 8), 256>>>(x);

    // qkv = w_qkv @ x   (M=384, K=256)
    gemm_hmma<<<dim3(NTOK / 64, 3, 8), 128>>>(wqh, wql, xth, xtl, qkv, nullptr, 384, 256);

    prep_qk<<<dim3(NTOK / 32, 8, 8), 256>>>();
    prep_v<<<dim3((8 * 128 * NT2) / 256), 256>>>();

    attn_hmma<<<dim3(NTOK / 128, 4, 8), 128>>>();

    // out = w_out @ att + b_out   (M=256, K=128)
    gemm_hmma<<<dim3(NTOK / 64, 2, 8), 128>>>(woh, wol, ah, al, out, b_out, 256, 128);
}

// round 10
// speedup vs baseline: 2.6610x; 1.0503x over previous
#include <cuda_runtime.h>
#include <cuda_bf16.h>
#include <cstdint>

// Attention_9328668967755 — all-HMMA (bf16 3-term split) pipeline, ldmatrix frags.
// b=8, c=256, n=2304, heads=4, d_head=32.

#define NTOK 2304
#define NT2  1152
#define SCALE 0.17677669529663689f

__device__ float    g_qkv[8 * 384 * NTOK];
__device__ unsigned g_qh[8 * 4 * NTOK * 16];
__device__ unsigned g_ql[8 * 4 * NTOK * 16];
__device__ unsigned g_kh[8 * 4 * NTOK * 16];
__device__ unsigned g_kl[8 * 4 * NTOK * 16];
__device__ unsigned g_vh[8 * 128 * NT2];
__device__ unsigned g_vl[8 * 128 * NT2];
__device__ unsigned g_xth[8 * NTOK * 128];
__device__ unsigned g_xtl[8 * NTOK * 128];
__device__ unsigned g_ah[8 * NTOK * 64];
__device__ unsigned g_al[8 * NTOK * 64];
__device__ unsigned g_wqh[384 * 128];
__device__ unsigned g_wql[384 * 128];
__device__ unsigned g_woh[256 * 64];
__device__ unsigned g_wol[256 * 64];

// ---------------- helpers ----------------
__device__ __forceinline__ uint32_t cvt_bf16x2(float lo, float hi) {
    uint32_t r;
    asm("cvt.rn.satfinite.bf16x2.f32 %0, %1, %2;" : "=r"(r) : "f"(hi), "f"(lo));
    return r;
}
__device__ __forceinline__ float bflo(uint32_t u) { return __uint_as_float(u << 16); }
__device__ __forceinline__ float bfhi(uint32_t u) { return __uint_as_float(u & 0xffff0000u); }

__device__ __forceinline__ uint32_t smem_u32(const void* p) {
    uint32_t a;
    asm("{ .reg .u64 t; cvta.to.shared.u64 t, %1; cvt.u32.u64 %0, t; }" : "=r"(a) : "l"(p));
    return a;
}

__device__ __forceinline__ void mma16816(float* c, const uint32_t* a,
                                         uint32_t b0, uint32_t b1) {
    asm volatile(
        "mma.sync.aligned.m16n8k16.row.col.f32.bf16.bf16.f32 "
        "{%0,%1,%2,%3}, {%4,%5,%6,%7}, {%8,%9}, {%0,%1,%2,%3};"
        : "+f"(c[0]), "+f"(c[1]), "+f"(c[2]), "+f"(c[3])
        : "r"(a[0]), "r"(a[1]), "r"(a[2]), "r"(a[3]), "r"(b0), "r"(b1));
}

__device__ __forceinline__ void ldmx4(uint32_t* r, uint32_t addr) {
    asm volatile("ldmatrix.sync.aligned.m8n8.x4.shared.b16 {%0,%1,%2,%3}, [%4];"
                 : "=r"(r[0]), "=r"(r[1]), "=r"(r[2]), "=r"(r[3]) : "r"(addr));
}

// ---------------- prep: weight split ----------------
__global__ __launch_bounds__(256)
void prep_w(const float* __restrict__ src, unsigned* __restrict__ dh,
            unsigned* __restrict__ dl, int nwords)
{
    int idx = blockIdx.x * 256 + threadIdx.x;
    if (idx >= nwords) return;
    float2 s = *(const float2*)(src + (size_t)idx * 2);
    uint32_t hw = cvt_bf16x2(s.x, s.y);
    dh[idx] = hw;
    dl[idx] = cvt_bf16x2(s.x - bflo(hw), s.y - bfhi(hw));
}

// ---------------- prep: x transpose+split ----------------
__global__ __launch_bounds__(256)
void prep_x(const float* __restrict__ x)
{
    __shared__ float ts[32][33];
    const int t = threadIdx.x;
    const int tok0 = blockIdx.x * 32;
    const int k0 = blockIdx.y * 32;
    const int b = blockIdx.z;

    {
        int r = t >> 3, c = (t & 7) * 4;
        float4 v = *(const float4*)(x + ((size_t)b * 256 + k0 + r) * NTOK + tok0 + c);
        ts[r][c + 0] = v.x; ts[r][c + 1] = v.y; ts[r][c + 2] = v.z; ts[r][c + 3] = v.w;
    }
    __syncthreads();

    int tok = t >> 3, kq = (t & 7) * 4;
    float f0 = ts[kq + 0][tok], f1 = ts[kq + 1][tok];
    float f2 = ts[kq + 2][tok], f3 = ts[kq + 3][tok];

    uint32_t h01 = cvt_bf16x2(f0, f1);
    uint32_t l01 = cvt_bf16x2(f0 - bflo(h01), f1 - bfhi(h01));
    uint32_t h23 = cvt_bf16x2(f2, f3);
    uint32_t l23 = cvt_bf16x2(f2 - bflo(h23), f3 - bfhi(h23));

    size_t gi = ((size_t)b * NTOK + tok0 + tok) * 128 + (k0 + kq) / 2;
    g_xth[gi] = h01; g_xth[gi + 1] = h23;
    g_xtl[gi] = l01; g_xtl[gi + 1] = l23;
}

// ---------------- prep: qk transpose+split ----------------
__global__ __launch_bounds__(256)
void prep_qk()
{
    __shared__ float ts[32][33];
    const int t = threadIdx.x;
    const int tile = blockIdx.x;
    const int hy = blockIdx.y;
    const int b = blockIdx.z;
    const int isK = hy >> 2, h = hy & 3;

    const float* src = g_qkv + ((size_t)b * 384 + (size_t)isK * 128 + h * 32) * NTOK
                       + (size_t)tile * 32;
    {
        int r = t >> 3, c = (t & 7) * 4;
        float4 v = *(const float4*)(src + (size_t)r * NTOK + c);
        ts[r][c + 0] = v.x; ts[r][c + 1] = v.y; ts[r][c + 2] = v.z; ts[r][c + 3] = v.w;
    }
    __syncthreads();

    int tok = t >> 3, d0 = (t & 7) * 4;
    float f0 = ts[d0 + 0][tok], f1 = ts[d0 + 1][tok];
    float f2 = ts[d0 + 2][tok], f3 = ts[d0 + 3][tok];
    if (!isK) { f0 *= SCALE; f1 *= SCALE; f2 *= SCALE; f3 *= SCALE; }

    uint32_t h01 = cvt_bf16x2(f0, f1);
    uint32_t l01 = cvt_bf16x2(f0 - bflo(h01), f1 - bfhi(h01));
    uint32_t h23 = cvt_bf16x2(f2, f3);
    uint32_t l23 = cvt_bf16x2(f2 - bflo(h23), f3 - bfhi(h23));

    unsigned* oh = isK ? g_kh : g_qh;
    unsigned* ol = isK ? g_kl : g_ql;
    size_t idx = ((size_t)(b * 4 + h) * NTOK + (size_t)tile * 32 + tok) * 16 + (t & 7) * 2;
    oh[idx] = h01; oh[idx + 1] = h23;
    ol[idx] = l01; ol[idx + 1] = l23;
}

__global__ __launch_bounds__(256)
void prep_v()
{
    size_t idx = (size_t)blockIdx.x * 256 + threadIdx.x;
    const size_t per_b = (size_t)128 * NT2;
    size_t b = idx / per_b, rem = idx % per_b;
    const float2 s = *(const float2*)(g_qkv + ((size_t)b * 384 + 256) * NTOK + rem * 2);
    uint32_t hw = cvt_bf16x2(s.x, s.y);
    uint32_t lw = cvt_bf16x2(s.x - bflo(hw), s.y - bfhi(hw));
    g_vh[idx] = hw;
    g_vl[idx] = lw;
}

// ---------------- HMMA GEMM (ldmatrix fragments) ----------------
// C[b][M][N] = Wsplit @ Xsplit^T (+bias). Grid (N/64, M/128, 8), 128 threads.
__global__ __launch_bounds__(128, 3)
void gemm_hmma(const unsigned* __restrict__ wh, const unsigned* __restrict__ wl,
               const unsigned* __restrict__ xh, const unsigned* __restrict__ xl,
               float* __restrict__ C, const float* __restrict__ bias,
               int M, int K)
{
    __shared__ __align__(16) unsigned char sWh[10240];  // 128 rows x 80B
    __shared__ __align__(16) unsigned char sWl[10240];
    __shared__ __align__(16) unsigned char sXh[5120];   // 64 rows x 80B
    __shared__ __align__(16) unsigned char sXl[5120];

    const int tid = threadIdx.x;
    const int w = tid >> 5, lane = tid & 31;
    const int t4 = lane >> 2, tm4 = lane & 3;
    const int nb = blockIdx.x * 64;
    const int mb = blockIdx.y * 128;
    const int bz = blockIdx.z;
    const int kws = K / 2;

    float o[2][8][4];
#pragma unroll
    for (int f = 0; f < 2; f++)
#pragma unroll
        for (int nf = 0; nf < 8; nf++)
#pragma unroll
            for (int r = 0; r < 4; r++) o[f][nf][r] = 0.f;

    const unsigned* wgh = wh + (size_t)(mb + tid) * kws;
    const unsigned* wgl = wl + (size_t)(mb + tid) * kws;
    const int xtok = tid >> 1, xhalf = tid & 1;
    const unsigned* xgh = xh + ((size_t)bz * NTOK + nb + xtok) * kws + xhalf * 8;
    const unsigned* xgl = xl + ((size_t)bz * NTOK + nb + xtok) * kws + xhalf * 8;
    unsigned char* swh = sWh + tid * 80;
    unsigned char* swl = sWl + tid * 80;
    unsigned char* sxh = sXh + xtok * 80 + xhalf * 32;
    unsigned char* sxl = sXl + xtok * 80 + xhalf * 32;

    // ldmatrix lane offsets
    const uint32_t aWh = smem_u32(sWh), aWl = smem_u32(sWl);
    const uint32_t aXh = smem_u32(sXh), aXl = smem_u32(sXl);
    const uint32_t aoff = (uint32_t)((w * 32 + (lane & 7) + ((lane >> 3) & 1) * 8) * 80
                                     + (lane >> 4) * 16);
    const uint32_t boff = (uint32_t)(((lane & 7) + ((lane >> 4) & 1) * 8) * 80
                                     + ((lane >> 3) & 1) * 16);

    for (int k0 = 0; k0 < kws; k0 += 16) {
        __syncthreads();
#pragma unroll
        for (int i = 0; i < 4; i++) {
            uint4 a = *(const uint4*)(wgh + k0 + i * 4);
            *(uint4*)(swh + i * 16) = a;
            a = *(const uint4*)(wgl + k0 + i * 4);
            *(uint4*)(swl + i * 16) = a;
        }
#pragma unroll
        for (int i = 0; i < 2; i++) {
            uint4 a = *(const uint4*)(xgh + k0 + i * 4);
            *(uint4*)(sxh + i * 16) = a;
            a = *(const uint4*)(xgl + k0 + i * 4);
            *(uint4*)(sxl + i * 16) = a;
        }
        __syncthreads();

#pragma unroll
        for (int ks = 0; ks < 2; ks++) {
            uint32_t ah[2][4], al[2][4];
            ldmx4(ah[0], aWh + aoff + ks * 32);
            ldmx4(ah[1], aWh + aoff + 1280 + ks * 32);
            ldmx4(al[0], aWl + aoff + ks * 32);
            ldmx4(al[1], aWl + aoff + 1280 + ks * 32);
#pragma unroll
            for (int p = 0; p < 4; p++) {
                uint32_t bh4[4], bl4[4];
                ldmx4(bh4, aXh + boff + p * 1280 + ks * 32);
                ldmx4(bl4, aXl + boff + p * 1280 + ks * 32);
#pragma unroll
                for (int f = 0; f < 2; f++) {
                    mma16816(o[f][2 * p + 0], ah[f], bh4[0], bh4[1]);
                    mma16816(o[f][2 * p + 0], ah[f], bl4[0], bl4[1]);
                    mma16816(o[f][2 * p + 0], al[f], bh4[0], bh4[1]);
                    mma16816(o[f][2 * p + 1], ah[f], bh4[2], bh4[3]);
                    mma16816(o[f][2 * p + 1], ah[f], bl4[2], bl4[3]);
                    mma16816(o[f][2 * p + 1], al[f], bh4[2], bh4[3]);
                }
            }
        }
    }

    float* Cb = C + (size_t)bz * M * NTOK;
#pragma unroll
    for (int f = 0; f < 2; f++) {
        int row0 = mb + w * 32 + f * 16 + t4;
        int row1 = row0 + 8;
        float b0 = bias ? bias[row0] : 0.f;
        float b1 = bias ? bias[row1] : 0.f;
#pragma unroll
        for (int nf = 0; nf < 8; nf++) {
            int col = nb + nf * 8 + tm4 * 2;
            *(float2*)(Cb + (size_t)row0 * NTOK + col) =
                make_float2(o[f][nf][0] + b0, o[f][nf][1] + b0);
            *(float2*)(Cb + (size_t)row1 * NTOK + col) =
                make_float2(o[f][nf][2] + b1, o[f][nf][3] + b1);
        }
    }
}

// ---------------- attention (HMMA + ldmatrix) ----------------
__global__ __launch_bounds__(128, 3)
void attn_hmma()
{
    __shared__ __align__(16) unsigned char sKh[5120];
    __shared__ __align__(16) unsigned char sKl[5120];
    __shared__ __align__(16) unsigned char sVh[4608];
    __shared__ __align__(16) unsigned char sVl[4608];

    const int tid = threadIdx.x;
    const int w = tid >> 5, lane = tid & 31;
    const int t4 = lane >> 2, tm4 = lane & 3;
    const int q0 = blockIdx.x * 128;
    const int h = blockIdx.y, b = blockIdx.z;
    const int bh = b * 4 + h;

    uint32_t qh[2][2][4], ql[2][2][4];
#pragma unroll
    for (int f = 0; f < 2; f++)
#pragma unroll
        for (int ks = 0; ks < 2; ks++)
#pragma unroll
            for (int r = 0; r < 4; r++) {
                int row = q0 + w * 32 + f * 16 + (r & 1) * 8 + t4;
                int word = ks * 8 + tm4 + (r >> 1) * 4;
                size_t gi = ((size_t)bh * NTOK + row) * 16 + word;
                qh[f][ks][r] = g_qh[gi];
                ql[f][ks][r] = g_ql[gi];
            }

    float o[2][4][4];
#pragma unroll
    for (int f = 0; f < 2; f++)
#pragma unroll
        for (int j = 0; j < 4; j++)
#pragma unroll
            for (int r = 0; r < 4; r++) o[f][j][r] = 0.f;
    float lsum[2][2] = {{0.f, 0.f}, {0.f, 0.f}};

    const int ktok = tid >> 1, khalf = tid & 1;
    const size_t kgbase = ((size_t)bh * NTOK + ktok) * 16 + khalf * 8;
    unsigned char* ksh = sKh + ktok * 80 + khalf * 32;
    unsigned char* ksl = sKl + ktok * 80 + khalf * 32;
    const int vd = tid >> 2, vq = tid & 3;
    const size_t vgbase = ((size_t)(b * 128 + h * 32 + vd)) * NT2 + vq * 8;
    unsigned char* vsh = sVh + vd * 144 + vq * 32;
    unsigned char* vsl = sVl + vd * 144 + vq * 32;

    // ldmatrix lane offsets
    const uint32_t aKh = smem_u32(sKh), aKl = smem_u32(sKl);
    const uint32_t aVh = smem_u32(sVh), aVl = smem_u32(sVl);
    const uint32_t koff = (uint32_t)((lane & 7) * 80 + (lane >> 3) * 16);
    const uint32_t voff = (uint32_t)(((lane & 7) + ((lane >> 4) & 1) * 8) * 144
                                     + ((lane >> 3) & 1) * 16);

    for (int t = 0; t < 36; t++) {
        __syncthreads();
        {
            const uint4* s = (const uint4*)(g_kh + kgbase + (size_t)t * 64 * 16);
            uint4 a = s[0], c = s[1];
            *(uint4*)ksh = a; *(uint4*)(ksh + 16) = c;
            s = (const uint4*)(g_kl + kgbase + (size_t)t * 64 * 16);
            a = s[0]; c = s[1];
            *(uint4*)ksl = a; *(uint4*)(ksl + 16) = c;
            s = (const uint4*)(g_vh + vgbase + t * 32);
            a = s[0]; c = s[1];
            *(uint4*)vsh = a; *(uint4*)(vsh + 16) = c;
            s = (const uint4*)(g_vl + vgbase + t * 32);
            a = s[0]; c = s[1];
            *(uint4*)vsl = a; *(uint4*)(vsl + 16) = c;
        }
        __syncthreads();

#pragma unroll
        for (int kt = 0; kt < 4; kt++) {
            float e2[2][2][4];
#pragma unroll
            for (int ii = 0; ii < 2; ii++) {
                const int i = kt * 2 + ii;
                uint32_t kh4[4], kl4[4];
                ldmx4(kh4, aKh + koff + i * 640);
                ldmx4(kl4, aKl + koff + i * 640);

#pragma unroll
                for (int f = 0; f < 2; f++) {
                    float cacc[4] = {0.f, 0.f, 0.f, 0.f};
                    mma16816(cacc, qh[f][0], kh4[0], kh4[1]);
                    mma16816(cacc, qh[f][0], kl4[0], kl4[1]);
                    mma16816(cacc, ql[f][0], kh4[0], kh4[1]);
                    mma16816(cacc, qh[f][1], kh4[2], kh4[3]);
                    mma16816(cacc, qh[f][1], kl4[2], kl4[3]);
                    mma16816(cacc, ql[f][1], kh4[2], kh4[3]);
#pragma unroll
                    for (int r = 0; r < 4; r++) e2[f][ii][r] = __expf(cacc[r]);
                    lsum[f][0] += e2[f][ii][0] + e2[f][ii][1];
                    lsum[f][1] += e2[f][ii][2] + e2[f][ii][3];
                }
            }

            uint32_t pah[2][4], pal[2][4];
#pragma unroll
            for (int f = 0; f < 2; f++) {
                uint32_t a0 = cvt_bf16x2(e2[f][0][0], e2[f][0][1]);
                uint32_t a1 = cvt_bf16x2(e2[f][0][2], e2[f][0][3]);
                uint32_t a2 = cvt_bf16x2(e2[f][1][0], e2[f][1][1]);
                uint32_t a3 = cvt_bf16x2(e2[f][1][2], e2[f][1][3]);
                pah[f][0] = a0; pah[f][1] = a1; pah[f][2] = a2; pah[f][3] = a3;
                pal[f][0] = cvt_bf16x2(e2[f][0][0] - bflo(a0), e2[f][0][1] - bfhi(a0));
                pal[f][1] = cvt_bf16x2(e2[f][0][2] - bflo(a1), e2[f][0][3] - bfhi(a1));
                pal[f][2] = cvt_bf16x2(e2[f][1][0] - bflo(a2), e2[f][1][1] - bfhi(a2));
                pal[f][3] = cvt_bf16x2(e2[f][1][2] - bflo(a3), e2[f][1][3] - bfhi(a3));
            }

#pragma unroll
            for (int jp = 0; jp < 2; jp++) {
                uint32_t vh4[4], vl4[4];
                ldmx4(vh4, aVh + voff + jp * 2304 + kt * 32);
                ldmx4(vl4, aVl + voff + jp * 2304 + kt * 32);
#pragma unroll
                for (int f = 0; f < 2; f++) {
                    mma16816(o[f][2 * jp + 0], pah[f], vh4[0], vh4[1]);
                    mma16816(o[f][2 * jp + 0], pah[f], vl4[0], vl4[1]);
                    mma16816(o[f][2 * jp + 0], pal[f], vh4[0], vh4[1]);
                    mma16816(o[f][2 * jp + 1], pah[f], vh4[2], vh4[3]);
                    mma16816(o[f][2 * jp + 1], pah[f], vl4[2], vl4[3]);
                    mma16816(o[f][2 * jp + 1], pal[f], vh4[2], vh4[3]);
                }
            }
        }
    }

    // epilogue: normalize + split-store att[b][tok][hidden]
    float inv[2][2];
#pragma unroll
    for (int f = 0; f < 2; f++)
#pragma unroll
        for (int rr = 0; rr < 2; rr++) {
            float lv = lsum[f][rr];
            lv += __shfl_xor_sync(0xffffffffu, lv, 1);
            lv += __shfl_xor_sync(0xffffffffu, lv, 2);
            inv[f][rr] = 1.f / lv;
        }

#pragma unroll
    for (int f = 0; f < 2; f++)
#pragma unroll
        for (int rr = 0; rr < 2; rr++) {
            int qrow = q0 + w * 32 + f * 16 + rr * 8 + t4;
            float iv = inv[f][rr];
#pragma unroll
            for (int j = 0; j < 4; j++) {
                float v0 = o[f][j][rr * 2 + 0] * iv;
                float v1 = o[f][j][rr * 2 + 1] * iv;
                uint32_t hw = cvt_bf16x2(v0, v1);
                uint32_t lw = cvt_bf16x2(v0 - bflo(hw), v1 - bfhi(hw));
                size_t gi = ((size_t)b * NTOK + qrow) * 64 + h * 16 + j * 4 + tm4;
                g_ah[gi] = hw;
                g_al[gi] = lw;
            }
        }
}

// ---------------- launch ----------------
extern "C" void kernel_launch(void* const* d_in, const int* in_sizes, int n_in,
                              void* d_out, int out_size)
{
    const float* x     = (const float*)d_in[0];
    const float* w_qkv = (const float*)d_in[1];
    const float* w_out = (const float*)d_in[2];
    const float* b_out = (const float*)d_in[3];
    float* out = (float*)d_out;

    float* qkv = nullptr;
    cudaGetSymbolAddress((void**)&qkv, g_qkv);
    unsigned *wqh, *wql, *woh, *wol, *xth, *xtl, *ah, *al;
    cudaGetSymbolAddress((void**)&wqh, g_wqh);
    cudaGetSymbolAddress((void**)&wql, g_wql);
    cudaGetSymbolAddress((void**)&woh, g_woh);
    cudaGetSymbolAddress((void**)&wol, g_wol);
    cudaGetSymbolAddress((void**)&xth, g_xth);
    cudaGetSymbolAddress((void**)&xtl, g_xtl);
    cudaGetSymbolAddress((void**)&ah, g_ah);
    cudaGetSymbolAddress((void**)&al, g_al);

    prep_w<<<192, 256>>>(w_qkv, wqh, wql, 384 * 128);
    prep_w<<<64, 256>>>(w_out, woh, wol, 256 * 64);
    prep_x<<<dim3(NTOK / 32, 8, 8), 256>>>(x);

    gemm_hmma<<<dim3(NTOK / 64, 3, 8), 128>>>(wqh, wql, xth, xtl, qkv, nullptr, 384, 256);

    prep_qk<<<dim3(NTOK / 32, 8, 8), 256>>>();
    prep_v<<<dim3((8 * 128 * NT2) / 256), 256>>>();

    attn_hmma<<<dim3(NTOK / 128, 4, 8), 128>>>();

    gemm_hmma<<<dim3(NTOK / 64, 2, 8), 128>>>(woh, wol, ah, al, out, b_out, 256, 128);
}

// round 11
// speedup vs baseline: 2.9949x; 1.1255x over previous
#include <cuda_runtime.h>
#include <cuda_bf16.h>
#include <cstdint>

// Attention_9328668967755 — all-HMMA bf16-split pipeline, k-tiled layouts + cp.async.
// b=8, c=256, n=2304, heads=4, d_head=32.

#define NTOK 2304
#define NT2  1152
#define SCALE 0.17677669529663689f

__device__ float    g_qkv[8 * 384 * NTOK];
__device__ unsigned g_qh[8 * 4 * NTOK * 16];
__device__ unsigned g_ql[8 * 4 * NTOK * 16];
__device__ unsigned g_kh[8 * 4 * NTOK * 16];
__device__ unsigned g_kl[8 * 4 * NTOK * 16];
__device__ unsigned g_vh[8 * 128 * NT2];
__device__ unsigned g_vl[8 * 128 * NT2];
// k-block tiled: [b][kb][tok][16 u32]
__device__ unsigned g_xth[8 * 8 * NTOK * 16];
__device__ unsigned g_xtl[8 * 8 * NTOK * 16];
__device__ unsigned g_ah[8 * 4 * NTOK * 16];
__device__ unsigned g_al[8 * 4 * NTOK * 16];
// weights k-block tiled: [kb][M][16 u32]
__device__ unsigned g_wqh[8 * 384 * 16];
__device__ unsigned g_wql[8 * 384 * 16];
__device__ unsigned g_woh[4 * 256 * 16];
__device__ unsigned g_wol[4 * 256 * 16];

// ---------------- helpers ----------------
__device__ __forceinline__ uint32_t cvt_bf16x2(float lo, float hi) {
    uint32_t r;
    asm("cvt.rn.satfinite.bf16x2.f32 %0, %1, %2;" : "=r"(r) : "f"(hi), "f"(lo));
    return r;
}
__device__ __forceinline__ float bflo(uint32_t u) { return __uint_as_float(u << 16); }
__device__ __forceinline__ float bfhi(uint32_t u) { return __uint_as_float(u & 0xffff0000u); }

__device__ __forceinline__ uint32_t smem_u32(const void* p) {
    uint32_t a;
    asm("{ .reg .u64 t; cvta.to.shared.u64 t, %1; cvt.u32.u64 %0, t; }" : "=r"(a) : "l"(p));
    return a;
}
__device__ __forceinline__ void mma16816(float* c, const uint32_t* a,
                                         uint32_t b0, uint32_t b1) {
    asm volatile(
        "mma.sync.aligned.m16n8k16.row.col.f32.bf16.bf16.f32 "
        "{%0,%1,%2,%3}, {%4,%5,%6,%7}, {%8,%9}, {%0,%1,%2,%3};"
        : "+f"(c[0]), "+f"(c[1]), "+f"(c[2]), "+f"(c[3])
        : "r"(a[0]), "r"(a[1]), "r"(a[2]), "r"(a[3]), "r"(b0), "r"(b1));
}
__device__ __forceinline__ void ldmx4(uint32_t* r, uint32_t addr) {
    asm volatile("ldmatrix.sync.aligned.m8n8.x4.shared.b16 {%0,%1,%2,%3}, [%4];"
                 : "=r"(r[0]), "=r"(r[1]), "=r"(r[2]), "=r"(r[3]) : "r"(addr));
}
#define CP_ASYNC(dst, src) \
    asm volatile("cp.async.cg.shared.global [%0], [%1], 16;" :: "r"(dst), "l"(src) : "memory")
#define CP_COMMIT asm volatile("cp.async.commit_group;" ::: "memory")
#define CP_WAIT1 asm volatile("cp.async.wait_group 1;" ::: "memory")
#define CP_WAIT0 asm volatile("cp.async.wait_group 0;" ::: "memory")

// ---------------- prep: weight split to [kb][M][16] ----------------
__global__ __launch_bounds__(256)
void prep_w(const float* __restrict__ src, unsigned* __restrict__ dh,
            unsigned* __restrict__ dl, int M, int kws)
{
    int idx = blockIdx.x * 256 + threadIdx.x;
    if (idx >= M * kws) return;
    int m = idx / kws, kw = idx % kws;
    float2 s = *(const float2*)(src + (size_t)idx * 2);
    uint32_t hw = cvt_bf16x2(s.x, s.y);
    uint32_t lw = cvt_bf16x2(s.x - bflo(hw), s.y - bfhi(hw));
    size_t dst = ((size_t)(kw >> 4) * M + m) * 16 + (kw & 15);
    dh[dst] = hw;
    dl[dst] = lw;
}

// ---------------- prep: x transpose+split to [b][kb][tok][16] ----------------
__global__ __launch_bounds__(256)
void prep_x(const float* __restrict__ x)
{
    __shared__ float ts[32][33];
    const int t = threadIdx.x;
    const int tok0 = blockIdx.x * 32;
    const int k0 = blockIdx.y * 32;
    const int b = blockIdx.z;

    {
        int r = t >> 3, c = (t & 7) * 4;
        float4 v = *(const float4*)(x + ((size_t)b * 256 + k0 + r) * NTOK + tok0 + c);
        ts[r][c + 0] = v.x; ts[r][c + 1] = v.y; ts[r][c + 2] = v.z; ts[r][c + 3] = v.w;
    }
    __syncthreads();

    int tok = t >> 3, kq = (t & 7) * 4;
    float f0 = ts[kq + 0][tok], f1 = ts[kq + 1][tok];
    float f2 = ts[kq + 2][tok], f3 = ts[kq + 3][tok];

    uint32_t h01 = cvt_bf16x2(f0, f1);
    uint32_t l01 = cvt_bf16x2(f0 - bflo(h01), f1 - bfhi(h01));
    uint32_t h23 = cvt_bf16x2(f2, f3);
    uint32_t l23 = cvt_bf16x2(f2 - bflo(h23), f3 - bfhi(h23));

    size_t gi = (((size_t)b * 8 + blockIdx.y) * NTOK + tok0 + tok) * 16 + kq / 2;
    g_xth[gi] = h01; g_xth[gi + 1] = h23;
    g_xtl[gi] = l01; g_xtl[gi + 1] = l23;
}

// ---------------- prep: qk transpose+split (layout unchanged) ----------------
__global__ __launch_bounds__(256)
void prep_qk()
{
    __shared__ float ts[32][33];
    const int t = threadIdx.x;
    const int tile = blockIdx.x;
    const int hy = blockIdx.y;
    const int b = blockIdx.z;
    const int isK = hy >> 2, h = hy & 3;

    const float* src = g_qkv + ((size_t)b * 384 + (size_t)isK * 128 + h * 32) * NTOK
                       + (size_t)tile * 32;
    {
        int r = t >> 3, c = (t & 7) * 4;
        float4 v = *(const float4*)(src + (size_t)r * NTOK + c);
        ts[r][c + 0] = v.x; ts[r][c + 1] = v.y; ts[r][c + 2] = v.z; ts[r][c + 3] = v.w;
    }
    __syncthreads();

    int tok = t >> 3, d0 = (t & 7) * 4;
    float f0 = ts[d0 + 0][tok], f1 = ts[d0 + 1][tok];
    float f2 = ts[d0 + 2][tok], f3 = ts[d0 + 3][tok];
    if (!isK) { f0 *= SCALE; f1 *= SCALE; f2 *= SCALE; f3 *= SCALE; }

    uint32_t h01 = cvt_bf16x2(f0, f1);
    uint32_t l01 = cvt_bf16x2(f0 - bflo(h01), f1 - bfhi(h01));
    uint32_t h23 = cvt_bf16x2(f2, f3);
    uint32_t l23 = cvt_bf16x2(f2 - bflo(h23), f3 - bfhi(h23));

    unsigned* oh = isK ? g_kh : g_qh;
    unsigned* ol = isK ? g_kl : g_ql;
    size_t idx = ((size_t)(b * 4 + h) * NTOK + (size_t)tile * 32 + tok) * 16 + (t & 7) * 2;
    oh[idx] = h01; oh[idx + 1] = h23;
    ol[idx] = l01; ol[idx + 1] = l23;
}

__global__ __launch_bounds__(256)
void prep_v()
{
    size_t idx = (size_t)blockIdx.x * 256 + threadIdx.x;
    const size_t per_b = (size_t)128 * NT2;
    size_t b = idx / per_b, rem = idx % per_b;
    const float2 s = *(const float2*)(g_qkv + ((size_t)b * 384 + 256) * NTOK + rem * 2);
    uint32_t hw = cvt_bf16x2(s.x, s.y);
    uint32_t lw = cvt_bf16x2(s.x - bflo(hw), s.y - bfhi(hw));
    g_vh[idx] = hw;
    g_vl[idx] = lw;
}

// ---------------- HMMA GEMM: cp.async 2-stage, k-tiled inputs ----------------
// stage layout (bytes): Wh@0 (10240), Wl@10240, Xh@20480 (5120), Xl@25600; stride 30720
#define GST 30720
__global__ __launch_bounds__(128, 3)
void gemm_hmma(const unsigned* __restrict__ wh, const unsigned* __restrict__ wl,
               const unsigned* __restrict__ xh, const unsigned* __restrict__ xl,
               float* __restrict__ C, const float* __restrict__ bias,
               int M, int nkb)
{
    extern __shared__ __align__(16) unsigned char sm[];
    const int tid = threadIdx.x;
    const int w = tid >> 5, lane = tid & 31;
    const int t4 = lane >> 2, tm4 = lane & 3;
    const int nb = blockIdx.x * 64;
    const int mb = blockIdx.y * 128;
    const int bz = blockIdx.z;

    const uint32_t sb = smem_u32(sm);
    const uint32_t stW = (uint32_t)((tid >> 2) * 80 + (tid & 3) * 16);
    const uint32_t aoff = (uint32_t)((w * 32 + (lane & 7) + ((lane >> 3) & 1) * 8) * 80
                                     + (lane >> 4) * 16);
    const uint32_t boff = (uint32_t)(((lane & 7) + ((lane >> 4) & 1) * 8) * 80
                                     + ((lane >> 3) & 1) * 16);

    float o[2][8][4];
#pragma unroll
    for (int f = 0; f < 2; f++)
#pragma unroll
        for (int nf = 0; nf < 8; nf++)
#pragma unroll
            for (int r = 0; r < 4; r++) o[f][nf][r] = 0.f;

    auto load_stage = [&](int kb) {
        uint32_t st = sb + (kb & 1) * GST;
        const unsigned* gwh = wh + ((size_t)kb * M + mb) * 16 + tid * 4;
        const unsigned* gwl = wl + ((size_t)kb * M + mb) * 16 + tid * 4;
#pragma unroll
        for (int i = 0; i < 4; i++) {
            CP_ASYNC(st + stW + i * 2560, gwh + i * 512);
            CP_ASYNC(st + 10240 + stW + i * 2560, gwl + i * 512);
        }
        const unsigned* gxh = xh + (((size_t)bz * nkb + kb) * NTOK + nb) * 16 + tid * 4;
        const unsigned* gxl = xl + (((size_t)bz * nkb + kb) * NTOK + nb) * 16 + tid * 4;
#pragma unroll
        for (int i = 0; i < 2; i++) {
            CP_ASYNC(st + 20480 + stW + i * 2560, gxh + i * 512);
            CP_ASYNC(st + 25600 + stW + i * 2560, gxl + i * 512);
        }
        CP_COMMIT;
    };

    load_stage(0);
    for (int kb = 0; kb < nkb; kb++) {
        if (kb + 1 < nkb) { load_stage(kb + 1); CP_WAIT1; }
        else              { CP_WAIT0; }
        __syncthreads();
        const uint32_t st = sb + (kb & 1) * GST;

#pragma unroll
        for (int ks = 0; ks < 2; ks++) {
            uint32_t ah[2][4], al[2][4];
            ldmx4(ah[0], st + aoff + ks * 32);
            ldmx4(ah[1], st + aoff + 1280 + ks * 32);
            ldmx4(al[0], st + 10240 + aoff + ks * 32);
            ldmx4(al[1], st + 10240 + aoff + 1280 + ks * 32);
#pragma unroll
            for (int p = 0; p < 4; p++) {
                uint32_t bh4[4], bl4[4];
                ldmx4(bh4, st + 20480 + boff + p * 1280 + ks * 32);
                ldmx4(bl4, st + 25600 + boff + p * 1280 + ks * 32);
#pragma unroll
                for (int f = 0; f < 2; f++) {
                    mma16816(o[f][2 * p + 0], ah[f], bh4[0], bh4[1]);
                    mma16816(o[f][2 * p + 0], ah[f], bl4[0], bl4[1]);
                    mma16816(o[f][2 * p + 0], al[f], bh4[0], bh4[1]);
                    mma16816(o[f][2 * p + 1], ah[f], bh4[2], bh4[3]);
                    mma16816(o[f][2 * p + 1], ah[f], bl4[2], bl4[3]);
                    mma16816(o[f][2 * p + 1], al[f], bh4[2], bh4[3]);
                }
            }
        }
        __syncthreads();
    }

    float* Cb = C + (size_t)bz * M * NTOK;
#pragma unroll
    for (int f = 0; f < 2; f++) {
        int row0 = mb + w * 32 + f * 16 + t4;
        int row1 = row0 + 8;
        float b0 = bias ? bias[row0] : 0.f;
        float b1 = bias ? bias[row1] : 0.f;
#pragma unroll
        for (int nf = 0; nf < 8; nf++) {
            int col = nb + nf * 8 + tm4 * 2;
            *(float2*)(Cb + (size_t)row0 * NTOK + col) =
                make_float2(o[f][nf][0] + b0, o[f][nf][1] + b0);
            *(float2*)(Cb + (size_t)row1 * NTOK + col) =
                make_float2(o[f][nf][2] + b1, o[f][nf][3] + b1);
        }
    }
}

// ---------------- attention (HMMA + ldmatrix + cp.async 2-stage) ----------------
// stage layout: Kh@0 (5120), Kl@5120, Vh@10240 (4608), Vl@14848; stride 19456
#define AST 19456
__global__ __launch_bounds__(128, 3)
void attn_hmma()
{
    __shared__ __align__(16) unsigned char sm[2 * AST];

    const int tid = threadIdx.x;
    const int w = tid >> 5, lane = tid & 31;
    const int t4 = lane >> 2, tm4 = lane & 3;
    const int q0 = blockIdx.x * 128;
    const int h = blockIdx.y, b = blockIdx.z;
    const int bh = b * 4 + h;

    uint32_t qh[2][2][4], ql[2][2][4];
#pragma unroll
    for (int f = 0; f < 2; f++)
#pragma unroll
        for (int ks = 0; ks < 2; ks++)
#pragma unroll
            for (int r = 0; r < 4; r++) {
                int row = q0 + w * 32 + f * 16 + (r & 1) * 8 + t4;
                int word = ks * 8 + tm4 + (r >> 1) * 4;
                size_t gi = ((size_t)bh * NTOK + row) * 16 + word;
                qh[f][ks][r] = g_qh[gi];
                ql[f][ks][r] = g_ql[gi];
            }

    float o[2][4][4];
#pragma unroll
    for (int f = 0; f < 2; f++)
#pragma unroll
        for (int j = 0; j < 4; j++)
#pragma unroll
            for (int r = 0; r < 4; r++) o[f][j][r] = 0.f;
    float lsum[2][2] = {{0.f, 0.f}, {0.f, 0.f}};

    const uint32_t sb = smem_u32(sm);
    const int ktok = tid >> 1, khalf = tid & 1;
    const size_t kgbase = ((size_t)bh * NTOK + ktok) * 16 + khalf * 8;
    const uint32_t kst = (uint32_t)(ktok * 80 + khalf * 32);
    const int vd = tid >> 2, vq = tid & 3;
    const size_t vgbase = ((size_t)(b * 128 + h * 32 + vd)) * NT2 + vq * 8;
    const uint32_t vst = (uint32_t)(vd * 144 + vq * 32);

    const uint32_t koff = (uint32_t)((lane & 7) * 80 + (lane >> 3) * 16);
    const uint32_t voff = (uint32_t)(((lane & 7) + ((lane >> 4) & 1) * 8) * 144
                                     + ((lane >> 3) & 1) * 16);

    auto load_stage = [&](int t) {
        uint32_t st = sb + (t & 1) * AST;
        const unsigned* s = g_kh + kgbase + (size_t)t * 1024;
        CP_ASYNC(st + kst, s); CP_ASYNC(st + kst + 16, s + 4);
        s = g_kl + kgbase + (size_t)t * 1024;
        CP_ASYNC(st + 5120 + kst, s); CP_ASYNC(st + 5120 + kst + 16, s + 4);
        s = g_vh + vgbase + (size_t)t * 32;
        CP_ASYNC(st + 10240 + vst, s); CP_ASYNC(st + 10240 + vst + 16, s + 4);
        s = g_vl + vgbase + (size_t)t * 32;
        CP_ASYNC(st + 14848 + vst, s); CP_ASYNC(st + 14848 + vst + 16, s + 4);
        CP_COMMIT;
    };

    load_stage(0);
    for (int t = 0; t < 36; t++) {
        if (t + 1 < 36) { load_stage(t + 1); CP_WAIT1; }
        else            { CP_WAIT0; }
        __syncthreads();
        const uint32_t st = sb + (t & 1) * AST;

#pragma unroll
        for (int kt = 0; kt < 4; kt++) {
            float e2[2][2][4];
#pragma unroll
            for (int ii = 0; ii < 2; ii++) {
                const int i = kt * 2 + ii;
                uint32_t kh4[4], kl4[4];
                ldmx4(kh4, st + koff + i * 640);
                ldmx4(kl4, st + 5120 + koff + i * 640);

#pragma unroll
                for (int f = 0; f < 2; f++) {
                    float cacc[4] = {0.f, 0.f, 0.f, 0.f};
                    mma16816(cacc, qh[f][0], kh4[0], kh4[1]);
                    mma16816(cacc, qh[f][0], kl4[0], kl4[1]);
                    mma16816(cacc, ql[f][0], kh4[0], kh4[1]);
                    mma16816(cacc, qh[f][1], kh4[2], kh4[3]);
                    mma16816(cacc, qh[f][1], kl4[2], kl4[3]);
                    mma16816(cacc, ql[f][1], kh4[2], kh4[3]);
#pragma unroll
                    for (int r = 0; r < 4; r++) e2[f][ii][r] = __expf(cacc[r]);
                    lsum[f][0] += e2[f][ii][0] + e2[f][ii][1];
                    lsum[f][1] += e2[f][ii][2] + e2[f][ii][3];
                }
            }

            uint32_t pah[2][4], pal[2][4];
#pragma unroll
            for (int f = 0; f < 2; f++) {
                uint32_t a0 = cvt_bf16x2(e2[f][0][0], e2[f][0][1]);
                uint32_t a1 = cvt_bf16x2(e2[f][0][2], e2[f][0][3]);
                uint32_t a2 = cvt_bf16x2(e2[f][1][0], e2[f][1][1]);
                uint32_t a3 = cvt_bf16x2(e2[f][1][2], e2[f][1][3]);
                pah[f][0] = a0; pah[f][1] = a1; pah[f][2] = a2; pah[f][3] = a3;
                pal[f][0] = cvt_bf16x2(e2[f][0][0] - bflo(a0), e2[f][0][1] - bfhi(a0));
                pal[f][1] = cvt_bf16x2(e2[f][0][2] - bflo(a1), e2[f][0][3] - bfhi(a1));
                pal[f][2] = cvt_bf16x2(e2[f][1][0] - bflo(a2), e2[f][1][1] - bfhi(a2));
                pal[f][3] = cvt_bf16x2(e2[f][1][2] - bflo(a3), e2[f][1][3] - bfhi(a3));
            }

#pragma unroll
            for (int jp = 0; jp < 2; jp++) {
                uint32_t vh4[4], vl4[4];
                ldmx4(vh4, st + 10240 + voff + jp * 2304 + kt * 32);
                ldmx4(vl4, st + 14848 + voff + jp * 2304 + kt * 32);
#pragma unroll
                for (int f = 0; f < 2; f++) {
                    mma16816(o[f][2 * jp + 0], pah[f], vh4[0], vh4[1]);
                    mma16816(o[f][2 * jp + 0], pah[f], vl4[0], vl4[1]);
                    mma16816(o[f][2 * jp + 0], pal[f], vh4[0], vh4[1]);
                    mma16816(o[f][2 * jp + 1], pah[f], vh4[2], vh4[3]);
                    mma16816(o[f][2 * jp + 1], pah[f], vl4[2], vl4[3]);
                    mma16816(o[f][2 * jp + 1], pal[f], vh4[2], vh4[3]);
                }
            }
        }
        __syncthreads();
    }

    // epilogue: normalize + split-store att in k-tiled layout [b][kb=h][tok][16]
    float inv[2][2];
#pragma unroll
    for (int f = 0; f < 2; f++)
#pragma unroll
        for (int rr = 0; rr < 2; rr++) {
            float lv = lsum[f][rr];
            lv += __shfl_xor_sync(0xffffffffu, lv, 1);
            lv += __shfl_xor_sync(0xffffffffu, lv, 2);
            inv[f][rr] = 1.f / lv;
        }

#pragma unroll
    for (int f = 0; f < 2; f++)
#pragma unroll
        for (int rr = 0; rr < 2; rr++) {
            int qrow = q0 + w * 32 + f * 16 + rr * 8 + t4;
            float iv = inv[f][rr];
#pragma unroll
            for (int j = 0; j < 4; j++) {
                float v0 = o[f][j][rr * 2 + 0] * iv;
                float v1 = o[f][j][rr * 2 + 1] * iv;
                uint32_t hw = cvt_bf16x2(v0, v1);
                uint32_t lw = cvt_bf16x2(v0 - bflo(hw), v1 - bfhi(hw));
                size_t gi = (((size_t)b * 4 + h) * NTOK + qrow) * 16 + j * 4 + tm4;
                g_ah[gi] = hw;
                g_al[gi] = lw;
            }
        }
}

// ---------------- launch ----------------
extern "C" void kernel_launch(void* const* d_in, const int* in_sizes, int n_in,
                              void* d_out, int out_size)
{
    const float* x     = (const float*)d_in[0];
    const float* w_qkv = (const float*)d_in[1];
    const float* w_out = (const float*)d_in[2];
    const float* b_out = (const float*)d_in[3];
    float* out = (float*)d_out;

    float* qkv = nullptr;
    cudaGetSymbolAddress((void**)&qkv, g_qkv);
    unsigned *wqh, *wql, *woh, *wol, *xth, *xtl, *ah, *al;
    cudaGetSymbolAddress((void**)&wqh, g_wqh);
    cudaGetSymbolAddress((void**)&wql, g_wql);
    cudaGetSymbolAddress((void**)&woh, g_woh);
    cudaGetSymbolAddress((void**)&wol, g_wol);
    cudaGetSymbolAddress((void**)&xth, g_xth);
    cudaGetSymbolAddress((void**)&xtl, g_xtl);
    cudaGetSymbolAddress((void**)&ah, g_ah);
    cudaGetSymbolAddress((void**)&al, g_al);

    static int smem_set = 0;
    if (!smem_set) {
        cudaFuncSetAttribute(gemm_hmma, cudaFuncAttributeMaxDynamicSharedMemorySize,
                             2 * GST);
        smem_set = 1;
    }

    prep_w<<<192, 256>>>(w_qkv, wqh, wql, 384, 128);
    prep_w<<<64, 256>>>(w_out, woh, wol, 256, 64);
    prep_x<<<dim3(NTOK / 32, 8, 8), 256>>>(x);

    gemm_hmma<<<dim3(NTOK / 64, 3, 8), 128, 2 * GST>>>(
        wqh, wql, xth, xtl, qkv, nullptr, 384, 8);

    prep_qk<<<dim3(NTOK / 32, 8, 8), 256>>>();
    prep_v<<<dim3((8 * 128 * NT2) / 256), 256>>>();

    attn_hmma<<<dim3(NTOK / 128, 4, 8), 128>>>();

    gemm_hmma<<<dim3(NTOK / 64, 2, 8), 128, 2 * GST>>>(
        woh, wol, ah, al, out, b_out, 256, 4);
}

// round 12
// speedup vs baseline: 3.0448x; 1.0167x over previous
#include <cuda_runtime.h>
#include <cuda_bf16.h>
#include <cstdint>

// Attention_9328668967755 — all-HMMA bf16-split pipeline.
// R12: gemm1 epilogue fuses Q/K/V transpose+split; attn kt-loop software-pipelined;
//      gemm b-fragment prefetch.
// b=8, c=256, n=2304, heads=4, d_head=32.

#define NTOK 2304
#define NT2  1152
#define SCALE 0.17677669529663689f

__device__ unsigned g_qh[8 * 4 * NTOK * 16];
__device__ unsigned g_ql[8 * 4 * NTOK * 16];
__device__ unsigned g_kh[8 * 4 * NTOK * 16];
__device__ unsigned g_kl[8 * 4 * NTOK * 16];
__device__ unsigned g_vh[8 * 128 * NT2];
__device__ unsigned g_vl[8 * 128 * NT2];
// k-block tiled: [b][kb][tok][16 u32]
__device__ unsigned g_xth[8 * 8 * NTOK * 16];
__device__ unsigned g_xtl[8 * 8 * NTOK * 16];
__device__ unsigned g_ah[8 * 4 * NTOK * 16];
__device__ unsigned g_al[8 * 4 * NTOK * 16];
// weights k-block tiled: [kb][M][16 u32]
__device__ unsigned g_wqh[8 * 384 * 16];
__device__ unsigned g_wql[8 * 384 * 16];
__device__ unsigned g_woh[4 * 256 * 16];
__device__ unsigned g_wol[4 * 256 * 16];

// ---------------- helpers ----------------
__device__ __forceinline__ uint32_t cvt_bf16x2(float lo, float hi) {
    uint32_t r;
    asm("cvt.rn.satfinite.bf16x2.f32 %0, %1, %2;" : "=r"(r) : "f"(hi), "f"(lo));
    return r;
}
__device__ __forceinline__ float bflo(uint32_t u) { return __uint_as_float(u << 16); }
__device__ __forceinline__ float bfhi(uint32_t u) { return __uint_as_float(u & 0xffff0000u); }

__device__ __forceinline__ uint32_t smem_u32(const void* p) {
    uint32_t a;
    asm("{ .reg .u64 t; cvta.to.shared.u64 t, %1; cvt.u32.u64 %0, t; }" : "=r"(a) : "l"(p));
    return a;
}
__device__ __forceinline__ void mma16816(float* c, const uint32_t* a,
                                         uint32_t b0, uint32_t b1) {
    asm volatile(
        "mma.sync.aligned.m16n8k16.row.col.f32.bf16.bf16.f32 "
        "{%0,%1,%2,%3}, {%4,%5,%6,%7}, {%8,%9}, {%0,%1,%2,%3};"
        : "+f"(c[0]), "+f"(c[1]), "+f"(c[2]), "+f"(c[3])
        : "r"(a[0]), "r"(a[1]), "r"(a[2]), "r"(a[3]), "r"(b0), "r"(b1));
}
__device__ __forceinline__ void ldmx4(uint32_t* r, uint32_t addr) {
    asm volatile("ldmatrix.sync.aligned.m8n8.x4.shared.b16 {%0,%1,%2,%3}, [%4];"
                 : "=r"(r[0]), "=r"(r[1]), "=r"(r[2]), "=r"(r[3]) : "r"(addr));
}
#define CP_ASYNC(dst, src) \
    asm volatile("cp.async.cg.shared.global [%0], [%1], 16;" :: "r"(dst), "l"(src) : "memory")
#define CP_COMMIT asm volatile("cp.async.commit_group;" ::: "memory")
#define CP_WAIT1 asm volatile("cp.async.wait_group 1;" ::: "memory")
#define CP_WAIT0 asm volatile("cp.async.wait_group 0;" ::: "memory")

// ---------------- prep: weight split to [kb][M][16] ----------------
__global__ __launch_bounds__(256)
void prep_w(const float* __restrict__ src, unsigned* __restrict__ dh,
            unsigned* __restrict__ dl, int M, int kws)
{
    int idx = blockIdx.x * 256 + threadIdx.x;
    if (idx >= M * kws) return;
    int m = idx / kws, kw = idx % kws;
    float2 s = *(const float2*)(src + (size_t)idx * 2);
    uint32_t hw = cvt_bf16x2(s.x, s.y);
    uint32_t lw = cvt_bf16x2(s.x - bflo(hw), s.y - bfhi(hw));
    size_t dst = ((size_t)(kw >> 4) * M + m) * 16 + (kw & 15);
    dh[dst] = hw;
    dl[dst] = lw;
}

// ---------------- prep: x transpose+split to [b][kb][tok][16] ----------------
__global__ __launch_bounds__(256)
void prep_x(const float* __restrict__ x)
{
    __shared__ float ts[32][33];
    const int t = threadIdx.x;
    const int tok0 = blockIdx.x * 32;
    const int k0 = blockIdx.y * 32;
    const int b = blockIdx.z;

    {
        int r = t >> 3, c = (t & 7) * 4;
        float4 v = *(const float4*)(x + ((size_t)b * 256 + k0 + r) * NTOK + tok0 + c);
        ts[r][c + 0] = v.x; ts[r][c + 1] = v.y; ts[r][c + 2] = v.z; ts[r][c + 3] = v.w;
    }
    __syncthreads();

    int tok = t >> 3, kq = (t & 7) * 4;
    float f0 = ts[kq + 0][tok], f1 = ts[kq + 1][tok];
    float f2 = ts[kq + 2][tok], f3 = ts[kq + 3][tok];

    uint32_t h01 = cvt_bf16x2(f0, f1);
    uint32_t l01 = cvt_bf16x2(f0 - bflo(h01), f1 - bfhi(h01));
    uint32_t h23 = cvt_bf16x2(f2, f3);
    uint32_t l23 = cvt_bf16x2(f2 - bflo(h23), f3 - bfhi(h23));

    size_t gi = (((size_t)b * 8 + blockIdx.y) * NTOK + tok0 + tok) * 16 + kq / 2;
    g_xth[gi] = h01; g_xth[gi + 1] = h23;
    g_xtl[gi] = l01; g_xtl[gi + 1] = l23;
}

// ---------------- HMMA GEMM ----------------
// MODE 0: plain fp32 C(+bias) epilogue.
// MODE 1: qkv epilogue — blockIdx.y selects Q(0)/K(1)/V(2); writes split bf16
//         Q/K transposed per-head into g_qh/g_kh (Q pre-scaled), V into g_vh.
// stage layout (bytes): Wh@0 (10240), Wl@10240, Xh@20480 (5120), Xl@25600; stride 30720
#define GST 30720
template <int MODE>
__global__ __launch_bounds__(128, 3)
void gemm_hmma(const unsigned* __restrict__ wh, const unsigned* __restrict__ wl,
               const unsigned* __restrict__ xh, const unsigned* __restrict__ xl,
               float* __restrict__ C, const float* __restrict__ bias,
               int M, int nkb)
{
    extern __shared__ __align__(16) unsigned char sm[];
    const int tid = threadIdx.x;
    const int w = tid >> 5, lane = tid & 31;
    const int t4 = lane >> 2, tm4 = lane & 3;
    const int nb = blockIdx.x * 64;
    const int mb = blockIdx.y * 128;
    const int bz = blockIdx.z;

    const uint32_t sb = smem_u32(sm);
    const uint32_t stW = (uint32_t)((tid >> 2) * 80 + (tid & 3) * 16);
    const uint32_t aoff = (uint32_t)((w * 32 + (lane & 7) + ((lane >> 3) & 1) * 8) * 80
                                     + (lane >> 4) * 16);
    const uint32_t boff = (uint32_t)(((lane & 7) + ((lane >> 4) & 1) * 8) * 80
                                     + ((lane >> 3) & 1) * 16);

    float o[2][8][4];
#pragma unroll
    for (int f = 0; f < 2; f++)
#pragma unroll
        for (int nf = 0; nf < 8; nf++)
#pragma unroll
            for (int r = 0; r < 4; r++) o[f][nf][r] = 0.f;

    auto load_stage = [&](int kb) {
        uint32_t st = sb + (kb & 1) * GST;
        const unsigned* gwh = wh + ((size_t)kb * M + mb) * 16 + tid * 4;
        const unsigned* gwl = wl + ((size_t)kb * M + mb) * 16 + tid * 4;
#pragma unroll
        for (int i = 0; i < 4; i++) {
            CP_ASYNC(st + stW + i * 2560, gwh + i * 512);
            CP_ASYNC(st + 10240 + stW + i * 2560, gwl + i * 512);
        }
        const unsigned* gxh = xh + (((size_t)bz * nkb + kb) * NTOK + nb) * 16 + tid * 4;
        const unsigned* gxl = xl + (((size_t)bz * nkb + kb) * NTOK + nb) * 16 + tid * 4;
#pragma unroll
        for (int i = 0; i < 2; i++) {
            CP_ASYNC(st + 20480 + stW + i * 2560, gxh + i * 512);
            CP_ASYNC(st + 25600 + stW + i * 2560, gxl + i * 512);
        }
        CP_COMMIT;
    };

    load_stage(0);
    for (int kb = 0; kb < nkb; kb++) {
        if (kb + 1 < nkb) { load_stage(kb + 1); CP_WAIT1; }
        else              { CP_WAIT0; }
        __syncthreads();
        const uint32_t st = sb + (kb & 1) * GST;

#pragma unroll
        for (int ks = 0; ks < 2; ks++) {
            uint32_t ah[2][4], al[2][4];
            ldmx4(ah[0], st + aoff + ks * 32);
            ldmx4(ah[1], st + aoff + 1280 + ks * 32);
            ldmx4(al[0], st + 10240 + aoff + ks * 32);
            ldmx4(al[1], st + 10240 + aoff + 1280 + ks * 32);

            uint32_t bh4[2][4], bl4[2][4];
            ldmx4(bh4[0], st + 20480 + boff + ks * 32);
            ldmx4(bl4[0], st + 25600 + boff + ks * 32);
#pragma unroll
            for (int p = 0; p < 4; p++) {
                if (p < 3) {
                    ldmx4(bh4[(p + 1) & 1], st + 20480 + boff + (p + 1) * 1280 + ks * 32);
                    ldmx4(bl4[(p + 1) & 1], st + 25600 + boff + (p + 1) * 1280 + ks * 32);
                }
                const uint32_t* bh = bh4[p & 1];
                const uint32_t* bl = bl4[p & 1];
#pragma unroll
                for (int f = 0; f < 2; f++) {
                    mma16816(o[f][2 * p + 0], ah[f], bh[0], bh[1]);
                    mma16816(o[f][2 * p + 0], ah[f], bl[0], bl[1]);
                    mma16816(o[f][2 * p + 0], al[f], bh[0], bh[1]);
                    mma16816(o[f][2 * p + 1], ah[f], bh[2], bh[3]);
                    mma16816(o[f][2 * p + 1], ah[f], bl[2], bl[3]);
                    mma16816(o[f][2 * p + 1], al[f], bh[2], bh[3]);
                }
            }
        }
        __syncthreads();
    }

    if (MODE == 0) {
        float* Cb = C + (size_t)bz * M * NTOK;
#pragma unroll
        for (int f = 0; f < 2; f++) {
            int row0 = mb + w * 32 + f * 16 + t4;
            int row1 = row0 + 8;
            float b0 = bias ? bias[row0] : 0.f;
            float b1 = bias ? bias[row1] : 0.f;
#pragma unroll
            for (int nf = 0; nf < 8; nf++) {
                int col = nb + nf * 8 + tm4 * 2;
                *(float2*)(Cb + (size_t)row0 * NTOK + col) =
                    make_float2(o[f][nf][0] + b0, o[f][nf][1] + b0);
                *(float2*)(Cb + (size_t)row1 * NTOK + col) =
                    make_float2(o[f][nf][2] + b1, o[f][nf][3] + b1);
            }
        }
    } else {
        if (blockIdx.y == 2) {
            // V: fragments hold adjacent-token pairs per channel — direct split store.
#pragma unroll
            for (int f = 0; f < 2; f++)
#pragma unroll
                for (int rr = 0; rr < 2; rr++) {
                    int row = w * 32 + f * 16 + rr * 8 + t4;   // channel 0..127
                    size_t vr = (size_t)(bz * 128 + row) * NT2;
#pragma unroll
                    for (int nf = 0; nf < 8; nf++) {
                        float v0 = o[f][nf][rr * 2 + 0];
                        float v1 = o[f][nf][rr * 2 + 1];
                        uint32_t hw = cvt_bf16x2(v0, v1);
                        uint32_t lw = cvt_bf16x2(v0 - bflo(hw), v1 - bfhi(hw));
                        size_t tp = (size_t)(nb >> 1) + nf * 4 + tm4;
                        g_vh[vr + tp] = hw;
                        g_vl[vr + tp] = lw;
                    }
                }
        } else {
            // Q/K: transpose via smem (reuse pipeline buffers), then split-store
            // token-major per head. Q gets SCALE.
            float* ts = (float*)sm;   // [64 tok][stride 130 f32] (ch 0..127)
#pragma unroll
            for (int f = 0; f < 2; f++)
#pragma unroll
                for (int nf = 0; nf < 8; nf++) {
                    int rowb = w * 32 + f * 16 + t4;
                    int colb = nf * 8 + tm4 * 2;
                    ts[(colb + 0) * 130 + rowb]     = o[f][nf][0];
                    ts[(colb + 1) * 130 + rowb]     = o[f][nf][1];
                    ts[(colb + 0) * 130 + rowb + 8] = o[f][nf][2];
                    ts[(colb + 1) * 130 + rowb + 8] = o[f][nf][3];
                }
            __syncthreads();

            const float sc = (blockIdx.y == 0) ? SCALE : 1.f;
            unsigned* oh = (blockIdx.y == 0) ? g_qh : g_kh;
            unsigned* ol = (blockIdx.y == 0) ? g_ql : g_kl;
            const int tok = tid >> 1, half = tid & 1;
            const float* trow = ts + tok * 130;
#pragma unroll
            for (int hd = 0; hd < 4; hd++) {
                uint32_t hw8[8], lw8[8];
#pragma unroll
                for (int wp = 0; wp < 8; wp++) {
                    int ch = hd * 32 + (half * 8 + wp) * 2;
                    float v0 = trow[ch] * sc;
                    float v1 = trow[ch + 1] * sc;
                    uint32_t hw = cvt_bf16x2(v0, v1);
                    hw8[wp] = hw;
                    lw8[wp] = cvt_bf16x2(v0 - bflo(hw), v1 - bfhi(hw));
                }
                size_t gi = ((size_t)(bz * 4 + hd) * NTOK + nb + tok) * 16 + half * 8;
                *(uint4*)(oh + gi)     = make_uint4(hw8[0], hw8[1], hw8[2], hw8[3]);
                *(uint4*)(oh + gi + 4) = make_uint4(hw8[4], hw8[5], hw8[6], hw8[7]);
                *(uint4*)(ol + gi)     = make_uint4(lw8[0], lw8[1], lw8[2], lw8[3]);
                *(uint4*)(ol + gi + 4) = make_uint4(lw8[4], lw8[5], lw8[6], lw8[7]);
            }
        }
    }
}

// ---------------- attention (HMMA + ldmatrix + cp.async + kt pipelining) ----------------
// stage layout: Kh@0 (5120), Kl@5120, Vh@10240 (4608), Vl@14848; stride 19456
#define AST 19456
__global__ __launch_bounds__(128, 3)
void attn_hmma()
{
    __shared__ __align__(16) unsigned char sm[2 * AST];

    const int tid = threadIdx.x;
    const int w = tid >> 5, lane = tid & 31;
    const int t4 = lane >> 2, tm4 = lane & 3;
    const int q0 = blockIdx.x * 128;
    const int h = blockIdx.y, b = blockIdx.z;
    const int bh = b * 4 + h;

    uint32_t qh[2][2][4], ql[2][2][4];
#pragma unroll
    for (int f = 0; f < 2; f++)
#pragma unroll
        for (int ks = 0; ks < 2; ks++)
#pragma unroll
            for (int r = 0; r < 4; r++) {
                int row = q0 + w * 32 + f * 16 + (r & 1) * 8 + t4;
                int word = ks * 8 + tm4 + (r >> 1) * 4;
                size_t gi = ((size_t)bh * NTOK + row) * 16 + word;
                qh[f][ks][r] = g_qh[gi];
                ql[f][ks][r] = g_ql[gi];
            }

    float o[2][4][4];
#pragma unroll
    for (int f = 0; f < 2; f++)
#pragma unroll
        for (int j = 0; j < 4; j++)
#pragma unroll
            for (int r = 0; r < 4; r++) o[f][j][r] = 0.f;
    float lsum[2][2] = {{0.f, 0.f}, {0.f, 0.f}};

    const uint32_t sb = smem_u32(sm);
    const int ktok = tid >> 1, khalf = tid & 1;
    const size_t kgbase = ((size_t)bh * NTOK + ktok) * 16 + khalf * 8;
    const uint32_t kst = (uint32_t)(ktok * 80 + khalf * 32);
    const int vd = tid >> 2, vq = tid & 3;
    const size_t vgbase = ((size_t)(b * 128 + h * 32 + vd)) * NT2 + vq * 8;
    const uint32_t vst = (uint32_t)(vd * 144 + vq * 32);

    const uint32_t koff = (uint32_t)((lane & 7) * 80 + (lane >> 3) * 16);
    const uint32_t voff = (uint32_t)(((lane & 7) + ((lane >> 4) & 1) * 8) * 144
                                     + ((lane >> 3) & 1) * 16);

    auto load_stage = [&](int t) {
        uint32_t st = sb + (t & 1) * AST;
        const unsigned* s = g_kh + kgbase + (size_t)t * 1024;
        CP_ASYNC(st + kst, s); CP_ASYNC(st + kst + 16, s + 4);
        s = g_kl + kgbase + (size_t)t * 1024;
        CP_ASYNC(st + 5120 + kst, s); CP_ASYNC(st + 5120 + kst + 16, s + 4);
        s = g_vh + vgbase + (size_t)t * 32;
        CP_ASYNC(st + 10240 + vst, s); CP_ASYNC(st + 10240 + vst + 16, s + 4);
        s = g_vl + vgbase + (size_t)t * 32;
        CP_ASYNC(st + 14848 + vst, s); CP_ASYNC(st + 14848 + vst + 16, s + 4);
        CP_COMMIT;
    };

    uint32_t pah[2][2][4], pal[2][2][4];   // [parity][f][4]

    load_stage(0);
    for (int t = 0; t < 36; t++) {
        if (t + 1 < 36) { load_stage(t + 1); CP_WAIT1; }
        else            { CP_WAIT0; }
        __syncthreads();
        const uint32_t st = sb + (t & 1) * AST;

        // S/exp/pack for chunk kt -> buffers[par]
        auto computeS = [&](int kt, int par) {
            float e2[2][2][4];
#pragma unroll
            for (int ii = 0; ii < 2; ii++) {
                const int i = kt * 2 + ii;
                uint32_t kh4[4], kl4[4];
                ldmx4(kh4, st + koff + i * 640);
                ldmx4(kl4, st + 5120 + koff + i * 640);
#pragma unroll
                for (int f = 0; f < 2; f++) {
                    float cacc[4] = {0.f, 0.f, 0.f, 0.f};
                    mma16816(cacc, qh[f][0], kh4[0], kh4[1]);
                    mma16816(cacc, qh[f][0], kl4[0], kl4[1]);
                    mma16816(cacc, ql[f][0], kh4[0], kh4[1]);
                    mma16816(cacc, qh[f][1], kh4[2], kh4[3]);
                    mma16816(cacc, qh[f][1], kl4[2], kl4[3]);
                    mma16816(cacc, ql[f][1], kh4[2], kh4[3]);
#pragma unroll
                    for (int r = 0; r < 4; r++) e2[f][ii][r] = __expf(cacc[r]);
                    lsum[f][0] += e2[f][ii][0] + e2[f][ii][1];
                    lsum[f][1] += e2[f][ii][2] + e2[f][ii][3];
                }
            }
#pragma unroll
            for (int f = 0; f < 2; f++) {
                uint32_t a0 = cvt_bf16x2(e2[f][0][0], e2[f][0][1]);
                uint32_t a1 = cvt_bf16x2(e2[f][0][2], e2[f][0][3]);
                uint32_t a2 = cvt_bf16x2(e2[f][1][0], e2[f][1][1]);
                uint32_t a3 = cvt_bf16x2(e2[f][1][2], e2[f][1][3]);
                pah[par][f][0] = a0; pah[par][f][1] = a1;
                pah[par][f][2] = a2; pah[par][f][3] = a3;
                pal[par][f][0] = cvt_bf16x2(e2[f][0][0] - bflo(a0), e2[f][0][1] - bfhi(a0));
                pal[par][f][1] = cvt_bf16x2(e2[f][0][2] - bflo(a1), e2[f][0][3] - bfhi(a1));
                pal[par][f][2] = cvt_bf16x2(e2[f][1][0] - bflo(a2), e2[f][1][1] - bfhi(a2));
                pal[par][f][3] = cvt_bf16x2(e2[f][1][2] - bflo(a3), e2[f][1][3] - bfhi(a3));
            }
        };

        auto doPV = [&](int kt, int par) {
#pragma unroll
            for (int jp = 0; jp < 2; jp++) {
                uint32_t vh4[4], vl4[4];
                ldmx4(vh4, st + 10240 + voff + jp * 2304 + kt * 32);
                ldmx4(vl4, st + 14848 + voff + jp * 2304 + kt * 32);
#pragma unroll
                for (int f = 0; f < 2; f++) {
                    mma16816(o[f][2 * jp + 0], pah[par][f], vh4[0], vh4[1]);
                    mma16816(o[f][2 * jp + 0], pah[par][f], vl4[0], vl4[1]);
                    mma16816(o[f][2 * jp + 0], pal[par][f], vh4[0], vh4[1]);
                    mma16816(o[f][2 * jp + 1], pah[par][f], vh4[2], vh4[3]);
                    mma16816(o[f][2 * jp + 1], pah[par][f], vl4[2], vl4[3]);
                    mma16816(o[f][2 * jp + 1], pal[par][f], vh4[2], vh4[3]);
                }
            }
        };

        computeS(0, 0);
#pragma unroll
        for (int kt = 0; kt < 4; kt++) {
            if (kt < 3) computeS(kt + 1, (kt + 1) & 1);
            doPV(kt, kt & 1);
        }
        __syncthreads();
    }

    // epilogue: normalize + split-store att in k-tiled layout [b][kb=h][tok][16]
    float inv[2][2];
#pragma unroll
    for (int f = 0; f < 2; f++)
#pragma unroll
        for (int rr = 0; rr < 2; rr++) {
            float lv = lsum[f][rr];
            lv += __shfl_xor_sync(0xffffffffu, lv, 1);
            lv += __shfl_xor_sync(0xffffffffu, lv, 2);
            inv[f][rr] = 1.f / lv;
        }

#pragma unroll
    for (int f = 0; f < 2; f++)
#pragma unroll
        for (int rr = 0; rr < 2; rr++) {
            int qrow = q0 + w * 32 + f * 16 + rr * 8 + t4;
            float iv = inv[f][rr];
#pragma unroll
            for (int j = 0; j < 4; j++) {
                float v0 = o[f][j][rr * 2 + 0] * iv;
                float v1 = o[f][j][rr * 2 + 1] * iv;
                uint32_t hw = cvt_bf16x2(v0, v1);
                uint32_t lw = cvt_bf16x2(v0 - bflo(hw), v1 - bfhi(hw));
                size_t gi = (((size_t)b * 4 + h) * NTOK + qrow) * 16 + j * 4 + tm4;
                g_ah[gi] = hw;
                g_al[gi] = lw;
            }
        }
}

// ---------------- launch ----------------
extern "C" void kernel_launch(void* const* d_in, const int* in_sizes, int n_in,
                              void* d_out, int out_size)
{
    const float* x     = (const float*)d_in[0];
    const float* w_qkv = (const float*)d_in[1];
    const float* w_out = (const float*)d_in[2];
    const float* b_out = (const float*)d_in[3];
    float* out = (float*)d_out;

    unsigned *wqh, *wql, *woh, *wol, *xth, *xtl, *ah, *al;
    cudaGetSymbolAddress((void**)&wqh, g_wqh);
    cudaGetSymbolAddress((void**)&wql, g_wql);
    cudaGetSymbolAddress((void**)&woh, g_woh);
    cudaGetSymbolAddress((void**)&wol, g_wol);
    cudaGetSymbolAddress((void**)&xth, g_xth);
    cudaGetSymbolAddress((void**)&xtl, g_xtl);
    cudaGetSymbolAddress((void**)&ah, g_ah);
    cudaGetSymbolAddress((void**)&al, g_al);

    static int smem_set = 0;
    if (!smem_set) {
        cudaFuncSetAttribute(gemm_hmma<0>, cudaFuncAttributeMaxDynamicSharedMemorySize,
                             2 * GST);
        cudaFuncSetAttribute(gemm_hmma<1>, cudaFuncAttributeMaxDynamicSharedMemorySize,
                             2 * GST);
        smem_set = 1;
    }

    prep_w<<<192, 256>>>(w_qkv, wqh, wql, 384, 128);
    prep_w<<<64, 256>>>(w_out, woh, wol, 256, 64);
    prep_x<<<dim3(NTOK / 32, 8, 8), 256>>>(x);

    // qkv GEMM with fused Q/K/V transpose+split epilogue
    gemm_hmma<1><<<dim3(NTOK / 64, 3, 8), 128, 2 * GST>>>(
        wqh, wql, xth, xtl, nullptr, nullptr, 384, 8);

    attn_hmma<<<dim3(NTOK / 128, 4, 8), 128>>>();

    gemm_hmma<0><<<dim3(NTOK / 64, 2, 8), 128, 2 * GST>>>(
        woh, wol, ah, al, out, b_out, 256, 4);
}

// round 13
// speedup vs baseline: 4.1398x; 1.3596x over previous
#include <cuda_runtime.h>
#include <cuda_bf16.h>
#include <cstdint>

// Attention_9328668967755 — R13: fp16 2-term attention (S=(Qh+Ql)Kh, PV=P(Vh+Vl)),
// 256-thread attn CTAs, exp2 with folded log2e; projections stay bf16 3-term HMMA.
// b=8, c=256, n=2304, heads=4, d_head=32.

#define NTOK 2304
#define NT2  1152
#define QSCALE (0.17677669529663689f * 1.4426950408889634f)  // dim^-0.5 * log2(e)

// attention operands (fp16 packed pairs)
__device__ unsigned g_qh[8 * 4 * NTOK * 16];   // Q hi (fp16x2), [bh][tok][16]
__device__ unsigned g_ql[8 * 4 * NTOK * 16];   // Q lo
__device__ unsigned g_kh[8 * 4 * NTOK * 16];   // K hi (single-term)
__device__ unsigned g_vh[8 * 128 * NT2];       // V hi, [b*128+ch][NT2]
__device__ unsigned g_vl[8 * 128 * NT2];       // V lo
// gemm operands (bf16 split, k-block tiled)
__device__ unsigned g_xth[8 * 8 * NTOK * 16];
__device__ unsigned g_xtl[8 * 8 * NTOK * 16];
__device__ unsigned g_ah[8 * 4 * NTOK * 16];
__device__ unsigned g_al[8 * 4 * NTOK * 16];
__device__ unsigned g_wqh[8 * 384 * 16];
__device__ unsigned g_wql[8 * 384 * 16];
__device__ unsigned g_woh[4 * 256 * 16];
__device__ unsigned g_wol[4 * 256 * 16];

// ---------------- helpers ----------------
__device__ __forceinline__ uint32_t cvt_bf16x2(float lo, float hi) {
    uint32_t r;
    asm("cvt.rn.satfinite.bf16x2.f32 %0, %1, %2;" : "=r"(r) : "f"(hi), "f"(lo));
    return r;
}
__device__ __forceinline__ float bflo(uint32_t u) { return __uint_as_float(u << 16); }
__device__ __forceinline__ float bfhi(uint32_t u) { return __uint_as_float(u & 0xffff0000u); }

__device__ __forceinline__ uint32_t cvt_f16x2(float lo, float hi) {
    uint32_t r;
    asm("cvt.rn.f16x2.f32 %0, %1, %2;" : "=r"(r) : "f"(hi), "f"(lo));
    return r;
}
__device__ __forceinline__ float f16lo(uint32_t u) {
    float f;
    asm("{ .reg .f16 l, h; mov.b32 {l, h}, %1; cvt.f32.f16 %0, l; }" : "=f"(f) : "r"(u));
    return f;
}
__device__ __forceinline__ float f16hi(uint32_t u) {
    float f;
    asm("{ .reg .f16 l, h; mov.b32 {l, h}, %1; cvt.f32.f16 %0, h; }" : "=f"(f) : "r"(u));
    return f;
}
__device__ __forceinline__ float ex2(float x) {
    float r;
    asm("ex2.approx.f32 %0, %1;" : "=f"(r) : "f"(x));
    return r;
}
__device__ __forceinline__ uint32_t smem_u32(const void* p) {
    uint32_t a;
    asm("{ .reg .u64 t; cvta.to.shared.u64 t, %1; cvt.u32.u64 %0, t; }" : "=r"(a) : "l"(p));
    return a;
}
__device__ __forceinline__ void mma_bf16(float* c, const uint32_t* a,
                                         uint32_t b0, uint32_t b1) {
    asm volatile(
        "mma.sync.aligned.m16n8k16.row.col.f32.bf16.bf16.f32 "
        "{%0,%1,%2,%3}, {%4,%5,%6,%7}, {%8,%9}, {%0,%1,%2,%3};"
        : "+f"(c[0]), "+f"(c[1]), "+f"(c[2]), "+f"(c[3])
        : "r"(a[0]), "r"(a[1]), "r"(a[2]), "r"(a[3]), "r"(b0), "r"(b1));
}
__device__ __forceinline__ void mma_f16(float* c, const uint32_t* a,
                                        uint32_t b0, uint32_t b1) {
    asm volatile(
        "mma.sync.aligned.m16n8k16.row.col.f32.f16.f16.f32 "
        "{%0,%1,%2,%3}, {%4,%5,%6,%7}, {%8,%9}, {%0,%1,%2,%3};"
        : "+f"(c[0]), "+f"(c[1]), "+f"(c[2]), "+f"(c[3])
        : "r"(a[0]), "r"(a[1]), "r"(a[2]), "r"(a[3]), "r"(b0), "r"(b1));
}
__device__ __forceinline__ void ldmx4(uint32_t* r, uint32_t addr) {
    asm volatile("ldmatrix.sync.aligned.m8n8.x4.shared.b16 {%0,%1,%2,%3}, [%4];"
                 : "=r"(r[0]), "=r"(r[1]), "=r"(r[2]), "=r"(r[3]) : "r"(addr));
}
#define CP_ASYNC(dst, src) \
    asm volatile("cp.async.cg.shared.global [%0], [%1], 16;" :: "r"(dst), "l"(src) : "memory")
#define CP_COMMIT asm volatile("cp.async.commit_group;" ::: "memory")
#define CP_WAIT1 asm volatile("cp.async.wait_group 1;" ::: "memory")
#define CP_WAIT0 asm volatile("cp.async.wait_group 0;" ::: "memory")

// ---------------- prep: weight split to [kb][M][16] (bf16) ----------------
__global__ __launch_bounds__(256)
void prep_w(const float* __restrict__ src, unsigned* __restrict__ dh,
            unsigned* __restrict__ dl, int M, int kws)
{
    int idx = blockIdx.x * 256 + threadIdx.x;
    if (idx >= M * kws) return;
    int m = idx / kws, kw = idx % kws;
    float2 s = *(const float2*)(src + (size_t)idx * 2);
    uint32_t hw = cvt_bf16x2(s.x, s.y);
    uint32_t lw = cvt_bf16x2(s.x - bflo(hw), s.y - bfhi(hw));
    size_t dst = ((size_t)(kw >> 4) * M + m) * 16 + (kw & 15);
    dh[dst] = hw;
    dl[dst] = lw;
}

// ---------------- prep: x transpose+split to [b][kb][tok][16] (bf16) ----------------
__global__ __launch_bounds__(256)
void prep_x(const float* __restrict__ x)
{
    __shared__ float ts[32][33];
    const int t = threadIdx.x;
    const int tok0 = blockIdx.x * 32;
    const int k0 = blockIdx.y * 32;
    const int b = blockIdx.z;

    {
        int r = t >> 3, c = (t & 7) * 4;
        float4 v = *(const float4*)(x + ((size_t)b * 256 + k0 + r) * NTOK + tok0 + c);
        ts[r][c + 0] = v.x; ts[r][c + 1] = v.y; ts[r][c + 2] = v.z; ts[r][c + 3] = v.w;
    }
    __syncthreads();

    int tok = t >> 3, kq = (t & 7) * 4;
    float f0 = ts[kq + 0][tok], f1 = ts[kq + 1][tok];
    float f2 = ts[kq + 2][tok], f3 = ts[kq + 3][tok];

    uint32_t h01 = cvt_bf16x2(f0, f1);
    uint32_t l01 = cvt_bf16x2(f0 - bflo(h01), f1 - bfhi(h01));
    uint32_t h23 = cvt_bf16x2(f2, f3);
    uint32_t l23 = cvt_bf16x2(f2 - bflo(h23), f3 - bfhi(h23));

    size_t gi = (((size_t)b * 8 + blockIdx.y) * NTOK + tok0 + tok) * 16 + kq / 2;
    g_xth[gi] = h01; g_xth[gi + 1] = h23;
    g_xtl[gi] = l01; g_xtl[gi + 1] = l23;
}

// ---------------- HMMA GEMM (bf16 3-term, cp.async 2-stage) ----------------
// MODE 0: fp32 C (+bias). MODE 1: qkv epilogue (Q/K/V fp16 prep for attention).
#define GST 30720
template <int MODE>
__global__ __launch_bounds__(128, 3)
void gemm_hmma(const unsigned* __restrict__ wh, const unsigned* __restrict__ wl,
               const unsigned* __restrict__ xh, const unsigned* __restrict__ xl,
               float* __restrict__ C, const float* __restrict__ bias,
               int M, int nkb)
{
    extern __shared__ __align__(16) unsigned char sm[];
    const int tid = threadIdx.x;
    const int w = tid >> 5, lane = tid & 31;
    const int t4 = lane >> 2, tm4 = lane & 3;
    const int nb = blockIdx.x * 64;
    const int mb = blockIdx.y * 128;
    const int bz = blockIdx.z;

    const uint32_t sb = smem_u32(sm);
    const uint32_t stW = (uint32_t)((tid >> 2) * 80 + (tid & 3) * 16);
    const uint32_t aoff = (uint32_t)((w * 32 + (lane & 7) + ((lane >> 3) & 1) * 8) * 80
                                     + (lane >> 4) * 16);
    const uint32_t boff = (uint32_t)(((lane & 7) + ((lane >> 4) & 1) * 8) * 80
                                     + ((lane >> 3) & 1) * 16);

    float o[2][8][4];
#pragma unroll
    for (int f = 0; f < 2; f++)
#pragma unroll
        for (int nf = 0; nf < 8; nf++)
#pragma unroll
            for (int r = 0; r < 4; r++) o[f][nf][r] = 0.f;

    auto load_stage = [&](int kb) {
        uint32_t st = sb + (kb & 1) * GST;
        const unsigned* gwh = wh + ((size_t)kb * M + mb) * 16 + tid * 4;
        const unsigned* gwl = wl + ((size_t)kb * M + mb) * 16 + tid * 4;
#pragma unroll
        for (int i = 0; i < 4; i++) {
            CP_ASYNC(st + stW + i * 2560, gwh + i * 512);
            CP_ASYNC(st + 10240 + stW + i * 2560, gwl + i * 512);
        }
        const unsigned* gxh = xh + (((size_t)bz * nkb + kb) * NTOK + nb) * 16 + tid * 4;
        const unsigned* gxl = xl + (((size_t)bz * nkb + kb) * NTOK + nb) * 16 + tid * 4;
#pragma unroll
        for (int i = 0; i < 2; i++) {
            CP_ASYNC(st + 20480 + stW + i * 2560, gxh + i * 512);
            CP_ASYNC(st + 25600 + stW + i * 2560, gxl + i * 512);
        }
        CP_COMMIT;
    };

    load_stage(0);
    for (int kb = 0; kb < nkb; kb++) {
        if (kb + 1 < nkb) { load_stage(kb + 1); CP_WAIT1; }
        else              { CP_WAIT0; }
        __syncthreads();
        const uint32_t st = sb + (kb & 1) * GST;

#pragma unroll
        for (int ks = 0; ks < 2; ks++) {
            uint32_t ah[2][4], al[2][4];
            ldmx4(ah[0], st + aoff + ks * 32);
            ldmx4(ah[1], st + aoff + 1280 + ks * 32);
            ldmx4(al[0], st + 10240 + aoff + ks * 32);
            ldmx4(al[1], st + 10240 + aoff + 1280 + ks * 32);

            uint32_t bh4[2][4], bl4[2][4];
            ldmx4(bh4[0], st + 20480 + boff + ks * 32);
            ldmx4(bl4[0], st + 25600 + boff + ks * 32);
#pragma unroll
            for (int p = 0; p < 4; p++) {
                if (p < 3) {
                    ldmx4(bh4[(p + 1) & 1], st + 20480 + boff + (p + 1) * 1280 + ks * 32);
                    ldmx4(bl4[(p + 1) & 1], st + 25600 + boff + (p + 1) * 1280 + ks * 32);
                }
                const uint32_t* bh = bh4[p & 1];
                const uint32_t* bl = bl4[p & 1];
#pragma unroll
                for (int f = 0; f < 2; f++) {
                    mma_bf16(o[f][2 * p + 0], ah[f], bh[0], bh[1]);
                    mma_bf16(o[f][2 * p + 0], ah[f], bl[0], bl[1]);
                    mma_bf16(o[f][2 * p + 0], al[f], bh[0], bh[1]);
                    mma_bf16(o[f][2 * p + 1], ah[f], bh[2], bh[3]);
                    mma_bf16(o[f][2 * p + 1], ah[f], bl[2], bl[3]);
                    mma_bf16(o[f][2 * p + 1], al[f], bh[2], bh[3]);
                }
            }
        }
        __syncthreads();
    }

    if (MODE == 0) {
        float* Cb = C + (size_t)bz * M * NTOK;
#pragma unroll
        for (int f = 0; f < 2; f++) {
            int row0 = mb + w * 32 + f * 16 + t4;
            int row1 = row0 + 8;
            float b0 = bias ? bias[row0] : 0.f;
            float b1 = bias ? bias[row1] : 0.f;
#pragma unroll
            for (int nf = 0; nf < 8; nf++) {
                int col = nb + nf * 8 + tm4 * 2;
                *(float2*)(Cb + (size_t)row0 * NTOK + col) =
                    make_float2(o[f][nf][0] + b0, o[f][nf][1] + b0);
                *(float2*)(Cb + (size_t)row1 * NTOK + col) =
                    make_float2(o[f][nf][2] + b1, o[f][nf][3] + b1);
            }
        }
    } else {
        if (blockIdx.y == 2) {
            // V: fp16 split, token pairs direct from fragments.
#pragma unroll
            for (int f = 0; f < 2; f++)
#pragma unroll
                for (int rr = 0; rr < 2; rr++) {
                    int row = w * 32 + f * 16 + rr * 8 + t4;   // channel
                    size_t vr = (size_t)(bz * 128 + row) * NT2;
#pragma unroll
                    for (int nf = 0; nf < 8; nf++) {
                        float v0 = o[f][nf][rr * 2 + 0];
                        float v1 = o[f][nf][rr * 2 + 1];
                        uint32_t hw = cvt_f16x2(v0, v1);
                        uint32_t lw = cvt_f16x2(v0 - f16lo(hw), v1 - f16hi(hw));
                        size_t tp = (size_t)(nb >> 1) + nf * 4 + tm4;
                        g_vh[vr + tp] = hw;
                        g_vl[vr + tp] = lw;
                    }
                }
        } else {
            // Q/K: transpose via smem, fp16 convert. Q: hi+lo (scaled by QSCALE);
            // K: hi only (2-term scheme drops K-lo).
            float* ts = (float*)sm;   // [64 tok][stride 130 f32]
#pragma unroll
            for (int f = 0; f < 2; f++)
#pragma unroll
                for (int nf = 0; nf < 8; nf++) {
                    int rowb = w * 32 + f * 16 + t4;
                    int colb = nf * 8 + tm4 * 2;
                    ts[(colb + 0) * 130 + rowb]     = o[f][nf][0];
                    ts[(colb + 1) * 130 + rowb]     = o[f][nf][1];
                    ts[(colb + 0) * 130 + rowb + 8] = o[f][nf][2];
                    ts[(colb + 1) * 130 + rowb + 8] = o[f][nf][3];
                }
            __syncthreads();

            const int isQ = (blockIdx.y == 0);
            const float sc = isQ ? QSCALE : 1.f;
            const int tok = tid >> 1, half = tid & 1;
            const float* trow = ts + tok * 130;
#pragma unroll
            for (int hd = 0; hd < 4; hd++) {
                uint32_t hw8[8], lw8[8];
#pragma unroll
                for (int wp = 0; wp < 8; wp++) {
                    int ch = hd * 32 + (half * 8 + wp) * 2;
                    float v0 = trow[ch] * sc;
                    float v1 = trow[ch + 1] * sc;
                    uint32_t hw = cvt_f16x2(v0, v1);
                    hw8[wp] = hw;
                    if (isQ) lw8[wp] = cvt_f16x2(v0 - f16lo(hw), v1 - f16hi(hw));
                }
                size_t gi = ((size_t)(bz * 4 + hd) * NTOK + nb + tok) * 16 + half * 8;
                unsigned* oh = isQ ? g_qh : g_kh;
                *(uint4*)(oh + gi)     = make_uint4(hw8[0], hw8[1], hw8[2], hw8[3]);
                *(uint4*)(oh + gi + 4) = make_uint4(hw8[4], hw8[5], hw8[6], hw8[7]);
                if (isQ) {
                    *(uint4*)(g_ql + gi)     = make_uint4(lw8[0], lw8[1], lw8[2], lw8[3]);
                    *(uint4*)(g_ql + gi + 4) = make_uint4(lw8[4], lw8[5], lw8[6], lw8[7]);
                }
            }
        }
    }
}

// ---------------- attention (fp16 2-term HMMA, 256 threads) ----------------
// stage: Kh@0 (64x80=5120), Vh@5120 (32x144=4608), Vl@9728; stride 14336
#define AST 14336
__global__ __launch_bounds__(256, 2)
void attn_hmma()
{
    __shared__ __align__(16) unsigned char sm[2 * AST];

    const int tid = threadIdx.x;
    const int w = tid >> 5, lane = tid & 31;
    const int t4 = lane >> 2, tm4 = lane & 3;
    const int q0 = blockIdx.x * 128;
    const int h = blockIdx.y, b = blockIdx.z;
    const int bh = b * 4 + h;

    // Q fragments: warp covers 16 query rows (q0 + w*16 ..).
    uint32_t qh[2][4], ql[2][4];
#pragma unroll
    for (int ks = 0; ks < 2; ks++)
#pragma unroll
        for (int r = 0; r < 4; r++) {
            int row = q0 + w * 16 + (r & 1) * 8 + t4;
            int word = ks * 8 + tm4 + (r >> 1) * 4;
            size_t gi = ((size_t)bh * NTOK + row) * 16 + word;
            qh[ks][r] = g_qh[gi];
            ql[ks][r] = g_ql[gi];
        }

    float o[4][4];
#pragma unroll
    for (int j = 0; j < 4; j++)
#pragma unroll
        for (int r = 0; r < 4; r++) o[j][r] = 0.f;
    float lsum[2] = {0.f, 0.f};

    const uint32_t sb = smem_u32(sm);
    // cooperative load maps (256 threads, 16B each)
    const int ktok = tid >> 2, kq = tid & 3;
    const size_t kgbase = ((size_t)bh * NTOK + ktok) * 16 + kq * 4;
    const uint32_t kst = (uint32_t)(ktok * 80 + kq * 16);
    const int vd = tid >> 3, vc = tid & 7;
    const size_t vgbase = ((size_t)(b * 128 + h * 32 + vd)) * NT2 + vc * 4;
    const uint32_t vst = (uint32_t)(vd * 144 + vc * 16);

    const uint32_t koff = (uint32_t)((lane & 7) * 80 + (lane >> 3) * 16);
    const uint32_t voff = (uint32_t)(((lane & 7) + ((lane >> 4) & 1) * 8) * 144
                                     + ((lane >> 3) & 1) * 16);

    auto load_stage = [&](int t) {
        uint32_t st = sb + (t & 1) * AST;
        CP_ASYNC(st + kst, g_kh + kgbase + (size_t)t * 1024);
        CP_ASYNC(st + 5120 + vst, g_vh + vgbase + (size_t)t * 32);
        CP_ASYNC(st + 9728 + vst, g_vl + vgbase + (size_t)t * 32);
        CP_COMMIT;
    };

    load_stage(0);
    for (int t = 0; t < 36; t++) {
        if (t + 1 < 36) { load_stage(t + 1); CP_WAIT1; }
        else            { CP_WAIT0; }
        __syncthreads();
        const uint32_t st = sb + (t & 1) * AST;

#pragma unroll
        for (int kt = 0; kt < 4; kt++) {
            float e[2][4];
            // S = (Qh + Ql) * Kh  (2 terms), exp2
#pragma unroll
            for (int ii = 0; ii < 2; ii++) {
                uint32_t kh4[4];
                ldmx4(kh4, st + koff + (kt * 2 + ii) * 640);
                float cacc[4] = {0.f, 0.f, 0.f, 0.f};
                mma_f16(cacc, qh[0], kh4[0], kh4[1]);
                mma_f16(cacc, ql[0], kh4[0], kh4[1]);
                mma_f16(cacc, qh[1], kh4[2], kh4[3]);
                mma_f16(cacc, ql[1], kh4[2], kh4[3]);
#pragma unroll
                for (int r = 0; r < 4; r++) e[ii][r] = ex2(cacc[r]);
                lsum[0] += e[ii][0] + e[ii][1];
                lsum[1] += e[ii][2] + e[ii][3];
            }
            // pack P (fp16, single term)
            uint32_t pa[4];
            pa[0] = cvt_f16x2(e[0][0], e[0][1]);
            pa[1] = cvt_f16x2(e[0][2], e[0][3]);
            pa[2] = cvt_f16x2(e[1][0], e[1][1]);
            pa[3] = cvt_f16x2(e[1][2], e[1][3]);
            // O += P * (Vh + Vl)  (2 terms)
#pragma unroll
            for (int jp = 0; jp < 2; jp++) {
                uint32_t vh4[4], vl4[4];
                ldmx4(vh4, st + 5120 + voff + jp * 2304 + kt * 32);
                ldmx4(vl4, st + 9728 + voff + jp * 2304 + kt * 32);
                mma_f16(o[2 * jp + 0], pa, vh4[0], vh4[1]);
                mma_f16(o[2 * jp + 0], pa, vl4[0], vl4[1]);
                mma_f16(o[2 * jp + 1], pa, vh4[2], vh4[3]);
                mma_f16(o[2 * jp + 1], pa, vl4[2], vl4[3]);
            }
        }
        __syncthreads();
    }

    // epilogue: normalize + bf16-split store att [b][kb=h][tok][16]
    float inv[2];
#pragma unroll
    for (int rr = 0; rr < 2; rr++) {
        float lv = lsum[rr];
        lv += __shfl_xor_sync(0xffffffffu, lv, 1);
        lv += __shfl_xor_sync(0xffffffffu, lv, 2);
        inv[rr] = 1.f / lv;
    }

#pragma unroll
    for (int rr = 0; rr < 2; rr++) {
        int qrow = q0 + w * 16 + rr * 8 + t4;
        float iv = inv[rr];
#pragma unroll
        for (int j = 0; j < 4; j++) {
            float v0 = o[j][rr * 2 + 0] * iv;
            float v1 = o[j][rr * 2 + 1] * iv;
            uint32_t hw = cvt_bf16x2(v0, v1);
            uint32_t lw = cvt_bf16x2(v0 - bflo(hw), v1 - bfhi(hw));
            size_t gi = (((size_t)b * 4 + h) * NTOK + qrow) * 16 + j * 4 + tm4;
            g_ah[gi] = hw;
            g_al[gi] = lw;
        }
    }
}

// ---------------- launch ----------------
extern "C" void kernel_launch(void* const* d_in, const int* in_sizes, int n_in,
                              void* d_out, int out_size)
{
    const float* x     = (const float*)d_in[0];
    const float* w_qkv = (const float*)d_in[1];
    const float* w_out = (const float*)d_in[2];
    const float* b_out = (const float*)d_in[3];
    float* out = (float*)d_out;

    unsigned *wqh, *wql, *woh, *wol, *xth, *xtl, *ah, *al;
    cudaGetSymbolAddress((void**)&wqh, g_wqh);
    cudaGetSymbolAddress((void**)&wql, g_wql);
    cudaGetSymbolAddress((void**)&woh, g_woh);
    cudaGetSymbolAddress((void**)&wol, g_wol);
    cudaGetSymbolAddress((void**)&xth, g_xth);
    cudaGetSymbolAddress((void**)&xtl, g_xtl);
    cudaGetSymbolAddress((void**)&ah, g_ah);
    cudaGetSymbolAddress((void**)&al, g_al);

    static int smem_set = 0;
    if (!smem_set) {
        cudaFuncSetAttribute(gemm_hmma<0>, cudaFuncAttributeMaxDynamicSharedMemorySize,
                             2 * GST);
        cudaFuncSetAttribute(gemm_hmma<1>, cudaFuncAttributeMaxDynamicSharedMemorySize,
                             2 * GST);
        smem_set = 1;
    }

    prep_w<<<192, 256>>>(w_qkv, wqh, wql, 384, 128);
    prep_w<<<64, 256>>>(w_out, woh, wol, 256, 64);
    prep_x<<<dim3(NTOK / 32, 8, 8), 256>>>(x);

    // qkv GEMM with fused fp16 Q/K/V prep epilogue
    gemm_hmma<1><<<dim3(NTOK / 64, 3, 8), 128, 2 * GST>>>(
        wqh, wql, xth, xtl, nullptr, nullptr, 384, 8);

    attn_hmma<<<dim3(NTOK / 128, 4, 8), 256>>>();

    gemm_hmma<0><<<dim3(NTOK / 64, 2, 8), 128, 2 * GST>>>(
        woh, wol, ah, al, out, b_out, 256, 4);
}

// round 15
// speedup vs baseline: 4.1783x; 1.0093x over previous
#include <cuda_runtime.h>
#include <cuda_bf16.h>
#include <cstdint>

// Attention_9328668967755 — R15: R14 (fp16 2-term attn, interleaved MMA,
// 3-stage cp.async) with the ring-buffer race fixed:
// order is WAIT -> syncthreads -> issue next stage -> compute.
// b=8, c=256, n=2304, heads=4, d_head=32.

#define NTOK 2304
#define NT2  1152
#define QSCALE (0.17677669529663689f * 1.4426950408889634f)  // dim^-0.5 * log2(e)

__device__ unsigned g_qh[8 * 4 * NTOK * 16];   // Q hi (fp16x2), [bh][tok][16]
__device__ unsigned g_ql[8 * 4 * NTOK * 16];   // Q lo
__device__ unsigned g_kh[8 * 4 * NTOK * 16];   // K hi
__device__ unsigned g_vh[8 * 128 * NT2];       // V hi, [b*128+ch][NT2]
__device__ unsigned g_vl[8 * 128 * NT2];       // V lo
__device__ unsigned g_xth[8 * 8 * NTOK * 16];  // bf16 split, k-block tiled
__device__ unsigned g_xtl[8 * 8 * NTOK * 16];
__device__ unsigned g_ah[8 * 4 * NTOK * 16];
__device__ unsigned g_al[8 * 4 * NTOK * 16];
__device__ unsigned g_wqh[8 * 384 * 16];
__device__ unsigned g_wql[8 * 384 * 16];
__device__ unsigned g_woh[4 * 256 * 16];
__device__ unsigned g_wol[4 * 256 * 16];

// ---------------- helpers ----------------
__device__ __forceinline__ uint32_t cvt_bf16x2(float lo, float hi) {
    uint32_t r;
    asm("cvt.rn.satfinite.bf16x2.f32 %0, %1, %2;" : "=r"(r) : "f"(hi), "f"(lo));
    return r;
}
__device__ __forceinline__ float bflo(uint32_t u) { return __uint_as_float(u << 16); }
__device__ __forceinline__ float bfhi(uint32_t u) { return __uint_as_float(u & 0xffff0000u); }

__device__ __forceinline__ uint32_t cvt_f16x2(float lo, float hi) {
    uint32_t r;
    asm("cvt.rn.f16x2.f32 %0, %1, %2;" : "=r"(r) : "f"(hi), "f"(lo));
    return r;
}
__device__ __forceinline__ float f16lo(uint32_t u) {
    float f;
    asm("{ .reg .f16 l, h; mov.b32 {l, h}, %1; cvt.f32.f16 %0, l; }" : "=f"(f) : "r"(u));
    return f;
}
__device__ __forceinline__ float f16hi(uint32_t u) {
    float f;
    asm("{ .reg .f16 l, h; mov.b32 {l, h}, %1; cvt.f32.f16 %0, h; }" : "=f"(f) : "r"(u));
    return f;
}
__device__ __forceinline__ float ex2(float x) {
    float r;
    asm("ex2.approx.f32 %0, %1;" : "=f"(r) : "f"(x));
    return r;
}
__device__ __forceinline__ uint32_t smem_u32(const void* p) {
    uint32_t a;
    asm("{ .reg .u64 t; cvta.to.shared.u64 t, %1; cvt.u32.u64 %0, t; }" : "=r"(a) : "l"(p));
    return a;
}
// non-volatile — pure register math, scheduler may interleave freely.
__device__ __forceinline__ void mma_bf16(float* c, const uint32_t* a,
                                         uint32_t b0, uint32_t b1) {
    asm("mma.sync.aligned.m16n8k16.row.col.f32.bf16.bf16.f32 "
        "{%0,%1,%2,%3}, {%4,%5,%6,%7}, {%8,%9}, {%0,%1,%2,%3};"
        : "+f"(c[0]), "+f"(c[1]), "+f"(c[2]), "+f"(c[3])
        : "r"(a[0]), "r"(a[1]), "r"(a[2]), "r"(a[3]), "r"(b0), "r"(b1));
}
__device__ __forceinline__ void mma_f16(float* c, const uint32_t* a,
                                        uint32_t b0, uint32_t b1) {
    asm("mma.sync.aligned.m16n8k16.row.col.f32.f16.f16.f32 "
        "{%0,%1,%2,%3}, {%4,%5,%6,%7}, {%8,%9}, {%0,%1,%2,%3};"
        : "+f"(c[0]), "+f"(c[1]), "+f"(c[2]), "+f"(c[3])
        : "r"(a[0]), "r"(a[1]), "r"(a[2]), "r"(a[3]), "r"(b0), "r"(b1));
}
__device__ __forceinline__ void ldmx4(uint32_t* r, uint32_t addr) {
    asm volatile("ldmatrix.sync.aligned.m8n8.x4.shared.b16 {%0,%1,%2,%3}, [%4];"
                 : "=r"(r[0]), "=r"(r[1]), "=r"(r[2]), "=r"(r[3]) : "r"(addr));
}
#define CP_ASYNC(dst, src) \
    asm volatile("cp.async.cg.shared.global [%0], [%1], 16;" :: "r"(dst), "l"(src) : "memory")
#define CP_COMMIT asm volatile("cp.async.commit_group;" ::: "memory")
#define CP_WAIT1 asm volatile("cp.async.wait_group 1;" ::: "memory")
#define CP_WAIT0 asm volatile("cp.async.wait_group 0;" ::: "memory")

// ---------------- prep: weight split to [kb][M][16] (bf16) ----------------
__global__ __launch_bounds__(256)
void prep_w(const float* __restrict__ src, unsigned* __restrict__ dh,
            unsigned* __restrict__ dl, int M, int kws)
{
    int idx = blockIdx.x * 256 + threadIdx.x;
    if (idx >= M * kws) return;
    int m = idx / kws, kw = idx % kws;
    float2 s = *(const float2*)(src + (size_t)idx * 2);
    uint32_t hw = cvt_bf16x2(s.x, s.y);
    uint32_t lw = cvt_bf16x2(s.x - bflo(hw), s.y - bfhi(hw));
    size_t dst = ((size_t)(kw >> 4) * M + m) * 16 + (kw & 15);
    dh[dst] = hw;
    dl[dst] = lw;
}

// ---------------- prep: x transpose+split to [b][kb][tok][16] (bf16) ----------------
__global__ __launch_bounds__(256)
void prep_x(const float* __restrict__ x)
{
    __shared__ float ts[32][33];
    const int t = threadIdx.x;
    const int tok0 = blockIdx.x * 32;
    const int k0 = blockIdx.y * 32;
    const int b = blockIdx.z;

    {
        int r = t >> 3, c = (t & 7) * 4;
        float4 v = *(const float4*)(x + ((size_t)b * 256 + k0 + r) * NTOK + tok0 + c);
        ts[r][c + 0] = v.x; ts[r][c + 1] = v.y; ts[r][c + 2] = v.z; ts[r][c + 3] = v.w;
    }
    __syncthreads();

    int tok = t >> 3, kq = (t & 7) * 4;
    float f0 = ts[kq + 0][tok], f1 = ts[kq + 1][tok];
    float f2 = ts[kq + 2][tok], f3 = ts[kq + 3][tok];

    uint32_t h01 = cvt_bf16x2(f0, f1);
    uint32_t l01 = cvt_bf16x2(f0 - bflo(h01), f1 - bfhi(h01));
    uint32_t h23 = cvt_bf16x2(f2, f3);
    uint32_t l23 = cvt_bf16x2(f2 - bflo(h23), f3 - bfhi(h23));

    size_t gi = (((size_t)b * 8 + blockIdx.y) * NTOK + tok0 + tok) * 16 + kq / 2;
    g_xth[gi] = h01; g_xth[gi + 1] = h23;
    g_xtl[gi] = l01; g_xtl[gi + 1] = l23;
}

// ---------------- HMMA GEMM (bf16 3-term, cp.async 2-stage) ----------------
#define GST 30720
template <int MODE>
__global__ __launch_bounds__(128, 3)
void gemm_hmma(const unsigned* __restrict__ wh, const unsigned* __restrict__ wl,
               const unsigned* __restrict__ xh, const unsigned* __restrict__ xl,
               float* __restrict__ C, const float* __restrict__ bias,
               int M, int nkb)
{
    extern __shared__ __align__(16) unsigned char sm[];
    const int tid = threadIdx.x;
    const int w = tid >> 5, lane = tid & 31;
    const int t4 = lane >> 2, tm4 = lane & 3;
    const int nb = blockIdx.x * 64;
    const int mb = blockIdx.y * 128;
    const int bz = blockIdx.z;

    const uint32_t sb = smem_u32(sm);
    const uint32_t stW = (uint32_t)((tid >> 2) * 80 + (tid & 3) * 16);
    const uint32_t aoff = (uint32_t)((w * 32 + (lane & 7) + ((lane >> 3) & 1) * 8) * 80
                                     + (lane >> 4) * 16);
    const uint32_t boff = (uint32_t)(((lane & 7) + ((lane >> 4) & 1) * 8) * 80
                                     + ((lane >> 3) & 1) * 16);

    float o[2][8][4];
#pragma unroll
    for (int f = 0; f < 2; f++)
#pragma unroll
        for (int nf = 0; nf < 8; nf++)
#pragma unroll
            for (int r = 0; r < 4; r++) o[f][nf][r] = 0.f;

    auto load_stage = [&](int kb) {
        uint32_t st = sb + (kb & 1) * GST;
        const unsigned* gwh = wh + ((size_t)kb * M + mb) * 16 + tid * 4;
        const unsigned* gwl = wl + ((size_t)kb * M + mb) * 16 + tid * 4;
#pragma unroll
        for (int i = 0; i < 4; i++) {
            CP_ASYNC(st + stW + i * 2560, gwh + i * 512);
            CP_ASYNC(st + 10240 + stW + i * 2560, gwl + i * 512);
        }
        const unsigned* gxh = xh + (((size_t)bz * nkb + kb) * NTOK + nb) * 16 + tid * 4;
        const unsigned* gxl = xl + (((size_t)bz * nkb + kb) * NTOK + nb) * 16 + tid * 4;
#pragma unroll
        for (int i = 0; i < 2; i++) {
            CP_ASYNC(st + 20480 + stW + i * 2560, gxh + i * 512);
            CP_ASYNC(st + 25600 + stW + i * 2560, gxl + i * 512);
        }
        CP_COMMIT;
    };

    load_stage(0);
    for (int kb = 0; kb < nkb; kb++) {
        if (kb + 1 < nkb) { load_stage(kb + 1); CP_WAIT1; }
        else              { CP_WAIT0; }
        __syncthreads();
        const uint32_t st = sb + (kb & 1) * GST;

#pragma unroll
        for (int ks = 0; ks < 2; ks++) {
            uint32_t ah[2][4], al[2][4];
            ldmx4(ah[0], st + aoff + ks * 32);
            ldmx4(ah[1], st + aoff + 1280 + ks * 32);
            ldmx4(al[0], st + 10240 + aoff + ks * 32);
            ldmx4(al[1], st + 10240 + aoff + 1280 + ks * 32);

            uint32_t bh4[2][4], bl4[2][4];
            ldmx4(bh4[0], st + 20480 + boff + ks * 32);
            ldmx4(bl4[0], st + 25600 + boff + ks * 32);
#pragma unroll
            for (int p = 0; p < 4; p++) {
                if (p < 3) {
                    ldmx4(bh4[(p + 1) & 1], st + 20480 + boff + (p + 1) * 1280 + ks * 32);
                    ldmx4(bl4[(p + 1) & 1], st + 25600 + boff + (p + 1) * 1280 + ks * 32);
                }
                const uint32_t* bh = bh4[p & 1];
                const uint32_t* bl = bl4[p & 1];
                // per-acc term order preserved (ah*bh, ah*bl, al*bh); interleaved
                // across 4 independent accumulators (reuse distance 4).
                mma_bf16(o[0][2 * p + 0], ah[0], bh[0], bh[1]);
                mma_bf16(o[1][2 * p + 0], ah[1], bh[0], bh[1]);
                mma_bf16(o[0][2 * p + 1], ah[0], bh[2], bh[3]);
                mma_bf16(o[1][2 * p + 1], ah[1], bh[2], bh[3]);
                mma_bf16(o[0][2 * p + 0], ah[0], bl[0], bl[1]);
                mma_bf16(o[1][2 * p + 0], ah[1], bl[0], bl[1]);
                mma_bf16(o[0][2 * p + 1], ah[0], bl[2], bl[3]);
                mma_bf16(o[1][2 * p + 1], ah[1], bl[2], bl[3]);
                mma_bf16(o[0][2 * p + 0], al[0], bh[0], bh[1]);
                mma_bf16(o[1][2 * p + 0], al[1], bh[0], bh[1]);
                mma_bf16(o[0][2 * p + 1], al[0], bh[2], bh[3]);
                mma_bf16(o[1][2 * p + 1], al[1], bh[2], bh[3]);
            }
        }
        __syncthreads();
    }

    if (MODE == 0) {
        float* Cb = C + (size_t)bz * M * NTOK;
#pragma unroll
        for (int f = 0; f < 2; f++) {
            int row0 = mb + w * 32 + f * 16 + t4;
            int row1 = row0 + 8;
            float b0 = bias ? bias[row0] : 0.f;
            float b1 = bias ? bias[row1] : 0.f;
#pragma unroll
            for (int nf = 0; nf < 8; nf++) {
                int col = nb + nf * 8 + tm4 * 2;
                *(float2*)(Cb + (size_t)row0 * NTOK + col) =
                    make_float2(o[f][nf][0] + b0, o[f][nf][1] + b0);
                *(float2*)(Cb + (size_t)row1 * NTOK + col) =
                    make_float2(o[f][nf][2] + b1, o[f][nf][3] + b1);
            }
        }
    } else {
        if (blockIdx.y == 2) {
            // V: fp16 split, token pairs direct from fragments.
#pragma unroll
            for (int f = 0; f < 2; f++)
#pragma unroll
                for (int rr = 0; rr < 2; rr++) {
                    int row = w * 32 + f * 16 + rr * 8 + t4;   // channel
                    size_t vr = (size_t)(bz * 128 + row) * NT2;
#pragma unroll
                    for (int nf = 0; nf < 8; nf++) {
                        float v0 = o[f][nf][rr * 2 + 0];
                        float v1 = o[f][nf][rr * 2 + 1];
                        uint32_t hw = cvt_f16x2(v0, v1);
                        uint32_t lw = cvt_f16x2(v0 - f16lo(hw), v1 - f16hi(hw));
                        size_t tp = (size_t)(nb >> 1) + nf * 4 + tm4;
                        g_vh[vr + tp] = hw;
                        g_vl[vr + tp] = lw;
                    }
                }
        } else {
            // Q/K: transpose via smem, fp16 convert. Q: hi+lo (QSCALE); K: hi only.
            float* ts = (float*)sm;
#pragma unroll
            for (int f = 0; f < 2; f++)
#pragma unroll
                for (int nf = 0; nf < 8; nf++) {
                    int rowb = w * 32 + f * 16 + t4;
                    int colb = nf * 8 + tm4 * 2;
                    ts[(colb + 0) * 130 + rowb]     = o[f][nf][0];
                    ts[(colb + 1) * 130 + rowb]     = o[f][nf][1];
                    ts[(colb + 0) * 130 + rowb + 8] = o[f][nf][2];
                    ts[(colb + 1) * 130 + rowb + 8] = o[f][nf][3];
                }
            __syncthreads();

            const int isQ = (blockIdx.y == 0);
            const float sc = isQ ? QSCALE : 1.f;
            const int tok = tid >> 1, half = tid & 1;
            const float* trow = ts + tok * 130;
#pragma unroll
            for (int hd = 0; hd < 4; hd++) {
                uint32_t hw8[8], lw8[8];
#pragma unroll
                for (int wp = 0; wp < 8; wp++) {
                    int ch = hd * 32 + (half * 8 + wp) * 2;
                    float v0 = trow[ch] * sc;
                    float v1 = trow[ch + 1] * sc;
                    uint32_t hw = cvt_f16x2(v0, v1);
                    hw8[wp] = hw;
                    if (isQ) lw8[wp] = cvt_f16x2(v0 - f16lo(hw), v1 - f16hi(hw));
                }
                size_t gi = ((size_t)(bz * 4 + hd) * NTOK + nb + tok) * 16 + half * 8;
                unsigned* oh = isQ ? g_qh : g_kh;
                *(uint4*)(oh + gi)     = make_uint4(hw8[0], hw8[1], hw8[2], hw8[3]);
                *(uint4*)(oh + gi + 4) = make_uint4(hw8[4], hw8[5], hw8[6], hw8[7]);
                if (isQ) {
                    *(uint4*)(g_ql + gi)     = make_uint4(lw8[0], lw8[1], lw8[2], lw8[3]);
                    *(uint4*)(g_ql + gi + 4) = make_uint4(lw8[4], lw8[5], lw8[6], lw8[7]);
                }
            }
        }
    }
}

// ---------------- attention (fp16 2-term, 256 threads, 3-stage cp.async) --------
// stage: Kh@0 (64x80=5120), Vh@5120 (32x144=4608), Vl@9728; stride 14336
// Ring discipline: WAIT -> sync -> issue stage t+2 -> compute stage t.
// The sync proves all reads of stage (t-1)%3 == (t+2)%3 are done before overwrite.
#define AST 14336
__global__ __launch_bounds__(256, 2)
void attn_hmma()
{
    __shared__ __align__(16) unsigned char sm[3 * AST];

    const int tid = threadIdx.x;
    const int w = tid >> 5, lane = tid & 31;
    const int t4 = lane >> 2, tm4 = lane & 3;
    const int q0 = blockIdx.x * 128;
    const int h = blockIdx.y, b = blockIdx.z;
    const int bh = b * 4 + h;

    uint32_t qh[2][4], ql[2][4];
#pragma unroll
    for (int ks = 0; ks < 2; ks++)
#pragma unroll
        for (int r = 0; r < 4; r++) {
            int row = q0 + w * 16 + (r & 1) * 8 + t4;
            int word = ks * 8 + tm4 + (r >> 1) * 4;
            size_t gi = ((size_t)bh * NTOK + row) * 16 + word;
            qh[ks][r] = g_qh[gi];
            ql[ks][r] = g_ql[gi];
        }

    float o[4][4];
#pragma unroll
    for (int j = 0; j < 4; j++)
#pragma unroll
        for (int r = 0; r < 4; r++) o[j][r] = 0.f;
    float lsum[2] = {0.f, 0.f};

    const uint32_t sb = smem_u32(sm);
    const int ktok = tid >> 2, kq = tid & 3;
    const size_t kgbase = ((size_t)bh * NTOK + ktok) * 16 + kq * 4;
    const uint32_t kst = (uint32_t)(ktok * 80 + kq * 16);
    const int vd = tid >> 3, vc = tid & 7;
    const size_t vgbase = ((size_t)(b * 128 + h * 32 + vd)) * NT2 + vc * 4;
    const uint32_t vst = (uint32_t)(vd * 144 + vc * 16);

    const uint32_t koff = (uint32_t)((lane & 7) * 80 + (lane >> 3) * 16);
    const uint32_t voff = (uint32_t)(((lane & 7) + ((lane >> 4) & 1) * 8) * 144
                                     + ((lane >> 3) & 1) * 16);

    auto load_stage = [&](int t) {
        uint32_t st = sb + (t % 3) * AST;
        CP_ASYNC(st + kst, g_kh + kgbase + (size_t)t * 1024);
        CP_ASYNC(st + 5120 + vst, g_vh + vgbase + (size_t)t * 32);
        CP_ASYNC(st + 9728 + vst, g_vl + vgbase + (size_t)t * 32);
        CP_COMMIT;
    };

    load_stage(0);
    load_stage(1);
    for (int t = 0; t < 36; t++) {
        if (t + 1 < 36) { CP_WAIT1; } else { CP_WAIT0; }
        __syncthreads();
        if (t + 2 < 36) load_stage(t + 2);
        const uint32_t st = sb + (t % 3) * AST;

#pragma unroll
        for (int kt = 0; kt < 4; kt++) {
            // S = (Qh + Ql) * Kh for both 8-key ntiles, chains interleaved.
            uint32_t ka[4], kb4[4];
            ldmx4(ka, st + koff + (kt * 2 + 0) * 640);
            ldmx4(kb4, st + koff + (kt * 2 + 1) * 640);
            float ca[4] = {0.f, 0.f, 0.f, 0.f};
            float cb[4] = {0.f, 0.f, 0.f, 0.f};
            mma_f16(ca, qh[0], ka[0], ka[1]);
            mma_f16(cb, qh[0], kb4[0], kb4[1]);
            mma_f16(ca, ql[0], ka[0], ka[1]);
            mma_f16(cb, ql[0], kb4[0], kb4[1]);
            mma_f16(ca, qh[1], ka[2], ka[3]);
            mma_f16(cb, qh[1], kb4[2], kb4[3]);
            mma_f16(ca, ql[1], ka[2], ka[3]);
            mma_f16(cb, ql[1], kb4[2], kb4[3]);

            float ea0 = ex2(ca[0]), ea1 = ex2(ca[1]), ea2 = ex2(ca[2]), ea3 = ex2(ca[3]);
            float eb0 = ex2(cb[0]), eb1 = ex2(cb[1]), eb2 = ex2(cb[2]), eb3 = ex2(cb[3]);
            lsum[0] += ea0 + ea1 + eb0 + eb1;
            lsum[1] += ea2 + ea3 + eb2 + eb3;

            uint32_t pa[4];
            pa[0] = cvt_f16x2(ea0, ea1);
            pa[1] = cvt_f16x2(ea2, ea3);
            pa[2] = cvt_f16x2(eb0, eb1);
            pa[3] = cvt_f16x2(eb2, eb3);

            // O += P * (Vh + Vl), rotated across 4 accumulators (reuse distance 4).
            uint32_t vha[4], vhb[4], vla[4], vlb[4];
            ldmx4(vha, st + 5120 + voff + kt * 32);
            ldmx4(vhb, st + 5120 + voff + 2304 + kt * 32);
            ldmx4(vla, st + 9728 + voff + kt * 32);
            ldmx4(vlb, st + 9728 + voff + 2304 + kt * 32);
            mma_f16(o[0], pa, vha[0], vha[1]);
            mma_f16(o[1], pa, vha[2], vha[3]);
            mma_f16(o[2], pa, vhb[0], vhb[1]);
            mma_f16(o[3], pa, vhb[2], vhb[3]);
            mma_f16(o[0], pa, vla[0], vla[1]);
            mma_f16(o[1], pa, vla[2], vla[3]);
            mma_f16(o[2], pa, vlb[0], vlb[1]);
            mma_f16(o[3], pa, vlb[2], vlb[3]);
        }
    }

    // epilogue: normalize + bf16-split store att [b][kb=h][tok][16]
    float inv[2];
#pragma unroll
    for (int rr = 0; rr < 2; rr++) {
        float lv = lsum[rr];
        lv += __shfl_xor_sync(0xffffffffu, lv, 1);
        lv += __shfl_xor_sync(0xffffffffu, lv, 2);
        inv[rr] = 1.f / lv;
    }

#pragma unroll
    for (int rr = 0; rr < 2; rr++) {
        int qrow = q0 + w * 16 + rr * 8 + t4;
        float iv = inv[rr];
#pragma unroll
        for (int j = 0; j < 4; j++) {
            float v0 = o[j][rr * 2 + 0] * iv;
            float v1 = o[j][rr * 2 + 1] * iv;
            uint32_t hw = cvt_bf16x2(v0, v1);
            uint32_t lw = cvt_bf16x2(v0 - bflo(hw), v1 - bfhi(hw));
            size_t gi = (((size_t)b * 4 + h) * NTOK + qrow) * 16 + j * 4 + tm4;
            g_ah[gi] = hw;
            g_al[gi] = lw;
        }
    }
}

// ---------------- launch ----------------
extern "C" void kernel_launch(void* const* d_in, const int* in_sizes, int n_in,
                              void* d_out, int out_size)
{
    const float* x     = (const float*)d_in[0];
    const float* w_qkv = (const float*)d_in[1];
    const float* w_out = (const float*)d_in[2];
    const float* b_out = (const float*)d_in[3];
    float* out = (float*)d_out;

    unsigned *wqh, *wql, *woh, *wol, *xth, *xtl, *ah, *al;
    cudaGetSymbolAddress((void**)&wqh, g_wqh);
    cudaGetSymbolAddress((void**)&wql, g_wql);
    cudaGetSymbolAddress((void**)&woh, g_woh);
    cudaGetSymbolAddress((void**)&wol, g_wol);
    cudaGetSymbolAddress((void**)&xth, g_xth);
    cudaGetSymbolAddress((void**)&xtl, g_xtl);
    cudaGetSymbolAddress((void**)&ah, g_ah);
    cudaGetSymbolAddress((void**)&al, g_al);

    static int smem_set = 0;
    if (!smem_set) {
        cudaFuncSetAttribute(gemm_hmma<0>, cudaFuncAttributeMaxDynamicSharedMemorySize,
                             2 * GST);
        cudaFuncSetAttribute(gemm_hmma<1>, cudaFuncAttributeMaxDynamicSharedMemorySize,
                             2 * GST);
        smem_set = 1;
    }

    prep_w<<<192, 256>>>(w_qkv, wqh, wql, 384, 128);
    prep_w<<<64, 256>>>(w_out, woh, wol, 256, 64);
    prep_x<<<dim3(NTOK / 32, 8, 8), 256>>>(x);

    gemm_hmma<1><<<dim3(NTOK / 64, 3, 8), 128, 2 * GST>>>(
        wqh, wql, xth, xtl, nullptr, nullptr, 384, 8);

    attn_hmma<<<dim3(NTOK / 128, 4, 8), 256>>>();

    gemm_hmma<0><<<dim3(NTOK / 64, 2, 8), 128, 2 * GST>>>(
        woh, wol, ah, al, out, b_out, 256, 4);
}

// round 16
// speedup vs baseline: 4.8689x; 1.1653x over previous
#include <cuda_runtime.h>
#include <cuda_bf16.h>
#include <cstdint>

// Attention_9328668967755 — R16: drop the P·Vl term (V single fp16 term in PV).
// attn MMA count -25%, g_vl eliminated, smem stage 14336->9728.
// fp16 2-term S, fp16 P, bf16 3-term projections.
// b=8, c=256, n=2304, heads=4, d_head=32.

#define NTOK 2304
#define NT2  1152
#define QSCALE (0.17677669529663689f * 1.4426950408889634f)  // dim^-0.5 * log2(e)

__device__ unsigned g_qh[8 * 4 * NTOK * 16];   // Q hi (fp16x2), [bh][tok][16]
__device__ unsigned g_ql[8 * 4 * NTOK * 16];   // Q lo
__device__ unsigned g_kh[8 * 4 * NTOK * 16];   // K hi
__device__ unsigned g_vh[8 * 128 * NT2];       // V (fp16), [b*128+ch][NT2]
__device__ unsigned g_xth[8 * 8 * NTOK * 16];  // bf16 split, k-block tiled
__device__ unsigned g_xtl[8 * 8 * NTOK * 16];
__device__ unsigned g_ah[8 * 4 * NTOK * 16];
__device__ unsigned g_al[8 * 4 * NTOK * 16];
__device__ unsigned g_wqh[8 * 384 * 16];
__device__ unsigned g_wql[8 * 384 * 16];
__device__ unsigned g_woh[4 * 256 * 16];
__device__ unsigned g_wol[4 * 256 * 16];

// ---------------- helpers ----------------
__device__ __forceinline__ uint32_t cvt_bf16x2(float lo, float hi) {
    uint32_t r;
    asm("cvt.rn.satfinite.bf16x2.f32 %0, %1, %2;" : "=r"(r) : "f"(hi), "f"(lo));
    return r;
}
__device__ __forceinline__ float bflo(uint32_t u) { return __uint_as_float(u << 16); }
__device__ __forceinline__ float bfhi(uint32_t u) { return __uint_as_float(u & 0xffff0000u); }

__device__ __forceinline__ uint32_t cvt_f16x2(float lo, float hi) {
    uint32_t r;
    asm("cvt.rn.f16x2.f32 %0, %1, %2;" : "=r"(r) : "f"(hi), "f"(lo));
    return r;
}
__device__ __forceinline__ float f16lo(uint32_t u) {
    float f;
    asm("{ .reg .f16 l, h; mov.b32 {l, h}, %1; cvt.f32.f16 %0, l; }" : "=f"(f) : "r"(u));
    return f;
}
__device__ __forceinline__ float f16hi(uint32_t u) {
    float f;
    asm("{ .reg .f16 l, h; mov.b32 {l, h}, %1; cvt.f32.f16 %0, h; }" : "=f"(f) : "r"(u));
    return f;
}
__device__ __forceinline__ float ex2(float x) {
    float r;
    asm("ex2.approx.f32 %0, %1;" : "=f"(r) : "f"(x));
    return r;
}
__device__ __forceinline__ uint32_t smem_u32(const void* p) {
    uint32_t a;
    asm("{ .reg .u64 t; cvta.to.shared.u64 t, %1; cvt.u32.u64 %0, t; }" : "=r"(a) : "l"(p));
    return a;
}
__device__ __forceinline__ void mma_bf16(float* c, const uint32_t* a,
                                         uint32_t b0, uint32_t b1) {
    asm("mma.sync.aligned.m16n8k16.row.col.f32.bf16.bf16.f32 "
        "{%0,%1,%2,%3}, {%4,%5,%6,%7}, {%8,%9}, {%0,%1,%2,%3};"
        : "+f"(c[0]), "+f"(c[1]), "+f"(c[2]), "+f"(c[3])
        : "r"(a[0]), "r"(a[1]), "r"(a[2]), "r"(a[3]), "r"(b0), "r"(b1));
}
__device__ __forceinline__ void mma_f16(float* c, const uint32_t* a,
                                        uint32_t b0, uint32_t b1) {
    asm("mma.sync.aligned.m16n8k16.row.col.f32.f16.f16.f32 "
        "{%0,%1,%2,%3}, {%4,%5,%6,%7}, {%8,%9}, {%0,%1,%2,%3};"
        : "+f"(c[0]), "+f"(c[1]), "+f"(c[2]), "+f"(c[3])
        : "r"(a[0]), "r"(a[1]), "r"(a[2]), "r"(a[3]), "r"(b0), "r"(b1));
}
__device__ __forceinline__ void ldmx4(uint32_t* r, uint32_t addr) {
    asm volatile("ldmatrix.sync.aligned.m8n8.x4.shared.b16 {%0,%1,%2,%3}, [%4];"
                 : "=r"(r[0]), "=r"(r[1]), "=r"(r[2]), "=r"(r[3]) : "r"(addr));
}
#define CP_ASYNC(dst, src) \
    asm volatile("cp.async.cg.shared.global [%0], [%1], 16;" :: "r"(dst), "l"(src) : "memory")
#define CP_COMMIT asm volatile("cp.async.commit_group;" ::: "memory")
#define CP_WAIT1 asm volatile("cp.async.wait_group 1;" ::: "memory")
#define CP_WAIT0 asm volatile("cp.async.wait_group 0;" ::: "memory")

// ---------------- prep: weight split to [kb][M][16] (bf16) ----------------
__global__ __launch_bounds__(256)
void prep_w(const float* __restrict__ src, unsigned* __restrict__ dh,
            unsigned* __restrict__ dl, int M, int kws)
{
    int idx = blockIdx.x * 256 + threadIdx.x;
    if (idx >= M * kws) return;
    int m = idx / kws, kw = idx % kws;
    float2 s = *(const float2*)(src + (size_t)idx * 2);
    uint32_t hw = cvt_bf16x2(s.x, s.y);
    uint32_t lw = cvt_bf16x2(s.x - bflo(hw), s.y - bfhi(hw));
    size_t dst = ((size_t)(kw >> 4) * M + m) * 16 + (kw & 15);
    dh[dst] = hw;
    dl[dst] = lw;
}

// ---------------- prep: x transpose+split to [b][kb][tok][16] (bf16) ----------------
__global__ __launch_bounds__(256)
void prep_x(const float* __restrict__ x)
{
    __shared__ float ts[32][33];
    const int t = threadIdx.x;
    const int tok0 = blockIdx.x * 32;
    const int k0 = blockIdx.y * 32;
    const int b = blockIdx.z;

    {
        int r = t >> 3, c = (t & 7) * 4;
        float4 v = *(const float4*)(x + ((size_t)b * 256 + k0 + r) * NTOK + tok0 + c);
        ts[r][c + 0] = v.x; ts[r][c + 1] = v.y; ts[r][c + 2] = v.z; ts[r][c + 3] = v.w;
    }
    __syncthreads();

    int tok = t >> 3, kq = (t & 7) * 4;
    float f0 = ts[kq + 0][tok], f1 = ts[kq + 1][tok];
    float f2 = ts[kq + 2][tok], f3 = ts[kq + 3][tok];

    uint32_t h01 = cvt_bf16x2(f0, f1);
    uint32_t l01 = cvt_bf16x2(f0 - bflo(h01), f1 - bfhi(h01));
    uint32_t h23 = cvt_bf16x2(f2, f3);
    uint32_t l23 = cvt_bf16x2(f2 - bflo(h23), f3 - bfhi(h23));

    size_t gi = (((size_t)b * 8 + blockIdx.y) * NTOK + tok0 + tok) * 16 + kq / 2;
    g_xth[gi] = h01; g_xth[gi + 1] = h23;
    g_xtl[gi] = l01; g_xtl[gi + 1] = l23;
}

// ---------------- HMMA GEMM (bf16 3-term, cp.async 2-stage) ----------------
#define GST 30720
template <int MODE>
__global__ __launch_bounds__(128, 3)
void gemm_hmma(const unsigned* __restrict__ wh, const unsigned* __restrict__ wl,
               const unsigned* __restrict__ xh, const unsigned* __restrict__ xl,
               float* __restrict__ C, const float* __restrict__ bias,
               int M, int nkb)
{
    extern __shared__ __align__(16) unsigned char sm[];
    const int tid = threadIdx.x;
    const int w = tid >> 5, lane = tid & 31;
    const int t4 = lane >> 2, tm4 = lane & 3;
    const int nb = blockIdx.x * 64;
    const int mb = blockIdx.y * 128;
    const int bz = blockIdx.z;

    const uint32_t sb = smem_u32(sm);
    const uint32_t stW = (uint32_t)((tid >> 2) * 80 + (tid & 3) * 16);
    const uint32_t aoff = (uint32_t)((w * 32 + (lane & 7) + ((lane >> 3) & 1) * 8) * 80
                                     + (lane >> 4) * 16);
    const uint32_t boff = (uint32_t)(((lane & 7) + ((lane >> 4) & 1) * 8) * 80
                                     + ((lane >> 3) & 1) * 16);

    float o[2][8][4];
#pragma unroll
    for (int f = 0; f < 2; f++)
#pragma unroll
        for (int nf = 0; nf < 8; nf++)
#pragma unroll
            for (int r = 0; r < 4; r++) o[f][nf][r] = 0.f;

    auto load_stage = [&](int kb) {
        uint32_t st = sb + (kb & 1) * GST;
        const unsigned* gwh = wh + ((size_t)kb * M + mb) * 16 + tid * 4;
        const unsigned* gwl = wl + ((size_t)kb * M + mb) * 16 + tid * 4;
#pragma unroll
        for (int i = 0; i < 4; i++) {
            CP_ASYNC(st + stW + i * 2560, gwh + i * 512);
            CP_ASYNC(st + 10240 + stW + i * 2560, gwl + i * 512);
        }
        const unsigned* gxh = xh + (((size_t)bz * nkb + kb) * NTOK + nb) * 16 + tid * 4;
        const unsigned* gxl = xl + (((size_t)bz * nkb + kb) * NTOK + nb) * 16 + tid * 4;
#pragma unroll
        for (int i = 0; i < 2; i++) {
            CP_ASYNC(st + 20480 + stW + i * 2560, gxh + i * 512);
            CP_ASYNC(st + 25600 + stW + i * 2560, gxl + i * 512);
        }
        CP_COMMIT;
    };

    load_stage(0);
    for (int kb = 0; kb < nkb; kb++) {
        if (kb + 1 < nkb) { load_stage(kb + 1); CP_WAIT1; }
        else              { CP_WAIT0; }
        __syncthreads();
        const uint32_t st = sb + (kb & 1) * GST;

#pragma unroll
        for (int ks = 0; ks < 2; ks++) {
            uint32_t ah[2][4], al[2][4];
            ldmx4(ah[0], st + aoff + ks * 32);
            ldmx4(ah[1], st + aoff + 1280 + ks * 32);
            ldmx4(al[0], st + 10240 + aoff + ks * 32);
            ldmx4(al[1], st + 10240 + aoff + 1280 + ks * 32);

            uint32_t bh4[2][4], bl4[2][4];
            ldmx4(bh4[0], st + 20480 + boff + ks * 32);
            ldmx4(bl4[0], st + 25600 + boff + ks * 32);
#pragma unroll
            for (int p = 0; p < 4; p++) {
                if (p < 3) {
                    ldmx4(bh4[(p + 1) & 1], st + 20480 + boff + (p + 1) * 1280 + ks * 32);
                    ldmx4(bl4[(p + 1) & 1], st + 25600 + boff + (p + 1) * 1280 + ks * 32);
                }
                const uint32_t* bh = bh4[p & 1];
                const uint32_t* bl = bl4[p & 1];
                mma_bf16(o[0][2 * p + 0], ah[0], bh[0], bh[1]);
                mma_bf16(o[1][2 * p + 0], ah[1], bh[0], bh[1]);
                mma_bf16(o[0][2 * p + 1], ah[0], bh[2], bh[3]);
                mma_bf16(o[1][2 * p + 1], ah[1], bh[2], bh[3]);
                mma_bf16(o[0][2 * p + 0], ah[0], bl[0], bl[1]);
                mma_bf16(o[1][2 * p + 0], ah[1], bl[0], bl[1]);
                mma_bf16(o[0][2 * p + 1], ah[0], bl[2], bl[3]);
                mma_bf16(o[1][2 * p + 1], ah[1], bl[2], bl[3]);
                mma_bf16(o[0][2 * p + 0], al[0], bh[0], bh[1]);
                mma_bf16(o[1][2 * p + 0], al[1], bh[0], bh[1]);
                mma_bf16(o[0][2 * p + 1], al[0], bh[2], bh[3]);
                mma_bf16(o[1][2 * p + 1], al[1], bh[2], bh[3]);
            }
        }
        __syncthreads();
    }

    if (MODE == 0) {
        float* Cb = C + (size_t)bz * M * NTOK;
#pragma unroll
        for (int f = 0; f < 2; f++) {
            int row0 = mb + w * 32 + f * 16 + t4;
            int row1 = row0 + 8;
            float b0 = bias ? bias[row0] : 0.f;
            float b1 = bias ? bias[row1] : 0.f;
#pragma unroll
            for (int nf = 0; nf < 8; nf++) {
                int col = nb + nf * 8 + tm4 * 2;
                *(float2*)(Cb + (size_t)row0 * NTOK + col) =
                    make_float2(o[f][nf][0] + b0, o[f][nf][1] + b0);
                *(float2*)(Cb + (size_t)row1 * NTOK + col) =
                    make_float2(o[f][nf][2] + b1, o[f][nf][3] + b1);
            }
        }
    } else {
        if (blockIdx.y == 2) {
            // V: single fp16 value per element, token pairs direct from fragments.
#pragma unroll
            for (int f = 0; f < 2; f++)
#pragma unroll
                for (int rr = 0; rr < 2; rr++) {
                    int row = w * 32 + f * 16 + rr * 8 + t4;   // channel
                    size_t vr = (size_t)(bz * 128 + row) * NT2;
#pragma unroll
                    for (int nf = 0; nf < 8; nf++) {
                        float v0 = o[f][nf][rr * 2 + 0];
                        float v1 = o[f][nf][rr * 2 + 1];
                        size_t tp = (size_t)(nb >> 1) + nf * 4 + tm4;
                        g_vh[vr + tp] = cvt_f16x2(v0, v1);
                    }
                }
        } else {
            // Q/K: transpose via smem, fp16 convert. Q: hi+lo (QSCALE); K: hi only.
            float* ts = (float*)sm;
#pragma unroll
            for (int f = 0; f < 2; f++)
#pragma unroll
                for (int nf = 0; nf < 8; nf++) {
                    int rowb = w * 32 + f * 16 + t4;
                    int colb = nf * 8 + tm4 * 2;
                    ts[(colb + 0) * 130 + rowb]     = o[f][nf][0];
                    ts[(colb + 1) * 130 + rowb]     = o[f][nf][1];
                    ts[(colb + 0) * 130 + rowb + 8] = o[f][nf][2];
                    ts[(colb + 1) * 130 + rowb + 8] = o[f][nf][3];
                }
            __syncthreads();

            const int isQ = (blockIdx.y == 0);
            const float sc = isQ ? QSCALE : 1.f;
            const int tok = tid >> 1, half = tid & 1;
            const float* trow = ts + tok * 130;
#pragma unroll
            for (int hd = 0; hd < 4; hd++) {
                uint32_t hw8[8], lw8[8];
#pragma unroll
                for (int wp = 0; wp < 8; wp++) {
                    int ch = hd * 32 + (half * 8 + wp) * 2;
                    float v0 = trow[ch] * sc;
                    float v1 = trow[ch + 1] * sc;
                    uint32_t hw = cvt_f16x2(v0, v1);
                    hw8[wp] = hw;
                    if (isQ) lw8[wp] = cvt_f16x2(v0 - f16lo(hw), v1 - f16hi(hw));
                }
                size_t gi = ((size_t)(bz * 4 + hd) * NTOK + nb + tok) * 16 + half * 8;
                unsigned* oh = isQ ? g_qh : g_kh;
                *(uint4*)(oh + gi)     = make_uint4(hw8[0], hw8[1], hw8[2], hw8[3]);
                *(uint4*)(oh + gi + 4) = make_uint4(hw8[4], hw8[5], hw8[6], hw8[7]);
                if (isQ) {
                    *(uint4*)(g_ql + gi)     = make_uint4(lw8[0], lw8[1], lw8[2], lw8[3]);
                    *(uint4*)(g_ql + gi + 4) = make_uint4(lw8[4], lw8[5], lw8[6], lw8[7]);
                }
            }
        }
    }
}

// ---------------- attention (fp16: S 2-term, PV 1-term; 3-stage cp.async) -------
// stage: Kh@0 (64x80=5120), Vh@5120 (32x144=4608); stride 9728
// Ring discipline: WAIT -> sync -> issue stage t+2 -> compute stage t.
#define AST 9728
__global__ __launch_bounds__(256, 2)
void attn_hmma()
{
    __shared__ __align__(16) unsigned char sm[3 * AST];

    const int tid = threadIdx.x;
    const int w = tid >> 5, lane = tid & 31;
    const int t4 = lane >> 2, tm4 = lane & 3;
    const int q0 = blockIdx.x * 128;
    const int h = blockIdx.y, b = blockIdx.z;
    const int bh = b * 4 + h;

    uint32_t qh[2][4], ql[2][4];
#pragma unroll
    for (int ks = 0; ks < 2; ks++)
#pragma unroll
        for (int r = 0; r < 4; r++) {
            int row = q0 + w * 16 + (r & 1) * 8 + t4;
            int word = ks * 8 + tm4 + (r >> 1) * 4;
            size_t gi = ((size_t)bh * NTOK + row) * 16 + word;
            qh[ks][r] = g_qh[gi];
            ql[ks][r] = g_ql[gi];
        }

    float o[4][4];
#pragma unroll
    for (int j = 0; j < 4; j++)
#pragma unroll
        for (int r = 0; r < 4; r++) o[j][r] = 0.f;
    float lsum[2] = {0.f, 0.f};

    const uint32_t sb = smem_u32(sm);
    const int ktok = tid >> 2, kq = tid & 3;
    const size_t kgbase = ((size_t)bh * NTOK + ktok) * 16 + kq * 4;
    const uint32_t kst = (uint32_t)(ktok * 80 + kq * 16);
    const int vd = tid >> 3, vc = tid & 7;
    const size_t vgbase = ((size_t)(b * 128 + h * 32 + vd)) * NT2 + vc * 4;
    const uint32_t vst = (uint32_t)(vd * 144 + vc * 16);

    const uint32_t koff = (uint32_t)((lane & 7) * 80 + (lane >> 3) * 16);
    const uint32_t voff = (uint32_t)(((lane & 7) + ((lane >> 4) & 1) * 8) * 144
                                     + ((lane >> 3) & 1) * 16);

    auto load_stage = [&](int t) {
        uint32_t st = sb + (t % 3) * AST;
        CP_ASYNC(st + kst, g_kh + kgbase + (size_t)t * 1024);
        CP_ASYNC(st + 5120 + vst, g_vh + vgbase + (size_t)t * 32);
        CP_COMMIT;
    };

    load_stage(0);
    load_stage(1);
    for (int t = 0; t < 36; t++) {
        if (t + 1 < 36) { CP_WAIT1; } else { CP_WAIT0; }
        __syncthreads();
        if (t + 2 < 36) load_stage(t + 2);
        const uint32_t st = sb + (t % 3) * AST;

#pragma unroll
        for (int kt = 0; kt < 4; kt++) {
            // S = (Qh + Ql) * Kh for both 8-key ntiles, chains interleaved.
            uint32_t ka[4], kb4[4];
            ldmx4(ka, st + koff + (kt * 2 + 0) * 640);
            ldmx4(kb4, st + koff + (kt * 2 + 1) * 640);
            float ca[4] = {0.f, 0.f, 0.f, 0.f};
            float cb[4] = {0.f, 0.f, 0.f, 0.f};
            mma_f16(ca, qh[0], ka[0], ka[1]);
            mma_f16(cb, qh[0], kb4[0], kb4[1]);
            mma_f16(ca, ql[0], ka[0], ka[1]);
            mma_f16(cb, ql[0], kb4[0], kb4[1]);
            mma_f16(ca, qh[1], ka[2], ka[3]);
            mma_f16(cb, qh[1], kb4[2], kb4[3]);
            mma_f16(ca, ql[1], ka[2], ka[3]);
            mma_f16(cb, ql[1], kb4[2], kb4[3]);

            float ea0 = ex2(ca[0]), ea1 = ex2(ca[1]), ea2 = ex2(ca[2]), ea3 = ex2(ca[3]);
            float eb0 = ex2(cb[0]), eb1 = ex2(cb[1]), eb2 = ex2(cb[2]), eb3 = ex2(cb[3]);
            lsum[0] += ea0 + ea1 + eb0 + eb1;
            lsum[1] += ea2 + ea3 + eb2 + eb3;

            uint32_t pa[4];
            pa[0] = cvt_f16x2(ea0, ea1);
            pa[1] = cvt_f16x2(ea2, ea3);
            pa[2] = cvt_f16x2(eb0, eb1);
            pa[3] = cvt_f16x2(eb2, eb3);

            // O += P * Vh (single term), 4 independent accumulators.
            uint32_t vha[4], vhb[4];
            ldmx4(vha, st + 5120 + voff + kt * 32);
            ldmx4(vhb, st + 5120 + voff + 2304 + kt * 32);
            mma_f16(o[0], pa, vha[0], vha[1]);
            mma_f16(o[1], pa, vha[2], vha[3]);
            mma_f16(o[2], pa, vhb[0], vhb[1]);
            mma_f16(o[3], pa, vhb[2], vhb[3]);
        }
    }

    // epilogue: normalize + bf16-split store att [b][kb=h][tok][16]
    float inv[2];
#pragma unroll
    for (int rr = 0; rr < 2; rr++) {
        float lv = lsum[rr];
        lv += __shfl_xor_sync(0xffffffffu, lv, 1);
        lv += __shfl_xor_sync(0xffffffffu, lv, 2);
        inv[rr] = 1.f / lv;
    }

#pragma unroll
    for (int rr = 0; rr < 2; rr++) {
        int qrow = q0 + w * 16 + rr * 8 + t4;
        float iv = inv[rr];
#pragma unroll
        for (int j = 0; j < 4; j++) {
            float v0 = o[j][rr * 2 + 0] * iv;
            float v1 = o[j][rr * 2 + 1] * iv;
            uint32_t hw = cvt_bf16x2(v0, v1);
            uint32_t lw = cvt_bf16x2(v0 - bflo(hw), v1 - bfhi(hw));
            size_t gi = (((size_t)b * 4 + h) * NTOK + qrow) * 16 + j * 4 + tm4;
            g_ah[gi] = hw;
            g_al[gi] = lw;
        }
    }
}

// ---------------- launch ----------------
extern "C" void kernel_launch(void* const* d_in, const int* in_sizes, int n_in,
                              void* d_out, int out_size)
{
    const float* x     = (const float*)d_in[0];
    const float* w_qkv = (const float*)d_in[1];
    const float* w_out = (const float*)d_in[2];
    const float* b_out = (const float*)d_in[3];
    float* out = (float*)d_out;

    unsigned *wqh, *wql, *woh, *wol, *xth, *xtl, *ah, *al;
    cudaGetSymbolAddress((void**)&wqh, g_wqh);
    cudaGetSymbolAddress((void**)&wql, g_wql);
    cudaGetSymbolAddress((void**)&woh, g_woh);
    cudaGetSymbolAddress((void**)&wol, g_wol);
    cudaGetSymbolAddress((void**)&xth, g_xth);
    cudaGetSymbolAddress((void**)&xtl, g_xtl);
    cudaGetSymbolAddress((void**)&ah, g_ah);
    cudaGetSymbolAddress((void**)&al, g_al);

    static int smem_set = 0;
    if (!smem_set) {
        cudaFuncSetAttribute(gemm_hmma<0>, cudaFuncAttributeMaxDynamicSharedMemorySize,
                             2 * GST);
        cudaFuncSetAttribute(gemm_hmma<1>, cudaFuncAttributeMaxDynamicSharedMemorySize,
                             2 * GST);
        smem_set = 1;
    }

    prep_w<<<192, 256>>>(w_qkv, wqh, wql, 384, 128);
    prep_w<<<64, 256>>>(w_out, woh, wol, 256, 64);
    prep_x<<<dim3(NTOK / 32, 8, 8), 256>>>(x);

    gemm_hmma<1><<<dim3(NTOK / 64, 3, 8), 128, 2 * GST>>>(
        wqh, wql, xth, xtl, nullptr, nullptr, 384, 8);

    attn_hmma<<<dim3(NTOK / 128, 4, 8), 256>>>();

    gemm_hmma<0><<<dim3(NTOK / 64, 2, 8), 128, 2 * GST>>>(
        woh, wol, ah, al, out, b_out, 256, 4);
}

// round 17
// speedup vs baseline: 6.2641x; 1.2866x over previous
#include <cuda_runtime.h>
#include <cuda_bf16.h>
#include <cstdint>

// Attention_9328668967755 — R17: plain fp16 attention (S=Q·K, PV=P·V single
// terms), fp16 2-term projections (W=hi+lo fp16, activations single fp16).
// b=8, c=256, n=2304, heads=4, d_head=32.

#define NTOK 2304
#define NT2  1152
#define QSCALE (0.17677669529663689f * 1.4426950408889634f)  // dim^-0.5 * log2(e)

__device__ unsigned g_qh[8 * 4 * NTOK * 16];   // Q (fp16x2, scaled), [bh][tok][16]
__device__ unsigned g_kh[8 * 4 * NTOK * 16];   // K (fp16x2)
__device__ unsigned g_vh[8 * 128 * NT2];       // V (fp16x2), [b*128+ch][NT2]
__device__ unsigned g_xth[8 * 8 * NTOK * 16];  // x^T fp16, k-block tiled
__device__ unsigned g_ah[8 * 4 * NTOK * 16];   // att fp16, k-block tiled
__device__ unsigned g_wqh[8 * 384 * 16];       // w_qkv fp16 hi, [kb][M][16]
__device__ unsigned g_wql[8 * 384 * 16];       // w_qkv fp16 lo (residual)
__device__ unsigned g_woh[4 * 256 * 16];
__device__ unsigned g_wol[4 * 256 * 16];

// ---------------- helpers ----------------
__device__ __forceinline__ uint32_t cvt_bf16x2(float lo, float hi) {
    uint32_t r;
    asm("cvt.rn.satfinite.bf16x2.f32 %0, %1, %2;" : "=r"(r) : "f"(hi), "f"(lo));
    return r;
}
__device__ __forceinline__ uint32_t cvt_f16x2(float lo, float hi) {
    uint32_t r;
    asm("cvt.rn.f16x2.f32 %0, %1, %2;" : "=r"(r) : "f"(hi), "f"(lo));
    return r;
}
__device__ __forceinline__ float f16lo(uint32_t u) {
    float f;
    asm("{ .reg .f16 l, h; mov.b32 {l, h}, %1; cvt.f32.f16 %0, l; }" : "=f"(f) : "r"(u));
    return f;
}
__device__ __forceinline__ float f16hi(uint32_t u) {
    float f;
    asm("{ .reg .f16 l, h; mov.b32 {l, h}, %1; cvt.f32.f16 %0, h; }" : "=f"(f) : "r"(u));
    return f;
}
__device__ __forceinline__ float ex2(float x) {
    float r;
    asm("ex2.approx.f32 %0, %1;" : "=f"(r) : "f"(x));
    return r;
}
__device__ __forceinline__ uint32_t smem_u32(const void* p) {
    uint32_t a;
    asm("{ .reg .u64 t; cvta.to.shared.u64 t, %1; cvt.u32.u64 %0, t; }" : "=r"(a) : "l"(p));
    return a;
}
__device__ __forceinline__ void mma_f16(float* c, const uint32_t* a,
                                        uint32_t b0, uint32_t b1) {
    asm("mma.sync.aligned.m16n8k16.row.col.f32.f16.f16.f32 "
        "{%0,%1,%2,%3}, {%4,%5,%6,%7}, {%8,%9}, {%0,%1,%2,%3};"
        : "+f"(c[0]), "+f"(c[1]), "+f"(c[2]), "+f"(c[3])
        : "r"(a[0]), "r"(a[1]), "r"(a[2]), "r"(a[3]), "r"(b0), "r"(b1));
}
__device__ __forceinline__ void ldmx4(uint32_t* r, uint32_t addr) {
    asm volatile("ldmatrix.sync.aligned.m8n8.x4.shared.b16 {%0,%1,%2,%3}, [%4];"
                 : "=r"(r[0]), "=r"(r[1]), "=r"(r[2]), "=r"(r[3]) : "r"(addr));
}
#define CP_ASYNC(dst, src) \
    asm volatile("cp.async.cg.shared.global [%0], [%1], 16;" :: "r"(dst), "l"(src) : "memory")
#define CP_COMMIT asm volatile("cp.async.commit_group;" ::: "memory")
#define CP_WAIT1 asm volatile("cp.async.wait_group 1;" ::: "memory")
#define CP_WAIT0 asm volatile("cp.async.wait_group 0;" ::: "memory")

// ---------------- prep: weight fp16 split to [kb][M][16] ----------------
__global__ __launch_bounds__(256)
void prep_w(const float* __restrict__ src, unsigned* __restrict__ dh,
            unsigned* __restrict__ dl, int M, int kws)
{
    int idx = blockIdx.x * 256 + threadIdx.x;
    if (idx >= M * kws) return;
    int m = idx / kws, kw = idx % kws;
    float2 s = *(const float2*)(src + (size_t)idx * 2);
    uint32_t hw = cvt_f16x2(s.x, s.y);
    uint32_t lw = cvt_f16x2(s.x - f16lo(hw), s.y - f16hi(hw));
    size_t dst = ((size_t)(kw >> 4) * M + m) * 16 + (kw & 15);
    dh[dst] = hw;
    dl[dst] = lw;
}

// ---------------- prep: x transpose -> fp16 [b][kb][tok][16] ----------------
__global__ __launch_bounds__(256)
void prep_x(const float* __restrict__ x)
{
    __shared__ float ts[32][33];
    const int t = threadIdx.x;
    const int tok0 = blockIdx.x * 32;
    const int k0 = blockIdx.y * 32;
    const int b = blockIdx.z;

    {
        int r = t >> 3, c = (t & 7) * 4;
        float4 v = *(const float4*)(x + ((size_t)b * 256 + k0 + r) * NTOK + tok0 + c);
        ts[r][c + 0] = v.x; ts[r][c + 1] = v.y; ts[r][c + 2] = v.z; ts[r][c + 3] = v.w;
    }
    __syncthreads();

    int tok = t >> 3, kq = (t & 7) * 4;
    float f0 = ts[kq + 0][tok], f1 = ts[kq + 1][tok];
    float f2 = ts[kq + 2][tok], f3 = ts[kq + 3][tok];

    size_t gi = (((size_t)b * 8 + blockIdx.y) * NTOK + tok0 + tok) * 16 + kq / 2;
    g_xth[gi] = cvt_f16x2(f0, f1);
    g_xth[gi + 1] = cvt_f16x2(f2, f3);
}

// ---------------- HMMA GEMM (fp16 2-term W, single-term X) ----------------
// stage: Wh@0 (10240), Wl@10240 (10240), X@20480 (5120); stride 25600
#define GST 25600
template <int MODE>
__global__ __launch_bounds__(128, 3)
void gemm_hmma(const unsigned* __restrict__ wh, const unsigned* __restrict__ wl,
               const unsigned* __restrict__ xh,
               float* __restrict__ C, const float* __restrict__ bias,
               int M, int nkb)
{
    extern __shared__ __align__(16) unsigned char sm[];
    const int tid = threadIdx.x;
    const int w = tid >> 5, lane = tid & 31;
    const int t4 = lane >> 2, tm4 = lane & 3;
    const int nb = blockIdx.x * 64;
    const int mb = blockIdx.y * 128;
    const int bz = blockIdx.z;

    const uint32_t sb = smem_u32(sm);
    const uint32_t stW = (uint32_t)((tid >> 2) * 80 + (tid & 3) * 16);
    const uint32_t aoff = (uint32_t)((w * 32 + (lane & 7) + ((lane >> 3) & 1) * 8) * 80
                                     + (lane >> 4) * 16);
    const uint32_t boff = (uint32_t)(((lane & 7) + ((lane >> 4) & 1) * 8) * 80
                                     + ((lane >> 3) & 1) * 16);

    float o[2][8][4];
#pragma unroll
    for (int f = 0; f < 2; f++)
#pragma unroll
        for (int nf = 0; nf < 8; nf++)
#pragma unroll
            for (int r = 0; r < 4; r++) o[f][nf][r] = 0.f;

    auto load_stage = [&](int kb) {
        uint32_t st = sb + (kb & 1) * GST;
        const unsigned* gwh = wh + ((size_t)kb * M + mb) * 16 + tid * 4;
        const unsigned* gwl = wl + ((size_t)kb * M + mb) * 16 + tid * 4;
#pragma unroll
        for (int i = 0; i < 4; i++) {
            CP_ASYNC(st + stW + i * 2560, gwh + i * 512);
            CP_ASYNC(st + 10240 + stW + i * 2560, gwl + i * 512);
        }
        const unsigned* gx = xh + (((size_t)bz * nkb + kb) * NTOK + nb) * 16 + tid * 4;
#pragma unroll
        for (int i = 0; i < 2; i++)
            CP_ASYNC(st + 20480 + stW + i * 2560, gx + i * 512);
        CP_COMMIT;
    };

    load_stage(0);
    for (int kb = 0; kb < nkb; kb++) {
        if (kb + 1 < nkb) { load_stage(kb + 1); CP_WAIT1; }
        else              { CP_WAIT0; }
        __syncthreads();
        const uint32_t st = sb + (kb & 1) * GST;

#pragma unroll
        for (int ks = 0; ks < 2; ks++) {
            uint32_t ah[2][4], al[2][4];
            ldmx4(ah[0], st + aoff + ks * 32);
            ldmx4(ah[1], st + aoff + 1280 + ks * 32);
            ldmx4(al[0], st + 10240 + aoff + ks * 32);
            ldmx4(al[1], st + 10240 + aoff + 1280 + ks * 32);

            uint32_t b4[2][4];
            ldmx4(b4[0], st + 20480 + boff + ks * 32);
#pragma unroll
            for (int p = 0; p < 4; p++) {
                if (p < 3)
                    ldmx4(b4[(p + 1) & 1], st + 20480 + boff + (p + 1) * 1280 + ks * 32);
                const uint32_t* bb = b4[p & 1];
                mma_f16(o[0][2 * p + 0], ah[0], bb[0], bb[1]);
                mma_f16(o[1][2 * p + 0], ah[1], bb[0], bb[1]);
                mma_f16(o[0][2 * p + 1], ah[0], bb[2], bb[3]);
                mma_f16(o[1][2 * p + 1], ah[1], bb[2], bb[3]);
                mma_f16(o[0][2 * p + 0], al[0], bb[0], bb[1]);
                mma_f16(o[1][2 * p + 0], al[1], bb[0], bb[1]);
                mma_f16(o[0][2 * p + 1], al[0], bb[2], bb[3]);
                mma_f16(o[1][2 * p + 1], al[1], bb[2], bb[3]);
            }
        }
        __syncthreads();
    }

    if (MODE == 0) {
        float* Cb = C + (size_t)bz * M * NTOK;
#pragma unroll
        for (int f = 0; f < 2; f++) {
            int row0 = mb + w * 32 + f * 16 + t4;
            int row1 = row0 + 8;
            float b0 = bias ? bias[row0] : 0.f;
            float b1 = bias ? bias[row1] : 0.f;
#pragma unroll
            for (int nf = 0; nf < 8; nf++) {
                int col = nb + nf * 8 + tm4 * 2;
                *(float2*)(Cb + (size_t)row0 * NTOK + col) =
                    make_float2(o[f][nf][0] + b0, o[f][nf][1] + b0);
                *(float2*)(Cb + (size_t)row1 * NTOK + col) =
                    make_float2(o[f][nf][2] + b1, o[f][nf][3] + b1);
            }
        }
    } else {
        if (blockIdx.y == 2) {
            // V: fp16, token pairs direct from fragments.
#pragma unroll
            for (int f = 0; f < 2; f++)
#pragma unroll
                for (int rr = 0; rr < 2; rr++) {
                    int row = w * 32 + f * 16 + rr * 8 + t4;   // channel
                    size_t vr = (size_t)(bz * 128 + row) * NT2;
#pragma unroll
                    for (int nf = 0; nf < 8; nf++) {
                        size_t tp = (size_t)(nb >> 1) + nf * 4 + tm4;
                        g_vh[vr + tp] = cvt_f16x2(o[f][nf][rr * 2 + 0],
                                                  o[f][nf][rr * 2 + 1]);
                    }
                }
        } else {
            // Q/K: transpose via smem, fp16 single convert (Q scaled by QSCALE).
            float* ts = (float*)sm;
#pragma unroll
            for (int f = 0; f < 2; f++)
#pragma unroll
                for (int nf = 0; nf < 8; nf++) {
                    int rowb = w * 32 + f * 16 + t4;
                    int colb = nf * 8 + tm4 * 2;
                    ts[(colb + 0) * 130 + rowb]     = o[f][nf][0];
                    ts[(colb + 1) * 130 + rowb]     = o[f][nf][1];
                    ts[(colb + 0) * 130 + rowb + 8] = o[f][nf][2];
                    ts[(colb + 1) * 130 + rowb + 8] = o[f][nf][3];
                }
            __syncthreads();

            const int isQ = (blockIdx.y == 0);
            const float sc = isQ ? QSCALE : 1.f;
            unsigned* oh = isQ ? g_qh : g_kh;
            const int tok = tid >> 1, half = tid & 1;
            const float* trow = ts + tok * 130;
#pragma unroll
            for (int hd = 0; hd < 4; hd++) {
                uint32_t hw8[8];
#pragma unroll
                for (int wp = 0; wp < 8; wp++) {
                    int ch = hd * 32 + (half * 8 + wp) * 2;
                    hw8[wp] = cvt_f16x2(trow[ch] * sc, trow[ch + 1] * sc);
                }
                size_t gi = ((size_t)(bz * 4 + hd) * NTOK + nb + tok) * 16 + half * 8;
                *(uint4*)(oh + gi)     = make_uint4(hw8[0], hw8[1], hw8[2], hw8[3]);
                *(uint4*)(oh + gi + 4) = make_uint4(hw8[4], hw8[5], hw8[6], hw8[7]);
            }
        }
    }
}

// ---------------- attention (plain fp16, 3-stage cp.async) ----------------
// stage: K@0 (64x80=5120), V@5120 (32x144=4608); stride 9728
// Ring discipline: WAIT -> sync -> issue stage t+2 -> compute stage t.
#define AST 9728
__global__ __launch_bounds__(256, 2)
void attn_hmma()
{
    __shared__ __align__(16) unsigned char sm[3 * AST];

    const int tid = threadIdx.x;
    const int w = tid >> 5, lane = tid & 31;
    const int t4 = lane >> 2, tm4 = lane & 3;
    const int q0 = blockIdx.x * 128;
    const int h = blockIdx.y, b = blockIdx.z;
    const int bh = b * 4 + h;

    uint32_t qh[2][4];
#pragma unroll
    for (int ks = 0; ks < 2; ks++)
#pragma unroll
        for (int r = 0; r < 4; r++) {
            int row = q0 + w * 16 + (r & 1) * 8 + t4;
            int word = ks * 8 + tm4 + (r >> 1) * 4;
            qh[ks][r] = g_qh[((size_t)bh * NTOK + row) * 16 + word];
        }

    float o[4][4];
#pragma unroll
    for (int j = 0; j < 4; j++)
#pragma unroll
        for (int r = 0; r < 4; r++) o[j][r] = 0.f;
    float lsum[2] = {0.f, 0.f};

    const uint32_t sb = smem_u32(sm);
    const int ktok = tid >> 2, kq = tid & 3;
    const size_t kgbase = ((size_t)bh * NTOK + ktok) * 16 + kq * 4;
    const uint32_t kst = (uint32_t)(ktok * 80 + kq * 16);
    const int vd = tid >> 3, vc = tid & 7;
    const size_t vgbase = ((size_t)(b * 128 + h * 32 + vd)) * NT2 + vc * 4;
    const uint32_t vst = (uint32_t)(vd * 144 + vc * 16);

    const uint32_t koff = (uint32_t)((lane & 7) * 80 + (lane >> 3) * 16);
    const uint32_t voff = (uint32_t)(((lane & 7) + ((lane >> 4) & 1) * 8) * 144
                                     + ((lane >> 3) & 1) * 16);

    auto load_stage = [&](int t) {
        uint32_t st = sb + (t % 3) * AST;
        CP_ASYNC(st + kst, g_kh + kgbase + (size_t)t * 1024);
        CP_ASYNC(st + 5120 + vst, g_vh + vgbase + (size_t)t * 32);
        CP_COMMIT;
    };

    load_stage(0);
    load_stage(1);
    for (int t = 0; t < 36; t++) {
        if (t + 1 < 36) { CP_WAIT1; } else { CP_WAIT0; }
        __syncthreads();
        if (t + 2 < 36) load_stage(t + 2);
        const uint32_t st = sb + (t % 3) * AST;

#pragma unroll
        for (int kt = 0; kt < 4; kt++) {
            // S = Q·K for both 8-key ntiles (single fp16 term).
            uint32_t ka[4], kb4[4];
            ldmx4(ka, st + koff + (kt * 2 + 0) * 640);
            ldmx4(kb4, st + koff + (kt * 2 + 1) * 640);
            float ca[4] = {0.f, 0.f, 0.f, 0.f};
            float cb[4] = {0.f, 0.f, 0.f, 0.f};
            mma_f16(ca, qh[0], ka[0], ka[1]);
            mma_f16(cb, qh[0], kb4[0], kb4[1]);
            mma_f16(ca, qh[1], ka[2], ka[3]);
            mma_f16(cb, qh[1], kb4[2], kb4[3]);

            float ea0 = ex2(ca[0]), ea1 = ex2(ca[1]), ea2 = ex2(ca[2]), ea3 = ex2(ca[3]);
            float eb0 = ex2(cb[0]), eb1 = ex2(cb[1]), eb2 = ex2(cb[2]), eb3 = ex2(cb[3]);
            lsum[0] += ea0 + ea1 + eb0 + eb1;
            lsum[1] += ea2 + ea3 + eb2 + eb3;

            uint32_t pa[4];
            pa[0] = cvt_f16x2(ea0, ea1);
            pa[1] = cvt_f16x2(ea2, ea3);
            pa[2] = cvt_f16x2(eb0, eb1);
            pa[3] = cvt_f16x2(eb2, eb3);

            // O += P·V (single term), 4 independent accumulators.
            uint32_t vha[4], vhb[4];
            ldmx4(vha, st + 5120 + voff + kt * 32);
            ldmx4(vhb, st + 5120 + voff + 2304 + kt * 32);
            mma_f16(o[0], pa, vha[0], vha[1]);
            mma_f16(o[1], pa, vha[2], vha[3]);
            mma_f16(o[2], pa, vhb[0], vhb[1]);
            mma_f16(o[3], pa, vhb[2], vhb[3]);
        }
    }

    // epilogue: normalize + fp16 store att [b][kb=h][tok][16]
    float inv[2];
#pragma unroll
    for (int rr = 0; rr < 2; rr++) {
        float lv = lsum[rr];
        lv += __shfl_xor_sync(0xffffffffu, lv, 1);
        lv += __shfl_xor_sync(0xffffffffu, lv, 2);
        inv[rr] = 1.f / lv;
    }

#pragma unroll
    for (int rr = 0; rr < 2; rr++) {
        int qrow = q0 + w * 16 + rr * 8 + t4;
        float iv = inv[rr];
#pragma unroll
        for (int j = 0; j < 4; j++) {
            size_t gi = (((size_t)b * 4 + h) * NTOK + qrow) * 16 + j * 4 + tm4;
            g_ah[gi] = cvt_f16x2(o[j][rr * 2 + 0] * iv, o[j][rr * 2 + 1] * iv);
        }
    }
}

// ---------------- launch ----------------
extern "C" void kernel_launch(void* const* d_in, const int* in_sizes, int n_in,
                              void* d_out, int out_size)
{
    const float* x     = (const float*)d_in[0];
    const float* w_qkv = (const float*)d_in[1];
    const float* w_out = (const float*)d_in[2];
    const float* b_out = (const float*)d_in[3];
    float* out = (float*)d_out;

    unsigned *wqh, *wql, *woh, *wol, *xth, *ah;
    cudaGetSymbolAddress((void**)&wqh, g_wqh);
    cudaGetSymbolAddress((void**)&wql, g_wql);
    cudaGetSymbolAddress((void**)&woh, g_woh);
    cudaGetSymbolAddress((void**)&wol, g_wol);
    cudaGetSymbolAddress((void**)&xth, g_xth);
    cudaGetSymbolAddress((void**)&ah, g_ah);

    static int smem_set = 0;
    if (!smem_set) {
        cudaFuncSetAttribute(gemm_hmma<0>, cudaFuncAttributeMaxDynamicSharedMemorySize,
                             2 * GST);
        cudaFuncSetAttribute(gemm_hmma<1>, cudaFuncAttributeMaxDynamicSharedMemorySize,
                             2 * GST);
        smem_set = 1;
    }

    prep_w<<<192, 256>>>(w_qkv, wqh, wql, 384, 128);
    prep_w<<<64, 256>>>(w_out, woh, wol, 256, 64);
    prep_x<<<dim3(NTOK / 32, 8, 8), 256>>>(x);

    gemm_hmma<1><<<dim3(NTOK / 64, 3, 8), 128, 2 * GST>>>(
        wqh, wql, xth, nullptr, nullptr, 384, 8);

    attn_hmma<<<dim3(NTOK / 128, 4, 8), 256>>>();

    gemm_hmma<0><<<dim3(NTOK / 64, 2, 8), 128, 2 * GST>>>(
        woh, wol, ah, out, b_out, 256, 4);
}